// round 1
// baseline (speedup 1.0000x reference)
#include <cuda_runtime.h>
#include <math.h>

#define Bb   64
#define Nn   256
#define INd  128
#define Ee   256
#define Hh   8
#define Ff   1024
#define Mrows (Bb*Nn)     // 16384
#define HE   (Hh*Ee)      // 2048

// ---------------- scratch (static device globals; no allocation) -------------
__device__ float d_dis [Bb*Nn];
__device__ float d_t   [(size_t)Mrows*Ff];     // shared: hW intermediates + FFN hidden
__device__ float d_g   [(size_t)Mrows*Ee];     // current GCN layer output
__device__ float d_res [(size_t)Mrows*Ee];     // gcn_res accumulator
__device__ float d_h   [(size_t)Mrows*Ee];     // LN output (reused for both LNs)
__device__ float d_q   [(size_t)Mrows*HE];
__device__ float d_k   [(size_t)Mrows*HE];
__device__ float d_v   [(size_t)Mrows*HE];
__device__ float d_s   [(size_t)Bb*Hh*Nn*Nn]; // attention scores
__device__ float d_y   [(size_t)Mrows*HE];
__device__ float d_att [(size_t)Mrows*Ee];

// ---------------- degree -> dis = rsqrt(clip(deg,1)) -------------------------
__global__ void deg_kernel(const float* __restrict__ adj, float* __restrict__ dis) {
    int row = blockIdx.x;              // b*N + i
    int b = row >> 8, i = row & 255;
    const float* a = adj + (size_t)b*Nn*Nn + (size_t)i*Nn;
    int t = threadIdx.x;
    float v = (t == i) ? 1.0f : a[t];  // A = adj with diag forced to 1
    __shared__ float sh[8];
    #pragma unroll
    for (int o = 16; o > 0; o >>= 1) v += __shfl_xor_sync(0xffffffffu, v, o);
    if ((t & 31) == 0) sh[t >> 5] = v;
    __syncthreads();
    if (t == 0) {
        float s = 0.f;
        #pragma unroll
        for (int w = 0; w < 8; w++) s += sh[w];
        dis[row] = rsqrtf(fmaxf(s, 1.0f));
    }
}

// ---------------- layernorm over E=256 ---------------------------------------
__global__ void ln_kernel(const float* __restrict__ x, const float* __restrict__ gam,
                          const float* __restrict__ bet, float* __restrict__ out) {
    int row = blockIdx.x;
    int t = threadIdx.x;
    float v = x[(size_t)row*Ee + t];
    __shared__ float sh[8];
    __shared__ float mv[2];
    float s = v;
    #pragma unroll
    for (int o = 16; o > 0; o >>= 1) s += __shfl_xor_sync(0xffffffffu, s, o);
    if ((t & 31) == 0) sh[t >> 5] = s;
    __syncthreads();
    if (t == 0) {
        float m = 0.f;
        #pragma unroll
        for (int w = 0; w < 8; w++) m += sh[w];
        mv[0] = m * (1.0f/Ee);
    }
    __syncthreads();
    float m = mv[0];
    float d = v - m;
    s = d * d;
    #pragma unroll
    for (int o = 16; o > 0; o >>= 1) s += __shfl_xor_sync(0xffffffffu, s, o);
    if ((t & 31) == 0) sh[t >> 5] = s;
    __syncthreads();
    if (t == 0) {
        float vv = 0.f;
        #pragma unroll
        for (int w = 0; w < 8; w++) vv += sh[w];
        mv[1] = rsqrtf(vv * (1.0f/Ee) + 1e-5f);
    }
    __syncthreads();
    out[(size_t)row*Ee + t] = d * mv[1] * gam[t] + bet[t];
}

// ---------------- masked softmax over m (row = b*H*N + h*N + n) ---------------
__global__ void softmax_kernel(float* __restrict__ s, const float* __restrict__ mask) {
    int row = blockIdx.x;
    int b = row / (Hh*Nn);
    int t = threadIdx.x;               // m
    float mk = mask[b*Nn + t];
    size_t off = (size_t)row*Nn + t;
    float v = s[off];
    float x = (mk != 0.0f) ? v : -3.0e38f;
    __shared__ float sh[8];
    __shared__ float red;
    float r = x;
    #pragma unroll
    for (int o = 16; o > 0; o >>= 1) r = fmaxf(r, __shfl_xor_sync(0xffffffffu, r, o));
    if ((t & 31) == 0) sh[t >> 5] = r;
    __syncthreads();
    if (t == 0) {
        float m = sh[0];
        #pragma unroll
        for (int w = 1; w < 8; w++) m = fmaxf(m, sh[w]);
        red = m;
    }
    __syncthreads();
    float mx = red;
    float p = (mk != 0.0f) ? expf(v - mx) : 0.0f;
    __syncthreads();
    r = p;
    #pragma unroll
    for (int o = 16; o > 0; o >>= 1) r += __shfl_xor_sync(0xffffffffu, r, o);
    if ((t & 31) == 0) sh[t >> 5] = r;
    __syncthreads();
    if (t == 0) {
        float m = 0.f;
        #pragma unroll
        for (int w = 0; w < 8; w++) m += sh[w];
        red = m;
    }
    __syncthreads();
    float sm = red;
    s[off] = (sm > 0.0f) ? p / sm : 0.0f;
}

// ---------------- generic strided-batched SGEMM with fused epilogue ----------
// C = epi(alpha * A@op(B)), 64x64 tiles, BK=16, 16x16 threads, 4x4 per thread.
// batch z -> (zb, zh) = (z/Hdiv, z%Hdiv); per-operand (b,h) strides.
// epi: v = alpha*acc; +bias[col]; act(relu/gelu); *rowmask[row]; +res1; +res2.
__global__ void sgemm_kernel(
    const float* __restrict__ A, const float* __restrict__ Bp, float* __restrict__ C,
    const float* __restrict__ bias, const float* __restrict__ rowmask,
    const float* __restrict__ res1, const float* __restrict__ res2,
    int K, int lda, int ldb, int ldc,
    long sAb, long sAh, long sBb, long sBh, long sCb, long sCh, long sRb, long sRh,
    int Hdiv, int transB, float alpha, int act)
{
    int z = blockIdx.z;
    int zb = z / Hdiv, zh = z - zb*Hdiv;
    A  += zb*sAb + zh*sAh;
    Bp += zb*sBb + zh*sBh;
    C  += zb*sCb + zh*sCh;
    const float* R1 = res1 ? res1 + zb*sRb + zh*sRh : (const float*)0;

    __shared__ float As[16][65];
    __shared__ float Bs[16][65];
    int tx = threadIdx.x, ty = threadIdx.y;
    int tid = ty*16 + tx;
    int row0 = blockIdx.y * 64;
    int col0 = blockIdx.x * 64;
    float acc[4][4] = {};

    int akk = tid & 15, am0 = tid >> 4;
    int bc  = tid & 63, bk0 = tid >> 6;
    int tkk = tid & 15, tc0 = tid >> 4;

    for (int k0 = 0; k0 < K; k0 += 16) {
        #pragma unroll
        for (int p = 0; p < 4; p++) {
            int m = am0 + 16*p;
            As[akk][m] = A[(size_t)(row0 + m)*lda + k0 + akk];
        }
        if (!transB) {
            #pragma unroll
            for (int p = 0; p < 4; p++)
                Bs[bk0 + 4*p][bc] = Bp[(size_t)(k0 + bk0 + 4*p)*ldb + col0 + bc];
        } else {
            #pragma unroll
            for (int p = 0; p < 4; p++)
                Bs[tkk][tc0 + 16*p] = Bp[(size_t)(col0 + tc0 + 16*p)*ldb + k0 + tkk];
        }
        __syncthreads();
        #pragma unroll
        for (int kk = 0; kk < 16; kk++) {
            float a[4], bb[4];
            #pragma unroll
            for (int i = 0; i < 4; i++) a[i]  = As[kk][ty + 16*i];
            #pragma unroll
            for (int j = 0; j < 4; j++) bb[j] = Bs[kk][tx + 16*j];
            #pragma unroll
            for (int i = 0; i < 4; i++)
                #pragma unroll
                for (int j = 0; j < 4; j++)
                    acc[i][j] += a[i] * bb[j];
        }
        __syncthreads();
    }

    #pragma unroll
    for (int i = 0; i < 4; i++) {
        int r = row0 + ty + 16*i;
        float rm = rowmask ? rowmask[r] : 1.0f;
        #pragma unroll
        for (int j = 0; j < 4; j++) {
            int c = col0 + tx + 16*j;
            float vv = alpha * acc[i][j];
            if (bias) vv += bias[c];
            if (act == 1)      vv = fmaxf(vv, 0.0f);
            else if (act == 2) vv = 0.5f*vv*(1.0f + erff(vv*0.70710678118654752f));
            vv *= rm;
            size_t o = (size_t)r*ldc + c;
            if (R1)   vv += R1[o];
            if (res2) vv += res2[o];
            C[o] = vv;
        }
    }
}

// ---------------- GCN aggregation: g = relu(dis_i * sum_j dis_j*A_ij*t_jf + b)*mask
// also writes/accumulates gcn_res. An generated on the fly from adj (diag=1).
__global__ void gcn_agg_kernel(
    const float* __restrict__ adj, const float* __restrict__ dis,
    const float* __restrict__ t, const float* __restrict__ bias,
    const float* __restrict__ mask, float* __restrict__ g,
    float* __restrict__ res, int initres)
{
    int b = blockIdx.z;
    const float* A = adj + (size_t)b*Nn*Nn;
    const float* T = t   + (size_t)b*Nn*Ee;
    const float* D = dis + b*Nn;
    __shared__ float As[16][65];
    __shared__ float Bs[16][65];
    int tx = threadIdx.x, ty = threadIdx.y;
    int tid = ty*16 + tx;
    int row0 = blockIdx.y * 64;
    int col0 = blockIdx.x * 64;
    float acc[4][4] = {};
    int akk = tid & 15, am0 = tid >> 4;
    int bc  = tid & 63, bk0 = tid >> 6;

    for (int k0 = 0; k0 < Nn; k0 += 16) {
        #pragma unroll
        for (int p = 0; p < 4; p++) {
            int i = am0 + 16*p;
            int j = k0 + akk;
            float a = (row0 + i == j) ? 1.0f : A[(size_t)(row0 + i)*Nn + j];
            As[akk][i] = a * D[j];
        }
        #pragma unroll
        for (int p = 0; p < 4; p++)
            Bs[bk0 + 4*p][bc] = T[(size_t)(k0 + bk0 + 4*p)*Ee + col0 + bc];
        __syncthreads();
        #pragma unroll
        for (int kk = 0; kk < 16; kk++) {
            float a[4], bb[4];
            #pragma unroll
            for (int i = 0; i < 4; i++) a[i]  = As[kk][ty + 16*i];
            #pragma unroll
            for (int j = 0; j < 4; j++) bb[j] = Bs[kk][tx + 16*j];
            #pragma unroll
            for (int i = 0; i < 4; i++)
                #pragma unroll
                for (int j = 0; j < 4; j++)
                    acc[i][j] += a[i] * bb[j];
        }
        __syncthreads();
    }

    #pragma unroll
    for (int i = 0; i < 4; i++) {
        int r = row0 + ty + 16*i;
        float sc = D[r];
        float mk = mask[b*Nn + r];
        #pragma unroll
        for (int j = 0; j < 4; j++) {
            int c = col0 + tx + 16*j;
            float v = fmaxf(acc[i][j]*sc + bias[c], 0.0f) * mk;
            size_t o = (size_t)(b*Nn + r)*Ee + c;
            g[o] = v;
            if (initres) res[o] = v; else res[o] += v;
        }
    }
}

// ---------------- launch -----------------------------------------------------
extern "C" void kernel_launch(void* const* d_in, const int* in_sizes, int n_in,
                              void* d_out, int out_size) {
    const float* x    = (const float*)d_in[0];
    const float* adj  = (const float*)d_in[1];
    const float* mask = (const float*)d_in[2];
    const float* dist = (const float*)d_in[3];
    const float* W1   = (const float*)d_in[4];
    const float* b1   = (const float*)d_in[5];
    const float* W2   = (const float*)d_in[6];
    const float* b2   = (const float*)d_in[7];
    const float* W3   = (const float*)d_in[8];
    const float* b3   = (const float*)d_in[9];
    const float* ln1g = (const float*)d_in[10];
    const float* ln1b = (const float*)d_in[11];
    const float* Wq   = (const float*)d_in[12];
    const float* Wk   = (const float*)d_in[13];
    const float* Wv   = (const float*)d_in[14];
    const float* Wo   = (const float*)d_in[15];
    const float* bo   = (const float*)d_in[16];
    const float* ln2g = (const float*)d_in[17];
    const float* ln2b = (const float*)d_in[18];
    const float* Wf1  = (const float*)d_in[19];
    const float* bf1  = (const float*)d_in[20];
    const float* Wf2  = (const float*)d_in[21];
    const float* bf2  = (const float*)d_in[22];
    float* out = (float*)d_out;

    float *dis, *t, *g, *res, *h, *q, *k, *v, *s, *y, *att;
    cudaGetSymbolAddress((void**)&dis, d_dis);
    cudaGetSymbolAddress((void**)&t,   d_t);
    cudaGetSymbolAddress((void**)&g,   d_g);
    cudaGetSymbolAddress((void**)&res, d_res);
    cudaGetSymbolAddress((void**)&h,   d_h);
    cudaGetSymbolAddress((void**)&q,   d_q);
    cudaGetSymbolAddress((void**)&k,   d_k);
    cudaGetSymbolAddress((void**)&v,   d_v);
    cudaGetSymbolAddress((void**)&s,   d_s);
    cudaGetSymbolAddress((void**)&y,   d_y);
    cudaGetSymbolAddress((void**)&att, d_att);

    dim3 blk(16, 16);
    const long ZL = 0;

    // 1) normalization factors
    deg_kernel<<<Mrows, 256>>>(adj, dis);

    // 2) GCN layer 1: t = x@W1 ; g1 = agg (init res)
    sgemm_kernel<<<dim3(Ee/64, Mrows/64, 1), blk>>>(x, W1, t, 0, 0, 0, 0,
        INd, INd, Ee, Ee, ZL,ZL,ZL,ZL,ZL,ZL,ZL,ZL, 1, 0, 1.0f, 0);
    gcn_agg_kernel<<<dim3(4, 4, Bb), blk>>>(adj, dis, t, b1, mask, g, res, 1);

    // 3) GCN layer 2
    sgemm_kernel<<<dim3(Ee/64, Mrows/64, 1), blk>>>(g, W2, t, 0, 0, 0, 0,
        Ee, Ee, Ee, Ee, ZL,ZL,ZL,ZL,ZL,ZL,ZL,ZL, 1, 0, 1.0f, 0);
    gcn_agg_kernel<<<dim3(4, 4, Bb), blk>>>(adj, dis, t, b2, mask, g, res, 0);

    // 4) GCN layer 3
    sgemm_kernel<<<dim3(Ee/64, Mrows/64, 1), blk>>>(g, W3, t, 0, 0, 0, 0,
        Ee, Ee, Ee, Ee, ZL,ZL,ZL,ZL,ZL,ZL,ZL,ZL, 1, 0, 1.0f, 0);
    gcn_agg_kernel<<<dim3(4, 4, Bb), blk>>>(adj, dis, t, b3, mask, g, res, 0);

    // 5) h = LN(gcn_res)
    ln_kernel<<<Mrows, 256>>>(res, ln1g, ln1b, h);

    // 6) q,k,v = h @ Wq/Wk/Wv   (mask on q/k/v provably redundant — see softmax)
    sgemm_kernel<<<dim3(HE/64, Mrows/64, 1), blk>>>(h, Wq, q, 0, 0, 0, 0,
        Ee, Ee, HE, HE, ZL,ZL,ZL,ZL,ZL,ZL,ZL,ZL, 1, 0, 1.0f, 0);
    sgemm_kernel<<<dim3(HE/64, Mrows/64, 1), blk>>>(h, Wk, k, 0, 0, 0, 0,
        Ee, Ee, HE, HE, ZL,ZL,ZL,ZL,ZL,ZL,ZL,ZL, 1, 0, 1.0f, 0);
    sgemm_kernel<<<dim3(HE/64, Mrows/64, 1), blk>>>(h, Wv, v, 0, 0, 0, 0,
        Ee, Ee, HE, HE, ZL,ZL,ZL,ZL,ZL,ZL,ZL,ZL, 1, 0, 1.0f, 0);

    // 7) scores: s[b,h] = (q@k^T)/16 + dist[b]   (batched over b*h)
    sgemm_kernel<<<dim3(Nn/64, Nn/64, Bb*Hh), blk>>>(q, k, s, 0, 0, dist, 0,
        Ee, HE, HE, Nn,
        (long)Nn*HE, 256L,          // A(q):  b-stride, h-stride
        (long)Nn*HE, 256L,          // B(k)
        (long)Hh*Nn*Nn, (long)Nn*Nn,// C(s)
        (long)Nn*Nn, 0L,            // res1(dist): per-b, broadcast over h
        Hh, 1, 0.0625f, 0);

    // 8) masked softmax in place
    softmax_kernel<<<Bb*Hh*Nn, 256>>>(s, mask);

    // 9) y[b,h] = a @ v, written directly in (b,n,h,e) layout
    sgemm_kernel<<<dim3(Ee/64, Nn/64, Bb*Hh), blk>>>(s, v, y, 0, 0, 0, 0,
        Nn, Nn, HE, HE,
        (long)Hh*Nn*Nn, (long)Nn*Nn,
        (long)Nn*HE, 256L,
        (long)Nn*HE, 256L,
        ZL, ZL,
        Hh, 0, 1.0f, 0);

    // 10) att = (y@Wo + bo)*mask + gcn_res
    sgemm_kernel<<<dim3(Ee/64, Mrows/64, 1), blk>>>(y, Wo, att, bo, mask, res, 0,
        HE, HE, Ee, Ee, ZL,ZL,ZL,ZL,ZL,ZL,ZL,ZL, 1, 0, 1.0f, 0);

    // 11) f_in = LN(att)
    ln_kernel<<<Mrows, 256>>>(att, ln2g, ln2b, h);

    // 12) FFN hidden: t = gelu(h@Wf1 + bf1)
    sgemm_kernel<<<dim3(Ff/64, Mrows/64, 1), blk>>>(h, Wf1, t, bf1, 0, 0, 0,
        Ee, Ee, Ff, Ff, ZL,ZL,ZL,ZL,ZL,ZL,ZL,ZL, 1, 0, 1.0f, 2);

    // 13) out = (t@Wf2 + bf2)*mask + att + gcn_res   ( = gcn_res + att_final )
    sgemm_kernel<<<dim3(Ee/64, Mrows/64, 1), blk>>>(t, Wf2, out, bf2, mask, att, res,
        Ff, Ff, Ee, Ee, ZL,ZL,ZL,ZL,ZL,ZL,ZL,ZL, 1, 0, 1.0f, 0);
}

// round 2
// speedup vs baseline: 1.0021x; 1.0021x over previous
#include <cuda_runtime.h>
#include <math.h>

#define Bb   64
#define Nn   256
#define INd  128
#define Ee   256
#define Hh   8
#define Ff   1024
#define Mrows (Bb*Nn)     // 16384
#define HE   (Hh*Ee)      // 2048

// ---------------- scratch (static device globals; no allocation) -------------
__device__ float d_dis [Bb*Nn];
__device__ float d_t   [(size_t)Mrows*Ff];     // shared: hW intermediates + FFN hidden
__device__ float d_g   [(size_t)Mrows*Ee];     // current GCN layer output
__device__ float d_res [(size_t)Mrows*Ee];     // gcn_res accumulator
__device__ float d_h   [(size_t)Mrows*Ee];     // LN output (reused for both LNs)
__device__ float d_q   [(size_t)Mrows*HE];
__device__ float d_k   [(size_t)Mrows*HE];
__device__ float d_v   [(size_t)Mrows*HE];
__device__ float d_s   [(size_t)Bb*Hh*Nn*Nn]; // attention scores
__device__ float d_y   [(size_t)Mrows*HE];
__device__ float d_att [(size_t)Mrows*Ee];

// ---------------- degree -> dis = rsqrt(clip(deg,1)) -------------------------
__global__ void deg_kernel(const float* __restrict__ adj, float* __restrict__ dis) {
    int row = blockIdx.x;              // b*N + i
    int b = row >> 8, i = row & 255;
    const float* a = adj + (size_t)b*Nn*Nn + (size_t)i*Nn;
    int t = threadIdx.x;
    float v = (t == i) ? 1.0f : a[t];  // A = adj with diag forced to 1
    __shared__ float sh[8];
    #pragma unroll
    for (int o = 16; o > 0; o >>= 1) v += __shfl_xor_sync(0xffffffffu, v, o);
    if ((t & 31) == 0) sh[t >> 5] = v;
    __syncthreads();
    if (t == 0) {
        float s = 0.f;
        #pragma unroll
        for (int w = 0; w < 8; w++) s += sh[w];
        dis[row] = rsqrtf(fmaxf(s, 1.0f));
    }
}

// ---------------- layernorm over E=256 ---------------------------------------
__global__ void ln_kernel(const float* __restrict__ x, const float* __restrict__ gam,
                          const float* __restrict__ bet, float* __restrict__ out) {
    int row = blockIdx.x;
    int t = threadIdx.x;
    float v = x[(size_t)row*Ee + t];
    __shared__ float sh[8];
    __shared__ float mv[2];
    float s = v;
    #pragma unroll
    for (int o = 16; o > 0; o >>= 1) s += __shfl_xor_sync(0xffffffffu, s, o);
    if ((t & 31) == 0) sh[t >> 5] = s;
    __syncthreads();
    if (t == 0) {
        float m = 0.f;
        #pragma unroll
        for (int w = 0; w < 8; w++) m += sh[w];
        mv[0] = m * (1.0f/Ee);
    }
    __syncthreads();
    float m = mv[0];
    float d = v - m;
    s = d * d;
    #pragma unroll
    for (int o = 16; o > 0; o >>= 1) s += __shfl_xor_sync(0xffffffffu, s, o);
    if ((t & 31) == 0) sh[t >> 5] = s;
    __syncthreads();
    if (t == 0) {
        float vv = 0.f;
        #pragma unroll
        for (int w = 0; w < 8; w++) vv += sh[w];
        mv[1] = rsqrtf(vv * (1.0f/Ee) + 1e-5f);
    }
    __syncthreads();
    out[(size_t)row*Ee + t] = d * mv[1] * gam[t] + bet[t];
}

// ---------------- masked softmax over m (row = b*H*N + h*N + n) ---------------
__global__ void softmax_kernel(float* __restrict__ s, const float* __restrict__ mask) {
    int row = blockIdx.x;
    int b = row / (Hh*Nn);
    int t = threadIdx.x;               // m
    float mk = mask[b*Nn + t];
    size_t off = (size_t)row*Nn + t;
    float v = s[off];
    float x = (mk != 0.0f) ? v : -3.0e38f;
    __shared__ float sh[8];
    __shared__ float red;
    float r = x;
    #pragma unroll
    for (int o = 16; o > 0; o >>= 1) r = fmaxf(r, __shfl_xor_sync(0xffffffffu, r, o));
    if ((t & 31) == 0) sh[t >> 5] = r;
    __syncthreads();
    if (t == 0) {
        float m = sh[0];
        #pragma unroll
        for (int w = 1; w < 8; w++) m = fmaxf(m, sh[w]);
        red = m;
    }
    __syncthreads();
    float mx = red;
    float p = (mk != 0.0f) ? expf(v - mx) : 0.0f;
    __syncthreads();
    r = p;
    #pragma unroll
    for (int o = 16; o > 0; o >>= 1) r += __shfl_xor_sync(0xffffffffu, r, o);
    if ((t & 31) == 0) sh[t >> 5] = r;
    __syncthreads();
    if (t == 0) {
        float m = 0.f;
        #pragma unroll
        for (int w = 0; w < 8; w++) m += sh[w];
        red = m;
    }
    __syncthreads();
    float sm = red;
    s[off] = (sm > 0.0f) ? p / sm : 0.0f;
}

// ---------------- generic strided-batched SGEMM with fused epilogue ----------
// C = epi(alpha * A@op(B)), 64x64 tiles, BK=16, 16x16 threads, 4x4 per thread.
// batch z -> (zb, zh) = (z/Hdiv, z%Hdiv); per-operand (b,h) strides.
// epi: v = alpha*acc; +bias[col]; act(relu/gelu); *rowmask[row]; +res1; +res2.
__global__ void sgemm_kernel(
    const float* __restrict__ A, const float* __restrict__ Bp, float* __restrict__ C,
    const float* __restrict__ bias, const float* __restrict__ rowmask,
    const float* __restrict__ res1, const float* __restrict__ res2,
    int K, int lda, int ldb, int ldc,
    long sAb, long sAh, long sBb, long sBh, long sCb, long sCh, long sRb, long sRh,
    int Hdiv, int transB, float alpha, int act)
{
    int z = blockIdx.z;
    int zb = z / Hdiv, zh = z - zb*Hdiv;
    A  += zb*sAb + zh*sAh;
    Bp += zb*sBb + zh*sBh;
    C  += zb*sCb + zh*sCh;
    const float* R1 = res1 ? res1 + zb*sRb + zh*sRh : (const float*)0;

    __shared__ float As[16][65];
    __shared__ float Bs[16][65];
    int tx = threadIdx.x, ty = threadIdx.y;
    int tid = ty*16 + tx;
    int row0 = blockIdx.y * 64;
    int col0 = blockIdx.x * 64;
    float acc[4][4] = {};

    int akk = tid & 15, am0 = tid >> 4;
    int bc  = tid & 63, bk0 = tid >> 6;
    int tkk = tid & 15, tc0 = tid >> 4;

    for (int k0 = 0; k0 < K; k0 += 16) {
        #pragma unroll
        for (int p = 0; p < 4; p++) {
            int m = am0 + 16*p;
            As[akk][m] = A[(size_t)(row0 + m)*lda + k0 + akk];
        }
        if (!transB) {
            #pragma unroll
            for (int p = 0; p < 4; p++)
                Bs[bk0 + 4*p][bc] = Bp[(size_t)(k0 + bk0 + 4*p)*ldb + col0 + bc];
        } else {
            #pragma unroll
            for (int p = 0; p < 4; p++)
                Bs[tkk][tc0 + 16*p] = Bp[(size_t)(col0 + tc0 + 16*p)*ldb + k0 + tkk];
        }
        __syncthreads();
        #pragma unroll
        for (int kk = 0; kk < 16; kk++) {
            float a[4], bb[4];
            #pragma unroll
            for (int i = 0; i < 4; i++) a[i]  = As[kk][ty + 16*i];
            #pragma unroll
            for (int j = 0; j < 4; j++) bb[j] = Bs[kk][tx + 16*j];
            #pragma unroll
            for (int i = 0; i < 4; i++)
                #pragma unroll
                for (int j = 0; j < 4; j++)
                    acc[i][j] += a[i] * bb[j];
        }
        __syncthreads();
    }

    #pragma unroll
    for (int i = 0; i < 4; i++) {
        int r = row0 + ty + 16*i;
        float rm = rowmask ? rowmask[r] : 1.0f;
        #pragma unroll
        for (int j = 0; j < 4; j++) {
            int c = col0 + tx + 16*j;
            float vv = alpha * acc[i][j];
            if (bias) vv += bias[c];
            if (act == 1)      vv = fmaxf(vv, 0.0f);
            else if (act == 2) vv = 0.5f*vv*(1.0f + erff(vv*0.70710678118654752f));
            vv *= rm;
            size_t o = (size_t)r*ldc + c;
            if (R1)   vv += R1[o];
            if (res2) vv += res2[o];
            C[o] = vv;
        }
    }
}

// ---------------- GCN aggregation: g = relu(dis_i * sum_j dis_j*A_ij*t_jf + b)*mask
// also writes/accumulates gcn_res. An generated on the fly from adj (diag=1).
__global__ void gcn_agg_kernel(
    const float* __restrict__ adj, const float* __restrict__ dis,
    const float* __restrict__ t, const float* __restrict__ bias,
    const float* __restrict__ mask, float* __restrict__ g,
    float* __restrict__ res, int initres)
{
    int b = blockIdx.z;
    const float* A = adj + (size_t)b*Nn*Nn;
    const float* T = t   + (size_t)b*Nn*Ee;
    const float* D = dis + b*Nn;
    __shared__ float As[16][65];
    __shared__ float Bs[16][65];
    int tx = threadIdx.x, ty = threadIdx.y;
    int tid = ty*16 + tx;
    int row0 = blockIdx.y * 64;
    int col0 = blockIdx.x * 64;
    float acc[4][4] = {};
    int akk = tid & 15, am0 = tid >> 4;
    int bc  = tid & 63, bk0 = tid >> 6;

    for (int k0 = 0; k0 < Nn; k0 += 16) {
        #pragma unroll
        for (int p = 0; p < 4; p++) {
            int i = am0 + 16*p;
            int j = k0 + akk;
            float a = (row0 + i == j) ? 1.0f : A[(size_t)(row0 + i)*Nn + j];
            As[akk][i] = a * D[j];
        }
        #pragma unroll
        for (int p = 0; p < 4; p++)
            Bs[bk0 + 4*p][bc] = T[(size_t)(k0 + bk0 + 4*p)*Ee + col0 + bc];
        __syncthreads();
        #pragma unroll
        for (int kk = 0; kk < 16; kk++) {
            float a[4], bb[4];
            #pragma unroll
            for (int i = 0; i < 4; i++) a[i]  = As[kk][ty + 16*i];
            #pragma unroll
            for (int j = 0; j < 4; j++) bb[j] = Bs[kk][tx + 16*j];
            #pragma unroll
            for (int i = 0; i < 4; i++)
                #pragma unroll
                for (int j = 0; j < 4; j++)
                    acc[i][j] += a[i] * bb[j];
        }
        __syncthreads();
    }

    #pragma unroll
    for (int i = 0; i < 4; i++) {
        int r = row0 + ty + 16*i;
        float sc = D[r];
        float mk = mask[b*Nn + r];
        #pragma unroll
        for (int j = 0; j < 4; j++) {
            int c = col0 + tx + 16*j;
            float v = fmaxf(acc[i][j]*sc + bias[c], 0.0f) * mk;
            size_t o = (size_t)(b*Nn + r)*Ee + c;
            g[o] = v;
            if (initres) res[o] = v; else res[o] += v;
        }
    }
}

// ---------------- launch -----------------------------------------------------
extern "C" void kernel_launch(void* const* d_in, const int* in_sizes, int n_in,
                              void* d_out, int out_size) {
    const float* x    = (const float*)d_in[0];
    const float* adj  = (const float*)d_in[1];
    const float* mask = (const float*)d_in[2];
    const float* dist = (const float*)d_in[3];
    const float* W1   = (const float*)d_in[4];
    const float* b1   = (const float*)d_in[5];
    const float* W2   = (const float*)d_in[6];
    const float* b2   = (const float*)d_in[7];
    const float* W3   = (const float*)d_in[8];
    const float* b3   = (const float*)d_in[9];
    const float* ln1g = (const float*)d_in[10];
    const float* ln1b = (const float*)d_in[11];
    const float* Wq   = (const float*)d_in[12];
    const float* Wk   = (const float*)d_in[13];
    const float* Wv   = (const float*)d_in[14];
    const float* Wo   = (const float*)d_in[15];
    const float* bo   = (const float*)d_in[16];
    const float* ln2g = (const float*)d_in[17];
    const float* ln2b = (const float*)d_in[18];
    const float* Wf1  = (const float*)d_in[19];
    const float* bf1  = (const float*)d_in[20];
    const float* Wf2  = (const float*)d_in[21];
    const float* bf2  = (const float*)d_in[22];
    float* out = (float*)d_out;

    float *dis, *t, *g, *res, *h, *q, *k, *v, *s, *y, *att;
    cudaGetSymbolAddress((void**)&dis, d_dis);
    cudaGetSymbolAddress((void**)&t,   d_t);
    cudaGetSymbolAddress((void**)&g,   d_g);
    cudaGetSymbolAddress((void**)&res, d_res);
    cudaGetSymbolAddress((void**)&h,   d_h);
    cudaGetSymbolAddress((void**)&q,   d_q);
    cudaGetSymbolAddress((void**)&k,   d_k);
    cudaGetSymbolAddress((void**)&v,   d_v);
    cudaGetSymbolAddress((void**)&s,   d_s);
    cudaGetSymbolAddress((void**)&y,   d_y);
    cudaGetSymbolAddress((void**)&att, d_att);

    dim3 blk(16, 16);
    const long ZL = 0;

    // 1) normalization factors
    deg_kernel<<<Mrows, 256>>>(adj, dis);

    // 2) GCN layer 1: t = x@W1 ; g1 = agg (init res)
    sgemm_kernel<<<dim3(Ee/64, Mrows/64, 1), blk>>>(x, W1, t, 0, 0, 0, 0,
        INd, INd, Ee, Ee, ZL,ZL,ZL,ZL,ZL,ZL,ZL,ZL, 1, 0, 1.0f, 0);
    gcn_agg_kernel<<<dim3(4, 4, Bb), blk>>>(adj, dis, t, b1, mask, g, res, 1);

    // 3) GCN layer 2
    sgemm_kernel<<<dim3(Ee/64, Mrows/64, 1), blk>>>(g, W2, t, 0, 0, 0, 0,
        Ee, Ee, Ee, Ee, ZL,ZL,ZL,ZL,ZL,ZL,ZL,ZL, 1, 0, 1.0f, 0);
    gcn_agg_kernel<<<dim3(4, 4, Bb), blk>>>(adj, dis, t, b2, mask, g, res, 0);

    // 4) GCN layer 3
    sgemm_kernel<<<dim3(Ee/64, Mrows/64, 1), blk>>>(g, W3, t, 0, 0, 0, 0,
        Ee, Ee, Ee, Ee, ZL,ZL,ZL,ZL,ZL,ZL,ZL,ZL, 1, 0, 1.0f, 0);
    gcn_agg_kernel<<<dim3(4, 4, Bb), blk>>>(adj, dis, t, b3, mask, g, res, 0);

    // 5) h = LN(gcn_res)
    ln_kernel<<<Mrows, 256>>>(res, ln1g, ln1b, h);

    // 6) q,k,v = h @ Wq/Wk/Wv   (mask on q/k/v provably redundant — see softmax)
    sgemm_kernel<<<dim3(HE/64, Mrows/64, 1), blk>>>(h, Wq, q, 0, 0, 0, 0,
        Ee, Ee, HE, HE, ZL,ZL,ZL,ZL,ZL,ZL,ZL,ZL, 1, 0, 1.0f, 0);
    sgemm_kernel<<<dim3(HE/64, Mrows/64, 1), blk>>>(h, Wk, k, 0, 0, 0, 0,
        Ee, Ee, HE, HE, ZL,ZL,ZL,ZL,ZL,ZL,ZL,ZL, 1, 0, 1.0f, 0);
    sgemm_kernel<<<dim3(HE/64, Mrows/64, 1), blk>>>(h, Wv, v, 0, 0, 0, 0,
        Ee, Ee, HE, HE, ZL,ZL,ZL,ZL,ZL,ZL,ZL,ZL, 1, 0, 1.0f, 0);

    // 7) scores: s[b,h] = (q@k^T)/16 + dist[b]   (batched over b*h)
    sgemm_kernel<<<dim3(Nn/64, Nn/64, Bb*Hh), blk>>>(q, k, s, 0, 0, dist, 0,
        Ee, HE, HE, Nn,
        (long)Nn*HE, 256L,          // A(q):  b-stride, h-stride
        (long)Nn*HE, 256L,          // B(k)
        (long)Hh*Nn*Nn, (long)Nn*Nn,// C(s)
        (long)Nn*Nn, 0L,            // res1(dist): per-b, broadcast over h
        Hh, 1, 0.0625f, 0);

    // 8) masked softmax in place
    softmax_kernel<<<Bb*Hh*Nn, 256>>>(s, mask);

    // 9) y[b,h] = a @ v, written directly in (b,n,h,e) layout
    sgemm_kernel<<<dim3(Ee/64, Nn/64, Bb*Hh), blk>>>(s, v, y, 0, 0, 0, 0,
        Nn, Nn, HE, HE,
        (long)Hh*Nn*Nn, (long)Nn*Nn,
        (long)Nn*HE, 256L,
        (long)Nn*HE, 256L,
        ZL, ZL,
        Hh, 0, 1.0f, 0);

    // 10) att = (y@Wo + bo)*mask + gcn_res
    sgemm_kernel<<<dim3(Ee/64, Mrows/64, 1), blk>>>(y, Wo, att, bo, mask, res, 0,
        HE, HE, Ee, Ee, ZL,ZL,ZL,ZL,ZL,ZL,ZL,ZL, 1, 0, 1.0f, 0);

    // 11) f_in = LN(att)
    ln_kernel<<<Mrows, 256>>>(att, ln2g, ln2b, h);

    // 12) FFN hidden: t = gelu(h@Wf1 + bf1)
    sgemm_kernel<<<dim3(Ff/64, Mrows/64, 1), blk>>>(h, Wf1, t, bf1, 0, 0, 0,
        Ee, Ee, Ff, Ff, ZL,ZL,ZL,ZL,ZL,ZL,ZL,ZL, 1, 0, 1.0f, 2);

    // 13) out = (t@Wf2 + bf2)*mask + att + gcn_res   ( = gcn_res + att_final )
    sgemm_kernel<<<dim3(Ee/64, Mrows/64, 1), blk>>>(t, Wf2, out, bf2, mask, att, res,
        Ff, Ff, Ee, Ee, ZL,ZL,ZL,ZL,ZL,ZL,ZL,ZL, 1, 0, 1.0f, 0);
}

// round 4
// speedup vs baseline: 3.4027x; 3.3955x over previous
#include <cuda_runtime.h>
#include <math.h>
#include <stdint.h>

#define Bb 64
#define Nn 256
#define INd 128
#define Ee 256
#define Hh 8
#define Ff 1024
#define Mrows (Bb*Nn)
#define HE (Hh*Ee)

// ---------------- scratch ----------------
__device__ float d_dis[Mrows];
__device__ float d_an [(size_t)Bb*Nn*Nn];
__device__ float d_t  [(size_t)Mrows*Ff];
__device__ float d_g  [(size_t)Mrows*Ee];
__device__ float d_res[(size_t)Mrows*Ee];
__device__ float d_h  [(size_t)Mrows*Ee];
__device__ float d_q  [(size_t)Mrows*HE];
__device__ float d_k  [(size_t)Mrows*HE];
__device__ float d_v  [(size_t)Mrows*HE];
__device__ float d_s  [(size_t)Bb*Hh*Nn*Nn];
__device__ float d_y  [(size_t)Mrows*HE];
__device__ float d_att[(size_t)Mrows*Ee];

// ---------------- asm helpers ----------------
__device__ __forceinline__ uint32_t smem_u32(const void* p){
    uint32_t a; asm("{ .reg .u64 t; cvta.to.shared.u64 t, %1; cvt.u32.u64 %0, t; }":"=r"(a):"l"(p)); return a; }
#define CP16(dst,src) asm volatile("cp.async.cg.shared.global [%0], [%1], 16;"::"r"(dst),"l"(src))
#define CP4(dst,src)  asm volatile("cp.async.ca.shared.global [%0], [%1], 4;"::"r"(dst),"l"(src))
#define CP_COMMIT()   asm volatile("cp.async.commit_group;")
#define CP_WAIT0()    asm volatile("cp.async.wait_group 0;")
#define CP_WAIT1()    asm volatile("cp.async.wait_group 1;")
#define CVT(u,f)      asm("cvt.rna.tf32.f32 %0, %1;":"=r"(u):"f"(f))
#define MMA(c,a,b) asm volatile( \
  "mma.sync.aligned.m16n8k8.row.col.f32.tf32.tf32.f32 {%0,%1,%2,%3},{%4,%5,%6,%7},{%8,%9},{%0,%1,%2,%3};" \
  : "+f"((c)[0]),"+f"((c)[1]),"+f"((c)[2]),"+f"((c)[3]) \
  : "r"((a)[0]),"r"((a)[1]),"r"((a)[2]),"r"((a)[3]),"r"((b)[0]),"r"((b)[1]))

// ---------------- small kernels ----------------
__global__ void deg_kernel(const float* __restrict__ adj, float* __restrict__ dis){
    int row=blockIdx.x, b=row>>8, i=row&255, t=threadIdx.x;
    const float* a=adj+(size_t)b*Nn*Nn+(size_t)i*Nn;
    float v=(t==i)?1.0f:a[t];
    __shared__ float sh[8];
    #pragma unroll
    for(int o=16;o>0;o>>=1) v+=__shfl_xor_sync(0xffffffffu,v,o);
    if((t&31)==0) sh[t>>5]=v;
    __syncthreads();
    if(t==0){ float s=0.f; for(int w=0;w<8;w++) s+=sh[w]; dis[row]=rsqrtf(fmaxf(s,1.0f)); }
}
__global__ void an_build(const float* __restrict__ adj, const float* __restrict__ dis,
                         float* __restrict__ An){
    long idx=(long)blockIdx.x*256+threadIdx.x;
    int j=(int)(idx&255); long t=idx>>8; int i=(int)(t&255); int b=(int)(t>>8);
    float a=(i==j)?1.0f:adj[idx];
    An[idx]=a*dis[b*256+i]*dis[b*256+j];
}
__global__ void ln_kernel(const float* __restrict__ x, const float* __restrict__ g,
                          const float* __restrict__ be, float* __restrict__ out){
    int row=blockIdx.x, t=threadIdx.x;
    float v=x[(size_t)row*Ee+t];
    __shared__ float sh[8]; __shared__ float mv[2];
    float s=v;
    #pragma unroll
    for(int o=16;o>0;o>>=1) s+=__shfl_xor_sync(0xffffffffu,s,o);
    if((t&31)==0) sh[t>>5]=s;
    __syncthreads();
    if(t==0){ float m=0.f; for(int w=0;w<8;w++) m+=sh[w]; mv[0]=m*(1.0f/Ee); }
    __syncthreads();
    float m=mv[0], d=v-m; s=d*d;
    #pragma unroll
    for(int o=16;o>0;o>>=1) s+=__shfl_xor_sync(0xffffffffu,s,o);
    if((t&31)==0) sh[t>>5]=s;
    __syncthreads();
    if(t==0){ float vv=0.f; for(int w=0;w<8;w++) vv+=sh[w]; mv[1]=rsqrtf(vv*(1.0f/Ee)+1e-5f); }
    __syncthreads();
    out[(size_t)row*Ee+t]=d*mv[1]*g[t]+be[t];
}
__global__ void softmax_kernel(float* __restrict__ s, const float* __restrict__ mask){
    int row=blockIdx.x, b=row/(Hh*Nn), t=threadIdx.x;
    float mk=mask[b*Nn+t];
    size_t off=(size_t)row*Nn+t;
    float v=s[off], x=(mk!=0.0f)?v:-3.0e38f;
    __shared__ float sh[8]; __shared__ float red;
    float r=x;
    #pragma unroll
    for(int o=16;o>0;o>>=1) r=fmaxf(r,__shfl_xor_sync(0xffffffffu,r,o));
    if((t&31)==0) sh[t>>5]=r;
    __syncthreads();
    if(t==0){ float m=sh[0]; for(int w=1;w<8;w++) m=fmaxf(m,sh[w]); red=m; }
    __syncthreads();
    float mx=red, p=(mk!=0.0f)?expf(v-mx):0.0f;
    __syncthreads();
    r=p;
    #pragma unroll
    for(int o=16;o>0;o>>=1) r+=__shfl_xor_sync(0xffffffffu,r,o);
    if((t&31)==0) sh[t>>5]=r;
    __syncthreads();
    if(t==0){ float m=0.f; for(int w=0;w<8;w++) m+=sh[w]; red=m; }
    __syncthreads();
    float sm=red;
    s[off]=(sm>0.0f)?p/sm:0.0f;
}

// ---------------- tf32 tensor-core GEMM ----------------
// C[m,n] = epi(alpha * sum_k A[m,k]*B'[k,n]); B' = B (transB=0, B is [k][n])
//                                             B' = B^T (transB=1, B is [n][k])
// CTA tile 128x256, BK=32, 8 warps (2m x 4n), warp tile 64x64, cp.async 2-stage.
#define APADF 36
#define BPADF 264
#define ABUF_F (128*APADF)       // 4608 floats
#define BBUF_F (32*BPADF)        // 8448 floats
#define SMEM_BYTES ((2*ABUF_F+2*BBUF_F)*4)   // 104448

__global__ void __launch_bounds__(256,1) tgemm(
    const float* __restrict__ A, const float* __restrict__ B, float* __restrict__ C,
    const float* __restrict__ bias, const float* __restrict__ rowmask,
    const float* __restrict__ res1, const float* __restrict__ res2,
    float* __restrict__ aux, int auxinit,
    int K, int lda, int ldb, int ldc,
    long sAb, long sAh, long sBb, long sBh, long sCb, long sCh,
    long sR1b, long sR1h, long sMb,
    int Hdiv, int transB, float alpha, int act)
{
    extern __shared__ float sm[];
    int tid=threadIdx.x, wid=tid>>5, lane=tid&31;
    int z=blockIdx.z, zb=z/Hdiv, zh=z-zb*Hdiv;
    int row0=blockIdx.y*128, col0=blockIdx.x*256;

    const float* Ag = A + zb*sAb + zh*sAh + (long)row0*lda;
    const float* Bg = B + zb*sBb + zh*sBh;
    float* Cb = C + zb*sCb + zh*sCh;
    const float* R1 = res1 ? res1 + zb*sR1b + zh*sR1h : (const float*)0;
    float* Ax = aux ? aux + zb*sCb + zh*sCh : (float*)0;

    uint32_t sbase = smem_u32(sm);
    const uint32_t aoffB[2] = { sbase, sbase + ABUF_F*4 };
    const uint32_t boffB[2] = { sbase + 2*ABUF_F*4, sbase + (2*ABUF_F+BBUF_F)*4 };

    // loaders
    auto loadA = [&](int buf, int k0){
        #pragma unroll
        for(int i=0;i<4;i++){
            int f4 = tid + i*256;           // 1024 float4s
            int row = f4>>3, c4 = f4&7;
            CP16(aoffB[buf] + (uint32_t)(row*APADF + c4*4)*4,
                 Ag + (long)row*lda + k0 + c4*4);
        }
    };
    auto loadB = [&](int buf, int k0){
        if(!transB){
            #pragma unroll
            for(int i=0;i<8;i++){
                int f4 = tid + i*256;       // 2048 float4s
                int kr = f4>>6, c4 = f4&63;
                CP16(boffB[buf] + (uint32_t)(kr*BPADF + c4*4)*4,
                     Bg + (long)(k0+kr)*ldb + col0 + c4*4);
            }
        } else {
            #pragma unroll
            for(int i=0;i<32;i++){
                int e = tid + i*256;        // 8192 scalars
                int n = e>>5, kk = e&31;
                CP4(boffB[buf] + (uint32_t)(kk*BPADF + n)*4,
                    Bg + (long)(col0+n)*ldb + k0 + kk);
            }
        }
    };

    int wm0 = (wid>>2)*64;   // 0 or 64
    int wn0 = (wid&3)*64;    // 0,64,128,192
    int tq = lane>>2, tr = lane&3;

    float cacc[4][8][4];
    #pragma unroll
    for(int a0=0;a0<4;a0++)
        #pragma unroll
        for(int b0=0;b0<8;b0++)
            #pragma unroll
            for(int c0=0;c0<4;c0++) cacc[a0][b0][c0]=0.f;

    int KT = K >> 5;
    loadA(0,0); loadB(0,0); CP_COMMIT();

    for(int kt=0; kt<KT; kt++){
        int buf = kt&1;
        if(kt+1<KT){ loadA(buf^1,(kt+1)*32); loadB(buf^1,(kt+1)*32); CP_COMMIT(); CP_WAIT1(); }
        else CP_WAIT0();
        __syncthreads();

        const float* As_ = sm + buf*ABUF_F;
        const float* Bs_ = sm + 2*ABUF_F + buf*BBUF_F;
        #pragma unroll
        for(int ks=0;ks<4;ks++){
            uint32_t af[4][4], bf[8][2];
            #pragma unroll
            for(int mt=0;mt<4;mt++){
                const float* ap = As_ + (wm0+mt*16+tq)*APADF + ks*8 + tr;
                CVT(af[mt][0], ap[0]);
                CVT(af[mt][1], ap[8*APADF]);
                CVT(af[mt][2], ap[4]);
                CVT(af[mt][3], ap[8*APADF+4]);
            }
            #pragma unroll
            for(int nt=0;nt<8;nt++){
                const float* bp = Bs_ + (ks*8+tr)*BPADF + wn0 + nt*8 + tq;
                CVT(bf[nt][0], bp[0]);
                CVT(bf[nt][1], bp[4*BPADF]);
            }
            #pragma unroll
            for(int mt=0;mt<4;mt++)
                #pragma unroll
                for(int nt=0;nt<8;nt++)
                    MMA(cacc[mt][nt], af[mt], bf[nt]);
        }
        __syncthreads();
    }

    // epilogue
    #pragma unroll
    for(int mt=0;mt<4;mt++){
        #pragma unroll
        for(int hf=0;hf<2;hf++){
            int r = row0 + wm0 + mt*16 + tq + hf*8;
            float rm = rowmask ? rowmask[zb*sMb + r] : 1.0f;
            #pragma unroll
            for(int nt=0;nt<8;nt++){
                int cc = col0 + wn0 + nt*8 + tr*2;
                float v0 = cacc[mt][nt][hf*2+0]*alpha;
                float v1 = cacc[mt][nt][hf*2+1]*alpha;
                if(bias){ v0+=bias[cc]; v1+=bias[cc+1]; }
                if(act==1){ v0=fmaxf(v0,0.f); v1=fmaxf(v1,0.f); }
                else if(act==2){
                    v0=0.5f*v0*(1.0f+erff(v0*0.70710678118654752f));
                    v1=0.5f*v1*(1.0f+erff(v1*0.70710678118654752f));
                }
                v0*=rm; v1*=rm;
                long o=(long)r*ldc+cc;
                if(R1){ float2 t2=*(const float2*)(R1+o); v0+=t2.x; v1+=t2.y; }
                if(res2){ float2 t2=*(const float2*)(res2+o); v0+=t2.x; v1+=t2.y; }
                float2 w; w.x=v0; w.y=v1;
                if(Ax){
                    if(auxinit) *(float2*)(Ax+o)=w;
                    else { float2 t2=*(const float2*)(Ax+o); float2 u; u.x=t2.x+v0; u.y=t2.y+v1; *(float2*)(Ax+o)=u; }
                }
                *(float2*)(Cb+o)=w;
            }
        }
    }
}

// ---------------- launch ----------------
extern "C" void kernel_launch(void* const* d_in, const int* in_sizes, int n_in,
                              void* d_out, int out_size){
    const float* x=(const float*)d_in[0];
    const float* adj=(const float*)d_in[1];
    const float* mask=(const float*)d_in[2];
    const float* dist=(const float*)d_in[3];
    const float* W1=(const float*)d_in[4];
    const float* b1=(const float*)d_in[5];
    const float* W2=(const float*)d_in[6];
    const float* b2=(const float*)d_in[7];
    const float* W3=(const float*)d_in[8];
    const float* b3=(const float*)d_in[9];
    const float* ln1g=(const float*)d_in[10];
    const float* ln1b=(const float*)d_in[11];
    const float* Wq=(const float*)d_in[12];
    const float* Wk=(const float*)d_in[13];
    const float* Wv=(const float*)d_in[14];
    const float* Wo=(const float*)d_in[15];
    const float* bo=(const float*)d_in[16];
    const float* ln2g=(const float*)d_in[17];
    const float* ln2b=(const float*)d_in[18];
    const float* Wf1=(const float*)d_in[19];
    const float* bf1=(const float*)d_in[20];
    const float* Wf2=(const float*)d_in[21];
    const float* bf2=(const float*)d_in[22];
    float* out=(float*)d_out;

    float *dis,*an,*t,*g,*res,*h,*q,*k,*v,*s,*y,*att;
    cudaGetSymbolAddress((void**)&dis,d_dis);
    cudaGetSymbolAddress((void**)&an,d_an);
    cudaGetSymbolAddress((void**)&t,d_t);
    cudaGetSymbolAddress((void**)&g,d_g);
    cudaGetSymbolAddress((void**)&res,d_res);
    cudaGetSymbolAddress((void**)&h,d_h);
    cudaGetSymbolAddress((void**)&q,d_q);
    cudaGetSymbolAddress((void**)&k,d_k);
    cudaGetSymbolAddress((void**)&v,d_v);
    cudaGetSymbolAddress((void**)&s,d_s);
    cudaGetSymbolAddress((void**)&y,d_y);
    cudaGetSymbolAddress((void**)&att,d_att);

    cudaFuncSetAttribute(tgemm, cudaFuncAttributeMaxDynamicSharedMemorySize, SMEM_BYTES);
    const long Z=0;

    // prep
    deg_kernel<<<Mrows,256>>>(adj,dis);
    an_build<<<(Bb*Nn*Nn)/256,256>>>(adj,dis,an);

    // GCN layer 1:  t = x@W1 ; g = relu(An@t+b1)*mask, res=g
    tgemm<<<dim3(1,128,1),256,SMEM_BYTES>>>(x,W1,t, 0,0,0,0, 0,0,
        128,128,256,256, Z,Z,Z,Z,Z,Z,Z,Z,Z, 1,0,1.0f,0);
    tgemm<<<dim3(1,2,Bb),256,SMEM_BYTES>>>(an,t,g, b1,mask,0,0, res,1,
        256,256,256,256, 65536L,Z, 65536L,Z, 65536L,Z, Z,Z, 256L, 1,0,1.0f,1);
    // layer 2
    tgemm<<<dim3(1,128,1),256,SMEM_BYTES>>>(g,W2,t, 0,0,0,0, 0,0,
        256,256,256,256, Z,Z,Z,Z,Z,Z,Z,Z,Z, 1,0,1.0f,0);
    tgemm<<<dim3(1,2,Bb),256,SMEM_BYTES>>>(an,t,g, b2,mask,0,0, res,0,
        256,256,256,256, 65536L,Z, 65536L,Z, 65536L,Z, Z,Z, 256L, 1,0,1.0f,1);
    // layer 3
    tgemm<<<dim3(1,128,1),256,SMEM_BYTES>>>(g,W3,t, 0,0,0,0, 0,0,
        256,256,256,256, Z,Z,Z,Z,Z,Z,Z,Z,Z, 1,0,1.0f,0);
    tgemm<<<dim3(1,2,Bb),256,SMEM_BYTES>>>(an,t,g, b3,mask,0,0, res,0,
        256,256,256,256, 65536L,Z, 65536L,Z, 65536L,Z, Z,Z, 256L, 1,0,1.0f,1);

    // LN1 + QKV
    ln_kernel<<<Mrows,256>>>(res,ln1g,ln1b,h);
    tgemm<<<dim3(8,128,1),256,SMEM_BYTES>>>(h,Wq,q, 0,0,0,0, 0,0,
        256,256,2048,2048, Z,Z,Z,Z,Z,Z,Z,Z,Z, 1,0,1.0f,0);
    tgemm<<<dim3(8,128,1),256,SMEM_BYTES>>>(h,Wk,k, 0,0,0,0, 0,0,
        256,256,2048,2048, Z,Z,Z,Z,Z,Z,Z,Z,Z, 1,0,1.0f,0);
    tgemm<<<dim3(8,128,1),256,SMEM_BYTES>>>(h,Wv,v, 0,0,0,0, 0,0,
        256,256,2048,2048, Z,Z,Z,Z,Z,Z,Z,Z,Z, 1,0,1.0f,0);

    // scores: s[b,h] = (q@k^T)/16 + dist[b]
    tgemm<<<dim3(1,2,Bb*Hh),256,SMEM_BYTES>>>(q,k,s, 0,0,dist,0, 0,0,
        256,2048,2048,256, 524288L,256L, 524288L,256L, 524288L,65536L, 65536L,Z, Z,
        Hh,1,0.0625f,0);
    softmax_kernel<<<Bb*Hh*Nn,256>>>(s,mask);
    // y[b,h] = a@v (written in (b,n,h,e) layout)
    tgemm<<<dim3(1,2,Bb*Hh),256,SMEM_BYTES>>>(s,v,y, 0,0,0,0, 0,0,
        256,256,2048,2048, 524288L,65536L, 524288L,256L, 524288L,256L, Z,Z, Z,
        Hh,0,1.0f,0);

    // att = (y@Wo+bo)*mask + res
    tgemm<<<dim3(1,128,1),256,SMEM_BYTES>>>(y,Wo,att, bo,mask,res,0, 0,0,
        2048,2048,256,256, Z,Z,Z,Z,Z,Z,Z,Z,Z, 1,0,1.0f,0);

    // FFN
    ln_kernel<<<Mrows,256>>>(att,ln2g,ln2b,h);
    tgemm<<<dim3(4,128,1),256,SMEM_BYTES>>>(h,Wf1,t, bf1,0,0,0, 0,0,
        256,256,1024,1024, Z,Z,Z,Z,Z,Z,Z,Z,Z, 1,0,1.0f,2);
    tgemm<<<dim3(1,128,1),256,SMEM_BYTES>>>(t,Wf2,out, bf2,mask,att,res, 0,0,
        1024,1024,256,256, Z,Z,Z,Z,Z,Z,Z,Z,Z, 1,0,1.0f,0);
}

// round 5
// speedup vs baseline: 3.6772x; 1.0807x over previous
#include <cuda_runtime.h>
#include <math.h>
#include <stdint.h>

#define Bb 64
#define Nn 256
#define INd 128
#define Ee 256
#define Hh 8
#define Ff 1024
#define Mrows (Bb*Nn)
#define HE (Hh*Ee)

// ---------------- scratch ----------------
__device__ float d_dis[Mrows];
__device__ float d_an [(size_t)Bb*Nn*Nn];
__device__ float d_t  [(size_t)Mrows*Ff];
__device__ float d_g  [(size_t)Mrows*Ee];
__device__ float d_res[(size_t)Mrows*Ee];
__device__ float d_h  [(size_t)Mrows*Ee];
__device__ float d_q  [(size_t)Mrows*HE];
__device__ float d_k  [(size_t)Mrows*HE];
__device__ float d_v  [(size_t)Mrows*HE];
__device__ float d_s  [(size_t)Bb*Hh*Nn*Nn];
__device__ float d_y  [(size_t)Mrows*HE];
__device__ float d_att[(size_t)Mrows*Ee];

// ---------------- asm helpers ----------------
__device__ __forceinline__ uint32_t smem_u32(const void* p){
    uint32_t a; asm("{ .reg .u64 t; cvta.to.shared.u64 t, %1; cvt.u32.u64 %0, t; }":"=r"(a):"l"(p)); return a; }
#define CP16(dst,src) asm volatile("cp.async.cg.shared.global [%0], [%1], 16;"::"r"(dst),"l"(src))
#define CP4(dst,src)  asm volatile("cp.async.ca.shared.global [%0], [%1], 4;"::"r"(dst),"l"(src))
#define CP_COMMIT()   asm volatile("cp.async.commit_group;")
#define CP_WAIT0()    asm volatile("cp.async.wait_group 0;")
#define CP_WAIT1()    asm volatile("cp.async.wait_group 1;")
#define CVT(u,f)      asm("cvt.rna.tf32.f32 %0, %1;":"=r"(u):"f"(f))
#define MMA(c,a,b) asm volatile( \
  "mma.sync.aligned.m16n8k8.row.col.f32.tf32.tf32.f32 {%0,%1,%2,%3},{%4,%5,%6,%7},{%8,%9},{%0,%1,%2,%3};" \
  : "+f"((c)[0]),"+f"((c)[1]),"+f"((c)[2]),"+f"((c)[3]) \
  : "r"((a)[0]),"r"((a)[1]),"r"((a)[2]),"r"((a)[3]),"r"((b)[0]),"r"((b)[1]))

// ---------------- small kernels ----------------
__global__ void deg_kernel(const float* __restrict__ adj, float* __restrict__ dis){
    int row=blockIdx.x, b=row>>8, i=row&255, t=threadIdx.x;
    const float* a=adj+(size_t)b*Nn*Nn+(size_t)i*Nn;
    float v=(t==i)?1.0f:a[t];
    __shared__ float sh[8];
    #pragma unroll
    for(int o=16;o>0;o>>=1) v+=__shfl_xor_sync(0xffffffffu,v,o);
    if((t&31)==0) sh[t>>5]=v;
    __syncthreads();
    if(t==0){ float s=0.f; for(int w=0;w<8;w++) s+=sh[w]; dis[row]=rsqrtf(fmaxf(s,1.0f)); }
}
__global__ void an_build(const float* __restrict__ adj, const float* __restrict__ dis,
                         float* __restrict__ An){
    long idx=(long)blockIdx.x*256+threadIdx.x;
    int j=(int)(idx&255); long t=idx>>8; int i=(int)(t&255); int b=(int)(t>>8);
    float a=(i==j)?1.0f:adj[idx];
    An[idx]=a*dis[b*256+i]*dis[b*256+j];
}
__global__ void ln_kernel(const float* __restrict__ x, const float* __restrict__ g,
                          const float* __restrict__ be, float* __restrict__ out){
    int row=blockIdx.x, t=threadIdx.x;
    float v=x[(size_t)row*Ee+t];
    __shared__ float sh[8]; __shared__ float mv[2];
    float s=v;
    #pragma unroll
    for(int o=16;o>0;o>>=1) s+=__shfl_xor_sync(0xffffffffu,s,o);
    if((t&31)==0) sh[t>>5]=s;
    __syncthreads();
    if(t==0){ float m=0.f; for(int w=0;w<8;w++) m+=sh[w]; mv[0]=m*(1.0f/Ee); }
    __syncthreads();
    float m=mv[0], d=v-m; s=d*d;
    #pragma unroll
    for(int o=16;o>0;o>>=1) s+=__shfl_xor_sync(0xffffffffu,s,o);
    if((t&31)==0) sh[t>>5]=s;
    __syncthreads();
    if(t==0){ float vv=0.f; for(int w=0;w<8;w++) vv+=sh[w]; mv[1]=rsqrtf(vv*(1.0f/Ee)+1e-5f); }
    __syncthreads();
    out[(size_t)row*Ee+t]=d*mv[1]*g[t]+be[t];
}
__global__ void softmax_kernel(float* __restrict__ s, const float* __restrict__ mask){
    int row=blockIdx.x, b=row/(Hh*Nn), t=threadIdx.x;
    float mk=mask[b*Nn+t];
    size_t off=(size_t)row*Nn+t;
    float v=s[off], x=(mk!=0.0f)?v:-3.0e38f;
    __shared__ float sh[8]; __shared__ float red;
    float r=x;
    #pragma unroll
    for(int o=16;o>0;o>>=1) r=fmaxf(r,__shfl_xor_sync(0xffffffffu,r,o));
    if((t&31)==0) sh[t>>5]=r;
    __syncthreads();
    if(t==0){ float m=sh[0]; for(int w=1;w<8;w++) m=fmaxf(m,sh[w]); red=m; }
    __syncthreads();
    float mx=red, p=(mk!=0.0f)?expf(v-mx):0.0f;
    __syncthreads();
    r=p;
    #pragma unroll
    for(int o=16;o>0;o>>=1) r+=__shfl_xor_sync(0xffffffffu,r,o);
    if((t&31)==0) sh[t>>5]=r;
    __syncthreads();
    if(t==0){ float m=0.f; for(int w=0;w<8;w++) m+=sh[w]; red=m; }
    __syncthreads();
    float sm=red;
    s[off]=(sm>0.0f)?p/sm:0.0f;
}

// ---------------- tf32 tensor-core GEMM ----------------
// CTA tile 128x128, BK=32, 8 warps (2m x 4n), warp tile 64x32, 2-stage cp.async.
// 2 CTAs/SM target (regs<=128).
#define APADF 36
#define BPADF 136
#define ABUF_F (128*APADF)       // 4608 floats
#define BBUF_F (32*BPADF)        // 4352 floats
#define SMEM_BYTES ((2*ABUF_F+2*BBUF_F)*4)   // 71680

__global__ void __launch_bounds__(256,2) tgemm(
    const float* __restrict__ A, const float* __restrict__ B, float* __restrict__ C,
    const float* __restrict__ bias, const float* __restrict__ rowmask,
    const float* __restrict__ res1, const float* __restrict__ res2,
    float* __restrict__ aux, int auxinit,
    int K, int lda, int ldb, int ldc,
    long sAb, long sAh, long sBb, long sBh, long sCb, long sCh,
    long sR1b, long sR1h, long sMb,
    int Hdiv, int transB, float alpha, int act)
{
    extern __shared__ float sm[];
    int tid=threadIdx.x, wid=tid>>5, lane=tid&31;
    int z=blockIdx.z, zb=z/Hdiv, zh=z-zb*Hdiv;
    int row0=blockIdx.y*128, col0=blockIdx.x*128;

    const float* Ag = A + zb*sAb + zh*sAh + (long)row0*lda;
    const float* Bg = B + zb*sBb + zh*sBh;
    float* Cb = C + zb*sCb + zh*sCh;
    const float* R1 = res1 ? res1 + zb*sR1b + zh*sR1h : (const float*)0;
    float* Ax = aux ? aux + zb*sCb + zh*sCh : (float*)0;

    uint32_t sbase = smem_u32(sm);
    const uint32_t aoffB[2] = { sbase, sbase + ABUF_F*4 };
    const uint32_t boffB[2] = { sbase + 2*ABUF_F*4, sbase + (2*ABUF_F+BBUF_F)*4 };

    auto loadA = [&](int buf, int k0){
        #pragma unroll
        for(int i=0;i<4;i++){
            int f4 = tid + i*256;           // 1024 float4s (128 rows x 8)
            int row = f4>>3, c4 = f4&7;
            CP16(aoffB[buf] + (uint32_t)(row*APADF + c4*4)*4,
                 Ag + (long)row*lda + k0 + c4*4);
        }
    };
    auto loadB = [&](int buf, int k0){
        if(!transB){
            #pragma unroll
            for(int i=0;i<4;i++){
                int f4 = tid + i*256;       // 1024 float4s (32 k-rows x 32)
                int kr = f4>>5, c4 = f4&31;
                CP16(boffB[buf] + (uint32_t)(kr*BPADF + c4*4)*4,
                     Bg + (long)(k0+kr)*ldb + col0 + c4*4);
            }
        } else {
            #pragma unroll
            for(int i=0;i<16;i++){
                int e = tid + i*256;        // 4096 scalars (128 n x 32 k)
                int n = e>>5, kk = e&31;
                CP4(boffB[buf] + (uint32_t)(kk*BPADF + n)*4,
                    Bg + (long)(col0+n)*ldb + k0 + kk);
            }
        }
    };

    int wm0 = (wid>>2)*64;   // 0 or 64
    int wn0 = (wid&3)*32;    // 0,32,64,96
    int tq = lane>>2, tr = lane&3;

    float cacc[4][4][4];
    #pragma unroll
    for(int a0=0;a0<4;a0++)
        #pragma unroll
        for(int b0=0;b0<4;b0++)
            #pragma unroll
            for(int c0=0;c0<4;c0++) cacc[a0][b0][c0]=0.f;

    int KT = K >> 5;
    loadA(0,0); loadB(0,0); CP_COMMIT();

    for(int kt=0; kt<KT; kt++){
        int buf = kt&1;
        if(kt+1<KT){ loadA(buf^1,(kt+1)*32); loadB(buf^1,(kt+1)*32); CP_COMMIT(); CP_WAIT1(); }
        else CP_WAIT0();
        __syncthreads();

        const float* As_ = sm + buf*ABUF_F;
        const float* Bs_ = sm + 2*ABUF_F + buf*BBUF_F;
        #pragma unroll
        for(int ks=0;ks<4;ks++){
            uint32_t af[4][4], bf[4][2];
            #pragma unroll
            for(int mt=0;mt<4;mt++){
                const float* ap = As_ + (wm0+mt*16+tq)*APADF + ks*8 + tr;
                CVT(af[mt][0], ap[0]);
                CVT(af[mt][1], ap[8*APADF]);
                CVT(af[mt][2], ap[4]);
                CVT(af[mt][3], ap[8*APADF+4]);
            }
            #pragma unroll
            for(int nt=0;nt<4;nt++){
                const float* bp = Bs_ + (ks*8+tr)*BPADF + wn0 + nt*8 + tq;
                CVT(bf[nt][0], bp[0]);
                CVT(bf[nt][1], bp[4*BPADF]);
            }
            #pragma unroll
            for(int mt=0;mt<4;mt++)
                #pragma unroll
                for(int nt=0;nt<4;nt++)
                    MMA(cacc[mt][nt], af[mt], bf[nt]);
        }
        __syncthreads();
    }

    // epilogue
    #pragma unroll
    for(int mt=0;mt<4;mt++){
        #pragma unroll
        for(int hf=0;hf<2;hf++){
            int r = row0 + wm0 + mt*16 + tq + hf*8;
            float rm = rowmask ? rowmask[zb*sMb + r] : 1.0f;
            #pragma unroll
            for(int nt=0;nt<4;nt++){
                int cc = col0 + wn0 + nt*8 + tr*2;
                float v0 = cacc[mt][nt][hf*2+0]*alpha;
                float v1 = cacc[mt][nt][hf*2+1]*alpha;
                if(bias){ v0+=bias[cc]; v1+=bias[cc+1]; }
                if(act==1){ v0=fmaxf(v0,0.f); v1=fmaxf(v1,0.f); }
                else if(act==2){
                    v0=0.5f*v0*(1.0f+erff(v0*0.70710678118654752f));
                    v1=0.5f*v1*(1.0f+erff(v1*0.70710678118654752f));
                }
                v0*=rm; v1*=rm;
                long o=(long)r*ldc+cc;
                if(R1){ float2 t2=*(const float2*)(R1+o); v0+=t2.x; v1+=t2.y; }
                if(res2){ float2 t2=*(const float2*)(res2+o); v0+=t2.x; v1+=t2.y; }
                float2 w; w.x=v0; w.y=v1;
                if(Ax){
                    if(auxinit) *(float2*)(Ax+o)=w;
                    else { float2 t2=*(const float2*)(Ax+o); float2 u; u.x=t2.x+v0; u.y=t2.y+v1; *(float2*)(Ax+o)=u; }
                }
                *(float2*)(Cb+o)=w;
            }
        }
    }
}

// ---------------- launch ----------------
extern "C" void kernel_launch(void* const* d_in, const int* in_sizes, int n_in,
                              void* d_out, int out_size){
    const float* x=(const float*)d_in[0];
    const float* adj=(const float*)d_in[1];
    const float* mask=(const float*)d_in[2];
    const float* dist=(const float*)d_in[3];
    const float* W1=(const float*)d_in[4];
    const float* b1=(const float*)d_in[5];
    const float* W2=(const float*)d_in[6];
    const float* b2=(const float*)d_in[7];
    const float* W3=(const float*)d_in[8];
    const float* b3=(const float*)d_in[9];
    const float* ln1g=(const float*)d_in[10];
    const float* ln1b=(const float*)d_in[11];
    const float* Wq=(const float*)d_in[12];
    const float* Wk=(const float*)d_in[13];
    const float* Wv=(const float*)d_in[14];
    const float* Wo=(const float*)d_in[15];
    const float* bo=(const float*)d_in[16];
    const float* ln2g=(const float*)d_in[17];
    const float* ln2b=(const float*)d_in[18];
    const float* Wf1=(const float*)d_in[19];
    const float* bf1=(const float*)d_in[20];
    const float* Wf2=(const float*)d_in[21];
    const float* bf2=(const float*)d_in[22];
    float* out=(float*)d_out;

    float *dis,*an,*t,*g,*res,*h,*q,*k,*v,*s,*y,*att;
    cudaGetSymbolAddress((void**)&dis,d_dis);
    cudaGetSymbolAddress((void**)&an,d_an);
    cudaGetSymbolAddress((void**)&t,d_t);
    cudaGetSymbolAddress((void**)&g,d_g);
    cudaGetSymbolAddress((void**)&res,d_res);
    cudaGetSymbolAddress((void**)&h,d_h);
    cudaGetSymbolAddress((void**)&q,d_q);
    cudaGetSymbolAddress((void**)&k,d_k);
    cudaGetSymbolAddress((void**)&v,d_v);
    cudaGetSymbolAddress((void**)&s,d_s);
    cudaGetSymbolAddress((void**)&y,d_y);
    cudaGetSymbolAddress((void**)&att,d_att);

    cudaFuncSetAttribute(tgemm, cudaFuncAttributeMaxDynamicSharedMemorySize, SMEM_BYTES);
    const long Z=0;

    // prep
    deg_kernel<<<Mrows,256>>>(adj,dis);
    an_build<<<(Bb*Nn*Nn)/256,256>>>(adj,dis,an);

    // GCN layer 1:  t = x@W1 ; g = relu(An@t+b1)*mask, res=g
    tgemm<<<dim3(2,128,1),256,SMEM_BYTES>>>(x,W1,t, 0,0,0,0, 0,0,
        128,128,256,256, Z,Z,Z,Z,Z,Z,Z,Z,Z, 1,0,1.0f,0);
    tgemm<<<dim3(2,2,Bb),256,SMEM_BYTES>>>(an,t,g, b1,mask,0,0, res,1,
        256,256,256,256, 65536L,Z, 65536L,Z, 65536L,Z, Z,Z, 256L, 1,0,1.0f,1);
    // layer 2
    tgemm<<<dim3(2,128,1),256,SMEM_BYTES>>>(g,W2,t, 0,0,0,0, 0,0,
        256,256,256,256, Z,Z,Z,Z,Z,Z,Z,Z,Z, 1,0,1.0f,0);
    tgemm<<<dim3(2,2,Bb),256,SMEM_BYTES>>>(an,t,g, b2,mask,0,0, res,0,
        256,256,256,256, 65536L,Z, 65536L,Z, 65536L,Z, Z,Z, 256L, 1,0,1.0f,1);
    // layer 3
    tgemm<<<dim3(2,128,1),256,SMEM_BYTES>>>(g,W3,t, 0,0,0,0, 0,0,
        256,256,256,256, Z,Z,Z,Z,Z,Z,Z,Z,Z, 1,0,1.0f,0);
    tgemm<<<dim3(2,2,Bb),256,SMEM_BYTES>>>(an,t,g, b3,mask,0,0, res,0,
        256,256,256,256, 65536L,Z, 65536L,Z, 65536L,Z, Z,Z, 256L, 1,0,1.0f,1);

    // LN1 + QKV
    ln_kernel<<<Mrows,256>>>(res,ln1g,ln1b,h);
    tgemm<<<dim3(16,128,1),256,SMEM_BYTES>>>(h,Wq,q, 0,0,0,0, 0,0,
        256,256,2048,2048, Z,Z,Z,Z,Z,Z,Z,Z,Z, 1,0,1.0f,0);
    tgemm<<<dim3(16,128,1),256,SMEM_BYTES>>>(h,Wk,k, 0,0,0,0, 0,0,
        256,256,2048,2048, Z,Z,Z,Z,Z,Z,Z,Z,Z, 1,0,1.0f,0);
    tgemm<<<dim3(16,128,1),256,SMEM_BYTES>>>(h,Wv,v, 0,0,0,0, 0,0,
        256,256,2048,2048, Z,Z,Z,Z,Z,Z,Z,Z,Z, 1,0,1.0f,0);

    // scores: s[b,h] = (q@k^T)/16 + dist[b]
    tgemm<<<dim3(2,2,Bb*Hh),256,SMEM_BYTES>>>(q,k,s, 0,0,dist,0, 0,0,
        256,2048,2048,256, 524288L,256L, 524288L,256L, 524288L,65536L, 65536L,Z, Z,
        Hh,1,0.0625f,0);
    softmax_kernel<<<Bb*Hh*Nn,256>>>(s,mask);
    // y[b,h] = a@v (written in (b,n,h,e) layout)
    tgemm<<<dim3(2,2,Bb*Hh),256,SMEM_BYTES>>>(s,v,y, 0,0,0,0, 0,0,
        256,256,2048,2048, 524288L,65536L, 524288L,256L, 524288L,256L, Z,Z, Z,
        Hh,0,1.0f,0);

    // att = (y@Wo+bo)*mask + res
    tgemm<<<dim3(2,128,1),256,SMEM_BYTES>>>(y,Wo,att, bo,mask,res,0, 0,0,
        2048,2048,256,256, Z,Z,Z,Z,Z,Z,Z,Z,Z, 1,0,1.0f,0);

    // FFN
    ln_kernel<<<Mrows,256>>>(att,ln2g,ln2b,h);
    tgemm<<<dim3(8,128,1),256,SMEM_BYTES>>>(h,Wf1,t, bf1,0,0,0, 0,0,
        256,256,1024,1024, Z,Z,Z,Z,Z,Z,Z,Z,Z, 1,0,1.0f,2);
    tgemm<<<dim3(2,128,1),256,SMEM_BYTES>>>(t,Wf2,out, bf2,mask,att,res, 0,0,
        1024,1024,256,256, Z,Z,Z,Z,Z,Z,Z,Z,Z, 1,0,1.0f,0);
}

// round 6
// speedup vs baseline: 3.7729x; 1.0260x over previous
#include <cuda_runtime.h>
#include <math.h>
#include <stdint.h>

#define Bb 64
#define Nn 256
#define INd 128
#define Ee 256
#define Hh 8
#define Ff 1024
#define Mrows (Bb*Nn)
#define HE (Hh*Ee)

// ---------------- scratch ----------------
__device__ float d_dis[Mrows];
__device__ float d_an [(size_t)Bb*Nn*Nn];
__device__ float d_t  [(size_t)Mrows*Ff];
__device__ float d_g  [(size_t)Mrows*Ee];
__device__ float d_res[(size_t)Mrows*Ee];
__device__ float d_h  [(size_t)Mrows*Ee];
__device__ float d_q  [(size_t)Mrows*HE];
__device__ float d_k  [(size_t)Mrows*HE];
__device__ float d_v  [(size_t)Mrows*HE];
__device__ float d_y  [(size_t)Mrows*HE];
__device__ float d_att[(size_t)Mrows*Ee];

// ---------------- asm helpers ----------------
__device__ __forceinline__ uint32_t smem_u32(const void* p){
    uint32_t a; asm("{ .reg .u64 t; cvta.to.shared.u64 t, %1; cvt.u32.u64 %0, t; }":"=r"(a):"l"(p)); return a; }
#define CP16(dst,src) asm volatile("cp.async.cg.shared.global [%0], [%1], 16;"::"r"(dst),"l"(src))
#define CP4(dst,src)  asm volatile("cp.async.ca.shared.global [%0], [%1], 4;"::"r"(dst),"l"(src))
#define CP_COMMIT()   asm volatile("cp.async.commit_group;")
#define CP_WAIT0()    asm volatile("cp.async.wait_group 0;")
#define CP_WAIT1()    asm volatile("cp.async.wait_group 1;")
#define CP_WAIT2()    asm volatile("cp.async.wait_group 2;")
#define CVT(u,f)      asm("cvt.rna.tf32.f32 %0, %1;":"=r"(u):"f"(f))
#define MMA(c,a,b) asm volatile( \
  "mma.sync.aligned.m16n8k8.row.col.f32.tf32.tf32.f32 {%0,%1,%2,%3},{%4,%5,%6,%7},{%8,%9},{%0,%1,%2,%3};" \
  : "+f"((c)[0]),"+f"((c)[1]),"+f"((c)[2]),"+f"((c)[3]) \
  : "r"((a)[0]),"r"((a)[1]),"r"((a)[2]),"r"((a)[3]),"r"((b)[0]),"r"((b)[1]))

// ---------------- small kernels ----------------
__global__ void deg_kernel(const float* __restrict__ adj, float* __restrict__ dis){
    int row=blockIdx.x, b=row>>8, i=row&255, t=threadIdx.x;
    const float* a=adj+(size_t)b*Nn*Nn+(size_t)i*Nn;
    float v=(t==i)?1.0f:a[t];
    __shared__ float sh[8];
    #pragma unroll
    for(int o=16;o>0;o>>=1) v+=__shfl_xor_sync(0xffffffffu,v,o);
    if((t&31)==0) sh[t>>5]=v;
    __syncthreads();
    if(t==0){ float s=0.f; for(int w=0;w<8;w++) s+=sh[w]; dis[row]=rsqrtf(fmaxf(s,1.0f)); }
}
__global__ void an_build(const float* __restrict__ adj, const float* __restrict__ dis,
                         float* __restrict__ An){
    long idx=(long)blockIdx.x*256+threadIdx.x;
    int j=(int)(idx&255); long t=idx>>8; int i=(int)(t&255); int b=(int)(t>>8);
    float a=(i==j)?1.0f:adj[idx];
    An[idx]=a*dis[b*256+i]*dis[b*256+j];
}
__global__ void ln_kernel(const float* __restrict__ x, const float* __restrict__ g,
                          const float* __restrict__ be, float* __restrict__ out){
    int row=blockIdx.x, t=threadIdx.x;
    float v=x[(size_t)row*Ee+t];
    __shared__ float sh[8]; __shared__ float mv[2];
    float s=v;
    #pragma unroll
    for(int o=16;o>0;o>>=1) s+=__shfl_xor_sync(0xffffffffu,s,o);
    if((t&31)==0) sh[t>>5]=s;
    __syncthreads();
    if(t==0){ float m=0.f; for(int w=0;w<8;w++) m+=sh[w]; mv[0]=m*(1.0f/Ee); }
    __syncthreads();
    float m=mv[0], d=v-m; s=d*d;
    #pragma unroll
    for(int o=16;o>0;o>>=1) s+=__shfl_xor_sync(0xffffffffu,s,o);
    if((t&31)==0) sh[t>>5]=s;
    __syncthreads();
    if(t==0){ float vv=0.f; for(int w=0;w<8;w++) vv+=sh[w]; mv[1]=rsqrtf(vv*(1.0f/Ee)+1e-5f); }
    __syncthreads();
    out[(size_t)row*Ee+t]=d*mv[1]*g[t]+be[t];
}

// ---------------- tf32 GEMM, 128x128 tile, 3-stage cp.async ----------------
#define APADF 36
#define BPADF 136
#define ABUF_F (128*APADF)
#define BBUF_F (32*BPADF)
#define SMEM_BYTES (3*(ABUF_F+BBUF_F)*4)   // 107520

__global__ void __launch_bounds__(256,2) tgemm(
    const float* __restrict__ A, const float* __restrict__ B, float* __restrict__ C,
    const float* __restrict__ bias, const float* __restrict__ rowmask,
    const float* __restrict__ res1, const float* __restrict__ res2,
    float* __restrict__ aux, int auxinit,
    int K, int lda, int ldb, int ldc,
    long sAb, long sAh, long sBb, long sBh, long sCb, long sCh,
    long sR1b, long sR1h, long sMb,
    int Hdiv, int transB, float alpha, int act)
{
    extern __shared__ float sm[];
    int tid=threadIdx.x, wid=tid>>5, lane=tid&31;
    int z=blockIdx.z, zb=z/Hdiv, zh=z-zb*Hdiv;
    int row0=blockIdx.y*128, col0=blockIdx.x*128;

    const float* Ag = A + zb*sAb + zh*sAh + (long)row0*lda;
    const float* Bg = B + zb*sBb + zh*sBh;
    float* Cb = C + zb*sCb + zh*sCh;
    const float* R1 = res1 ? res1 + zb*sR1b + zh*sR1h : (const float*)0;
    float* Ax = aux ? aux + zb*sCb + zh*sCh : (float*)0;

    uint32_t sbase = smem_u32(sm);
    uint32_t aoffB[3], boffB[3];
    #pragma unroll
    for(int i=0;i<3;i++){ aoffB[i]=sbase+i*ABUF_F*4; boffB[i]=sbase+(3*ABUF_F+i*BBUF_F)*4; }

    auto loadA = [&](int buf, int k0){
        #pragma unroll
        for(int i=0;i<4;i++){
            int f4 = tid + i*256;
            int row = f4>>3, c4 = f4&7;
            CP16(aoffB[buf] + (uint32_t)(row*APADF + c4*4)*4,
                 Ag + (long)row*lda + k0 + c4*4);
        }
    };
    auto loadB = [&](int buf, int k0){
        if(!transB){
            #pragma unroll
            for(int i=0;i<4;i++){
                int f4 = tid + i*256;
                int kr = f4>>5, c4 = f4&31;
                CP16(boffB[buf] + (uint32_t)(kr*BPADF + c4*4)*4,
                     Bg + (long)(k0+kr)*ldb + col0 + c4*4);
            }
        } else {
            #pragma unroll
            for(int i=0;i<16;i++){
                int e = tid + i*256;
                int n = e>>5, kk = e&31;
                CP4(boffB[buf] + (uint32_t)(kk*BPADF + n)*4,
                    Bg + (long)(col0+n)*ldb + k0 + kk);
            }
        }
    };

    int wm0 = (wid>>2)*64;
    int wn0 = (wid&3)*32;
    int tq = lane>>2, tr = lane&3;

    float cacc[4][4][4];
    #pragma unroll
    for(int a0=0;a0<4;a0++)
        #pragma unroll
        for(int b0=0;b0<4;b0++)
            #pragma unroll
            for(int c0=0;c0<4;c0++) cacc[a0][b0][c0]=0.f;

    int KT = K >> 5;
    loadA(0,0); loadB(0,0); CP_COMMIT();
    loadA(1,32); loadB(1,32); CP_COMMIT();

    for(int kt=0; kt<KT; kt++){
        int buf = kt%3;
        if(kt+2<KT){ int nb=(kt+2)%3; loadA(nb,(kt+2)*32); loadB(nb,(kt+2)*32); }
        CP_COMMIT();
        CP_WAIT2();
        __syncthreads();

        const float* As_ = sm + buf*ABUF_F;
        const float* Bs_ = sm + 3*ABUF_F + buf*BBUF_F;
        #pragma unroll
        for(int ks=0;ks<4;ks++){
            uint32_t af[4][4], bf[4][2];
            #pragma unroll
            for(int mt=0;mt<4;mt++){
                const float* ap = As_ + (wm0+mt*16+tq)*APADF + ks*8 + tr;
                CVT(af[mt][0], ap[0]);
                CVT(af[mt][1], ap[8*APADF]);
                CVT(af[mt][2], ap[4]);
                CVT(af[mt][3], ap[8*APADF+4]);
            }
            #pragma unroll
            for(int nt=0;nt<4;nt++){
                const float* bp = Bs_ + (ks*8+tr)*BPADF + wn0 + nt*8 + tq;
                CVT(bf[nt][0], bp[0]);
                CVT(bf[nt][1], bp[4*BPADF]);
            }
            #pragma unroll
            for(int mt=0;mt<4;mt++)
                #pragma unroll
                for(int nt=0;nt<4;nt++)
                    MMA(cacc[mt][nt], af[mt], bf[nt]);
        }
        __syncthreads();
    }

    #pragma unroll
    for(int mt=0;mt<4;mt++){
        #pragma unroll
        for(int hf=0;hf<2;hf++){
            int r = row0 + wm0 + mt*16 + tq + hf*8;
            float rm = rowmask ? rowmask[zb*sMb + r] : 1.0f;
            #pragma unroll
            for(int nt=0;nt<4;nt++){
                int cc = col0 + wn0 + nt*8 + tr*2;
                float v0 = cacc[mt][nt][hf*2+0]*alpha;
                float v1 = cacc[mt][nt][hf*2+1]*alpha;
                if(bias){ v0+=bias[cc]; v1+=bias[cc+1]; }
                if(act==1){ v0=fmaxf(v0,0.f); v1=fmaxf(v1,0.f); }
                else if(act==2){
                    v0=0.5f*v0*(1.0f+erff(v0*0.70710678118654752f));
                    v1=0.5f*v1*(1.0f+erff(v1*0.70710678118654752f));
                }
                v0*=rm; v1*=rm;
                long o=(long)r*ldc+cc;
                if(R1){ float2 t2=*(const float2*)(R1+o); v0+=t2.x; v1+=t2.y; }
                if(res2){ float2 t2=*(const float2*)(res2+o); v0+=t2.x; v1+=t2.y; }
                float2 w; w.x=v0; w.y=v1;
                if(Ax){
                    if(auxinit) *(float2*)(Ax+o)=w;
                    else { float2 t2=*(const float2*)(Ax+o); float2 u; u.x=t2.x+v0; u.y=t2.y+v1; *(float2*)(Ax+o)=u; }
                }
                *(float2*)(Cb+o)=w;
            }
        }
    }
}

// ---------------- fused attention ----------------
// grid (1, 2, B*H); block 512 (16 warps, 2m x 8n); per CTA: 128 q rows, all 256 keys.
// Phase1: S = q@k^T/16 + dist -> masked softmax (SMEM reduce) -> P (tf32) into q's SMEM.
// Phase2: Y = P@v -> y (b,n,h,e).
#define FA_SMEM ((8*4608 + 2*8448)*4)   // 215040 bytes

__global__ void __launch_bounds__(512,1) fused_attn(
    const float* __restrict__ q, const float* __restrict__ k, const float* __restrict__ v,
    const float* __restrict__ dist, const float* __restrict__ mask, float* __restrict__ y)
{
    extern __shared__ float sm[];
    float* qp  = sm;                 // 8 chunks of [128][36]
    float* kb0 = sm + 8*4608;
    float* kb1 = kb0 + 8448;
    float* redA    = kb1;            // [128][8]  (after phase-1 mainloop)
    float* rowmax_ = kb1 + 1024;     // [128]
    float* rowsum_ = kb1 + 1152;     // [128]
    float* mcol    = kb1 + 1280;     // [256]

    int tid=threadIdx.x, wid=tid>>5, lane=tid&31;
    int z=blockIdx.z, b=z>>3, h=z&7;
    int row0=blockIdx.y*128;
    const float* qg = q + ((long)b*256)*2048 + (long)h*256;
    const float* kg = k + ((long)b*256)*2048 + (long)h*256;
    const float* vg = v + ((long)b*256)*2048 + (long)h*256;
    const float* dg = dist + (long)b*65536;
    float* yg = y + ((long)b*256)*2048 + (long)h*256;

    uint32_t qpB = smem_u32(qp);
    uint32_t kbB[2] = { smem_u32(kb0), smem_u32(kb1) };

    // load q: 8 chunks (tf32 layout, raw fp32 values)
    #pragma unroll
    for(int i=0;i<16;i++){
        int f4 = tid + i*512;
        int ch = f4>>10, rr=(f4>>3)&127, c4=f4&7;
        CP16(qpB + (uint32_t)(ch*4608 + rr*36 + c4*4)*4,
             qg + (long)(row0+rr)*2048 + ch*32 + c4*4);
    }
    // k tile 0 (transposed to [kk][n])
    #pragma unroll
    for(int i=0;i<16;i++){
        int e=tid+i*512; int n=e>>5, kk=e&31;
        CP4(kbB[0] + (uint32_t)(kk*264+n)*4, kg + (long)n*2048 + kk);
    }
    CP_COMMIT();

    int wn_idx = wid&7, wm_idx = wid>>3;
    int wm0 = wm_idx*64, wn0 = wn_idx*32;
    int tq = lane>>2, tr = lane&3;

    float cacc[4][4][4];
    #pragma unroll
    for(int a0=0;a0<4;a0++)
        #pragma unroll
        for(int b0=0;b0<4;b0++)
            #pragma unroll
            for(int c0=0;c0<4;c0++) cacc[a0][b0][c0]=0.f;

    // ---- phase 1: S = q @ k^T ----
    for(int kt=0;kt<8;kt++){
        if(kt+1<8){
            int nb=(kt+1)&1;
            #pragma unroll
            for(int i=0;i<16;i++){
                int e=tid+i*512; int n=e>>5, kk=e&31;
                CP4(kbB[nb] + (uint32_t)(kk*264+n)*4, kg + (long)n*2048 + (kt+1)*32 + kk);
            }
            CP_COMMIT(); CP_WAIT1();
        } else CP_WAIT0();
        __syncthreads();
        const float* As_ = qp + kt*4608;
        const float* Bs_ = (kt&1)? kb1 : kb0;
        #pragma unroll
        for(int ks=0;ks<4;ks++){
            uint32_t af[4][4], bf[4][2];
            #pragma unroll
            for(int mt=0;mt<4;mt++){
                const float* ap = As_ + (wm0+mt*16+tq)*36 + ks*8 + tr;
                CVT(af[mt][0], ap[0]);
                CVT(af[mt][1], ap[8*36]);
                CVT(af[mt][2], ap[4]);
                CVT(af[mt][3], ap[8*36+4]);
            }
            #pragma unroll
            for(int nt=0;nt<4;nt++){
                const float* bp = Bs_ + (ks*8+tr)*264 + wn0 + nt*8 + tq;
                CVT(bf[nt][0], bp[0]);
                CVT(bf[nt][1], bp[4*264]);
            }
            #pragma unroll
            for(int mt=0;mt<4;mt++)
                #pragma unroll
                for(int nt=0;nt<4;nt++)
                    MMA(cacc[mt][nt], af[mt], bf[nt]);
        }
        __syncthreads();
    }

    // prefetch v tile 0 into kb0 (overlaps softmax)
    #pragma unroll
    for(int i=0;i<4;i++){
        int f4=tid+i*512; int kr=f4>>6, c4=f4&63;
        CP16(kbB[0] + (uint32_t)(kr*264+c4*4)*4, vg + (long)kr*2048 + c4*4);
    }
    CP_COMMIT();

    // ---- masked softmax ----
    if(tid<256) mcol[tid]=mask[b*256+tid];
    __syncthreads();

    // pass A: scale + dist, local/warp/CTA max
    #pragma unroll
    for(int mt=0;mt<4;mt++){
        #pragma unroll
        for(int hf=0;hf<2;hf++){
            int rl = wm0+mt*16+tq+hf*8;
            float lm=-3.0e38f;
            #pragma unroll
            for(int nt=0;nt<4;nt++){
                int c = wn0+nt*8+tr*2;
                float2 dd = *(const float2*)(dg + (long)(row0+rl)*256 + c);
                float s0 = cacc[mt][nt][hf*2+0]*0.0625f + dd.x;
                float s1 = cacc[mt][nt][hf*2+1]*0.0625f + dd.y;
                cacc[mt][nt][hf*2+0]=s0; cacc[mt][nt][hf*2+1]=s1;
                if(mcol[c]  !=0.0f) lm=fmaxf(lm,s0);
                if(mcol[c+1]!=0.0f) lm=fmaxf(lm,s1);
            }
            lm = fmaxf(lm, __shfl_xor_sync(0xffffffffu,lm,1));
            lm = fmaxf(lm, __shfl_xor_sync(0xffffffffu,lm,2));
            if(tr==0) redA[rl*8+wn_idx]=lm;
        }
    }
    __syncthreads();
    if(tid<128){ float m=-3.0e38f;
        #pragma unroll
        for(int w=0;w<8;w++) m=fmaxf(m,redA[tid*8+w]);
        rowmax_[tid]=m; }
    __syncthreads();

    // pass B: exp + sum
    #pragma unroll
    for(int mt=0;mt<4;mt++){
        #pragma unroll
        for(int hf=0;hf<2;hf++){
            int rl = wm0+mt*16+tq+hf*8;
            float mx = rowmax_[rl];
            float ls=0.f;
            #pragma unroll
            for(int nt=0;nt<4;nt++){
                int c = wn0+nt*8+tr*2;
                float p0 = (mcol[c]  !=0.0f)? expf(cacc[mt][nt][hf*2+0]-mx) : 0.0f;
                float p1 = (mcol[c+1]!=0.0f)? expf(cacc[mt][nt][hf*2+1]-mx) : 0.0f;
                cacc[mt][nt][hf*2+0]=p0; cacc[mt][nt][hf*2+1]=p1;
                ls += p0+p1;
            }
            ls += __shfl_xor_sync(0xffffffffu,ls,1);
            ls += __shfl_xor_sync(0xffffffffu,ls,2);
            if(tr==0) redA[rl*8+wn_idx]=ls;
        }
    }
    __syncthreads();
    if(tid<128){ float s=0.f;
        #pragma unroll
        for(int w=0;w<8;w++) s+=redA[tid*8+w];
        rowsum_[tid]=s; }
    __syncthreads();

    // pass C: normalize, round to tf32, store P into qp chunks; reset acc
    #pragma unroll
    for(int mt=0;mt<4;mt++){
        #pragma unroll
        for(int hf=0;hf<2;hf++){
            int rl = wm0+mt*16+tq+hf*8;
            float sum = rowsum_[rl];
            float inv = (sum>0.0f)? 1.0f/sum : 0.0f;
            #pragma unroll
            for(int nt=0;nt<4;nt++){
                int cl = nt*8+tr*2;
                float p0 = cacc[mt][nt][hf*2+0]*inv;
                float p1 = cacc[mt][nt][hf*2+1]*inv;
                uint32_t u0,u1; CVT(u0,p0); CVT(u1,p1);
                float2 w; w.x=__uint_as_float(u0); w.y=__uint_as_float(u1);
                *(float2*)(qp + wn_idx*4608 + rl*36 + cl) = w;
                cacc[mt][nt][hf*2+0]=0.f; cacc[mt][nt][hf*2+1]=0.f;
            }
        }
    }
    __syncthreads();

    // ---- phase 2: Y = P @ v ----
    for(int kt=0;kt<8;kt++){
        if(kt+1<8){
            int nb=(kt+1)&1;
            #pragma unroll
            for(int i=0;i<4;i++){
                int f4=tid+i*512; int kr=f4>>6, c4=f4&63;
                CP16(kbB[nb] + (uint32_t)(kr*264+c4*4)*4,
                     vg + (long)((kt+1)*32+kr)*2048 + c4*4);
            }
            CP_COMMIT(); CP_WAIT1();
        } else CP_WAIT0();
        __syncthreads();
        const float* As_ = qp + kt*4608;
        const float* Bs_ = (kt&1)? kb1 : kb0;
        #pragma unroll
        for(int ks=0;ks<4;ks++){
            uint32_t af[4][4], bf[4][2];
            #pragma unroll
            for(int mt=0;mt<4;mt++){
                const float* ap = As_ + (wm0+mt*16+tq)*36 + ks*8 + tr;
                af[mt][0]=__float_as_uint(ap[0]);
                af[mt][1]=__float_as_uint(ap[8*36]);
                af[mt][2]=__float_as_uint(ap[4]);
                af[mt][3]=__float_as_uint(ap[8*36+4]);
            }
            #pragma unroll
            for(int nt=0;nt<4;nt++){
                const float* bp = Bs_ + (ks*8+tr)*264 + wn0 + nt*8 + tq;
                CVT(bf[nt][0], bp[0]);
                CVT(bf[nt][1], bp[4*264]);
            }
            #pragma unroll
            for(int mt=0;mt<4;mt++)
                #pragma unroll
                for(int nt=0;nt<4;nt++)
                    MMA(cacc[mt][nt], af[mt], bf[nt]);
        }
        __syncthreads();
    }

    // epilogue: write y
    #pragma unroll
    for(int mt=0;mt<4;mt++){
        #pragma unroll
        for(int hf=0;hf<2;hf++){
            int rl = wm0+mt*16+tq+hf*8;
            #pragma unroll
            for(int nt=0;nt<4;nt++){
                int c = wn0+nt*8+tr*2;
                float2 w; w.x=cacc[mt][nt][hf*2+0]; w.y=cacc[mt][nt][hf*2+1];
                *(float2*)(yg + (long)(row0+rl)*2048 + c) = w;
            }
        }
    }
}

// ---------------- launch ----------------
extern "C" void kernel_launch(void* const* d_in, const int* in_sizes, int n_in,
                              void* d_out, int out_size){
    const float* x=(const float*)d_in[0];
    const float* adj=(const float*)d_in[1];
    const float* mask=(const float*)d_in[2];
    const float* dist=(const float*)d_in[3];
    const float* W1=(const float*)d_in[4];
    const float* b1=(const float*)d_in[5];
    const float* W2=(const float*)d_in[6];
    const float* b2=(const float*)d_in[7];
    const float* W3=(const float*)d_in[8];
    const float* b3=(const float*)d_in[9];
    const float* ln1g=(const float*)d_in[10];
    const float* ln1b=(const float*)d_in[11];
    const float* Wq=(const float*)d_in[12];
    const float* Wk=(const float*)d_in[13];
    const float* Wv=(const float*)d_in[14];
    const float* Wo=(const float*)d_in[15];
    const float* bo=(const float*)d_in[16];
    const float* ln2g=(const float*)d_in[17];
    const float* ln2b=(const float*)d_in[18];
    const float* Wf1=(const float*)d_in[19];
    const float* bf1=(const float*)d_in[20];
    const float* Wf2=(const float*)d_in[21];
    const float* bf2=(const float*)d_in[22];
    float* out=(float*)d_out;

    float *dis,*an,*t,*g,*res,*h,*q,*k,*v,*y,*att;
    cudaGetSymbolAddress((void**)&dis,d_dis);
    cudaGetSymbolAddress((void**)&an,d_an);
    cudaGetSymbolAddress((void**)&t,d_t);
    cudaGetSymbolAddress((void**)&g,d_g);
    cudaGetSymbolAddress((void**)&res,d_res);
    cudaGetSymbolAddress((void**)&h,d_h);
    cudaGetSymbolAddress((void**)&q,d_q);
    cudaGetSymbolAddress((void**)&k,d_k);
    cudaGetSymbolAddress((void**)&v,d_v);
    cudaGetSymbolAddress((void**)&y,d_y);
    cudaGetSymbolAddress((void**)&att,d_att);

    cudaFuncSetAttribute(tgemm, cudaFuncAttributeMaxDynamicSharedMemorySize, SMEM_BYTES);
    cudaFuncSetAttribute(fused_attn, cudaFuncAttributeMaxDynamicSharedMemorySize, FA_SMEM);
    const long Z=0;

    deg_kernel<<<Mrows,256>>>(adj,dis);
    an_build<<<(Bb*Nn*Nn)/256,256>>>(adj,dis,an);

    // GCN layer 1
    tgemm<<<dim3(2,128,1),256,SMEM_BYTES>>>(x,W1,t, 0,0,0,0, 0,0,
        128,128,256,256, Z,Z,Z,Z,Z,Z,Z,Z,Z, 1,0,1.0f,0);
    tgemm<<<dim3(2,2,Bb),256,SMEM_BYTES>>>(an,t,g, b1,mask,0,0, res,1,
        256,256,256,256, 65536L,Z, 65536L,Z, 65536L,Z, Z,Z, 256L, 1,0,1.0f,1);
    // layer 2
    tgemm<<<dim3(2,128,1),256,SMEM_BYTES>>>(g,W2,t, 0,0,0,0, 0,0,
        256,256,256,256, Z,Z,Z,Z,Z,Z,Z,Z,Z, 1,0,1.0f,0);
    tgemm<<<dim3(2,2,Bb),256,SMEM_BYTES>>>(an,t,g, b2,mask,0,0, res,0,
        256,256,256,256, 65536L,Z, 65536L,Z, 65536L,Z, Z,Z, 256L, 1,0,1.0f,1);
    // layer 3
    tgemm<<<dim3(2,128,1),256,SMEM_BYTES>>>(g,W3,t, 0,0,0,0, 0,0,
        256,256,256,256, Z,Z,Z,Z,Z,Z,Z,Z,Z, 1,0,1.0f,0);
    tgemm<<<dim3(2,2,Bb),256,SMEM_BYTES>>>(an,t,g, b3,mask,0,0, res,0,
        256,256,256,256, 65536L,Z, 65536L,Z, 65536L,Z, Z,Z, 256L, 1,0,1.0f,1);

    // LN1 + QKV
    ln_kernel<<<Mrows,256>>>(res,ln1g,ln1b,h);
    tgemm<<<dim3(16,128,1),256,SMEM_BYTES>>>(h,Wq,q, 0,0,0,0, 0,0,
        256,256,2048,2048, Z,Z,Z,Z,Z,Z,Z,Z,Z, 1,0,1.0f,0);
    tgemm<<<dim3(16,128,1),256,SMEM_BYTES>>>(h,Wk,k, 0,0,0,0, 0,0,
        256,256,2048,2048, Z,Z,Z,Z,Z,Z,Z,Z,Z, 1,0,1.0f,0);
    tgemm<<<dim3(16,128,1),256,SMEM_BYTES>>>(h,Wv,v, 0,0,0,0, 0,0,
        256,256,2048,2048, Z,Z,Z,Z,Z,Z,Z,Z,Z, 1,0,1.0f,0);

    // fused attention -> y
    fused_attn<<<dim3(1,2,Bb*Hh),512,FA_SMEM>>>(q,k,v,dist,mask,y);

    // att = (y@Wo+bo)*mask + res
    tgemm<<<dim3(2,128,1),256,SMEM_BYTES>>>(y,Wo,att, bo,mask,res,0, 0,0,
        2048,2048,256,256, Z,Z,Z,Z,Z,Z,Z,Z,Z, 1,0,1.0f,0);

    // FFN
    ln_kernel<<<Mrows,256>>>(att,ln2g,ln2b,h);
    tgemm<<<dim3(8,128,1),256,SMEM_BYTES>>>(h,Wf1,t, bf1,0,0,0, 0,0,
        256,256,1024,1024, Z,Z,Z,Z,Z,Z,Z,Z,Z, 1,0,1.0f,2);
    tgemm<<<dim3(2,128,1),256,SMEM_BYTES>>>(t,Wf2,out, bf2,mask,att,res, 0,0,
        1024,1024,256,256, Z,Z,Z,Z,Z,Z,Z,Z,Z, 1,0,1.0f,0);
}

// round 10
// speedup vs baseline: 3.9722x; 1.0528x over previous
#include <cuda_runtime.h>
#include <cuda_fp16.h>
#include <math.h>
#include <stdint.h>

#define Bb 64
#define Nn 256
#define INd 128
#define Ee 256
#define Hh 8
#define Ff 1024
#define Mrows (Bb*Nn)
#define HE (Hh*Ee)

// ---------------- scratch ----------------
__device__ float d_dis[Mrows];
__device__ float d_an [(size_t)Bb*Nn*Nn];
__device__ float d_t  [(size_t)Mrows*Ff];
__device__ float d_g  [(size_t)Mrows*Ee];
__device__ float d_res[(size_t)Mrows*Ee];
__device__ float d_h  [(size_t)Mrows*Ee];
__device__ float d_q  [(size_t)Mrows*HE];
__device__ float d_k  [(size_t)Mrows*HE];
__device__ float d_v  [(size_t)Mrows*HE];
__device__ float d_y  [(size_t)Mrows*HE];
__device__ float d_att[(size_t)Mrows*Ee];

// ---------------- asm helpers ----------------
__device__ __forceinline__ uint32_t smem_u32(const void* p){
    uint32_t a; asm("{ .reg .u64 t; cvta.to.shared.u64 t, %1; cvt.u32.u64 %0, t; }":"=r"(a):"l"(p)); return a; }
#define CP16(dst,src) asm volatile("cp.async.cg.shared.global [%0], [%1], 16;"::"r"(dst),"l"(src))
#define CP_COMMIT()   asm volatile("cp.async.commit_group;")
#define CP_WAIT0()    asm volatile("cp.async.wait_group 0;")
#define CP_WAIT1()    asm volatile("cp.async.wait_group 1;")
#define CP_WAIT2()    asm volatile("cp.async.wait_group 2;")
// pack two fp32 -> f16x2 (low half = lo, high half = hi)
#define CVTP(u,lo,hi) asm("cvt.rn.f16x2.f32 %0, %1, %2;":"=r"(u):"f"(hi),"f"(lo))
#define MMA16(c,a,b) asm volatile( \
  "mma.sync.aligned.m16n8k16.row.col.f32.f16.f16.f32 {%0,%1,%2,%3},{%4,%5,%6,%7},{%8,%9},{%0,%1,%2,%3};" \
  : "+f"((c)[0]),"+f"((c)[1]),"+f"((c)[2]),"+f"((c)[3]) \
  : "r"((a)[0]),"r"((a)[1]),"r"((a)[2]),"r"((a)[3]),"r"((b)[0]),"r"((b)[1]))

// ---------------- small kernels ----------------
__global__ void deg_kernel(const float* __restrict__ adj, float* __restrict__ dis){
    int row=blockIdx.x, b=row>>8, i=row&255, t=threadIdx.x;
    const float* a=adj+(size_t)b*Nn*Nn+(size_t)i*Nn;
    float v=(t==i)?1.0f:a[t];
    __shared__ float sh[8];
    #pragma unroll
    for(int o=16;o>0;o>>=1) v+=__shfl_xor_sync(0xffffffffu,v,o);
    if((t&31)==0) sh[t>>5]=v;
    __syncthreads();
    if(t==0){ float s=0.f; for(int w=0;w<8;w++) s+=sh[w]; dis[row]=rsqrtf(fmaxf(s,1.0f)); }
}
__global__ void an_build(const float* __restrict__ adj, const float* __restrict__ dis,
                         float* __restrict__ An){
    long idx=(long)blockIdx.x*256+threadIdx.x;
    int j=(int)(idx&255); long t=idx>>8; int i=(int)(t&255); int b=(int)(t>>8);
    float a=(i==j)?1.0f:adj[idx];
    An[idx]=a*dis[b*256+i]*dis[b*256+j];
}
__global__ void ln_kernel(const float* __restrict__ x, const float* __restrict__ g,
                          const float* __restrict__ be, float* __restrict__ out){
    int row=blockIdx.x, t=threadIdx.x;
    float v=x[(size_t)row*Ee+t];
    __shared__ float sh[8]; __shared__ float mv[2];
    float s=v;
    #pragma unroll
    for(int o=16;o>0;o>>=1) s+=__shfl_xor_sync(0xffffffffu,s,o);
    if((t&31)==0) sh[t>>5]=s;
    __syncthreads();
    if(t==0){ float m=0.f; for(int w=0;w<8;w++) m+=sh[w]; mv[0]=m*(1.0f/Ee); }
    __syncthreads();
    float m=mv[0], d=v-m; s=d*d;
    #pragma unroll
    for(int o=16;o>0;o>>=1) s+=__shfl_xor_sync(0xffffffffu,s,o);
    if((t&31)==0) sh[t>>5]=s;
    __syncthreads();
    if(t==0){ float vv=0.f; for(int w=0;w<8;w++) vv+=sh[w]; mv[1]=rsqrtf(vv*(1.0f/Ee)+1e-5f); }
    __syncthreads();
    out[(size_t)row*Ee+t]=d*mv[1]*g[t]+be[t];
}

// ---------------- fp16-MMA GEMM, 128x128 tile, 3-stage cp.async ----------------
#define APADF 36
#define BPADF 136
#define ABUF_F (128*APADF)
#define BBUF_F (32*BPADF)
#define SMEM_BYTES (3*(ABUF_F+BBUF_F)*4)   // 107520

__global__ void __launch_bounds__(256,2) tgemm(
    const float* __restrict__ A, const float* __restrict__ B, float* __restrict__ C,
    const float* __restrict__ bias, const float* __restrict__ rowmask,
    const float* __restrict__ res1, const float* __restrict__ res2,
    float* __restrict__ aux, int auxinit,
    int K, int lda, int ldb, int ldc,
    long sAb, long sAh, long sBb, long sBh, long sCb, long sCh,
    long sR1b, long sR1h, long sMb,
    int Hdiv, float alpha, int act)
{
    extern __shared__ float sm[];
    int tid=threadIdx.x, wid=tid>>5, lane=tid&31;
    int z=blockIdx.z, zb=z/Hdiv, zh=z-zb*Hdiv;
    int row0=blockIdx.y*128, col0=blockIdx.x*128;

    const float* Ag = A + zb*sAb + zh*sAh + (long)row0*lda;
    const float* Bg = B + zb*sBb + zh*sBh;
    float* Cb = C + zb*sCb + zh*sCh;
    const float* R1 = res1 ? res1 + zb*sR1b + zh*sR1h : (const float*)0;
    float* Ax = aux ? aux + zb*sCb + zh*sCh : (float*)0;

    uint32_t sbase = smem_u32(sm);
    uint32_t aoffB[3], boffB[3];
    #pragma unroll
    for(int i=0;i<3;i++){ aoffB[i]=sbase+i*ABUF_F*4; boffB[i]=sbase+(3*ABUF_F+i*BBUF_F)*4; }

    auto loadA = [&](int buf, int k0){
        #pragma unroll
        for(int i=0;i<4;i++){
            int f4 = tid + i*256;
            int row = f4>>3, c4 = f4&7;
            CP16(aoffB[buf] + (uint32_t)(row*APADF + c4*4)*4,
                 Ag + (long)row*lda + k0 + c4*4);
        }
    };
    auto loadB = [&](int buf, int k0){
        #pragma unroll
        for(int i=0;i<4;i++){
            int f4 = tid + i*256;
            int kr = f4>>5, c4 = f4&31;
            CP16(boffB[buf] + (uint32_t)(kr*BPADF + c4*4)*4,
                 Bg + (long)(k0+kr)*ldb + col0 + c4*4);
        }
    };

    int wm0 = (wid>>2)*64;
    int wn0 = (wid&3)*32;
    int tq = lane>>2, tr = lane&3;

    float cacc[4][4][4];
    #pragma unroll
    for(int a0=0;a0<4;a0++)
        #pragma unroll
        for(int b0=0;b0<4;b0++)
            #pragma unroll
            for(int c0=0;c0<4;c0++) cacc[a0][b0][c0]=0.f;

    int KT = K >> 5;
    loadA(0,0); loadB(0,0); CP_COMMIT();
    loadA(1,32); loadB(1,32); CP_COMMIT();

    for(int kt=0; kt<KT; kt++){
        int buf = kt%3;
        if(kt+2<KT){ int nb=(kt+2)%3; loadA(nb,(kt+2)*32); loadB(nb,(kt+2)*32); }
        CP_COMMIT();
        CP_WAIT2();
        __syncthreads();

        const float* As_ = sm + buf*ABUF_F;
        const float* Bs_ = sm + 3*ABUF_F + buf*BBUF_F;
        #pragma unroll
        for(int ks=0;ks<2;ks++){           // two k16 steps per BK=32
            uint32_t af[4][4], bf[4][2];
            #pragma unroll
            for(int mt=0;mt<4;mt++){
                const float* ap = As_ + (wm0+mt*16+tq)*APADF + ks*16 + 2*tr;
                float2 v0=*(const float2*)(ap);
                float2 v1=*(const float2*)(ap+8*APADF);
                float2 v2=*(const float2*)(ap+8);
                float2 v3=*(const float2*)(ap+8*APADF+8);
                CVTP(af[mt][0], v0.x, v0.y);
                CVTP(af[mt][1], v1.x, v1.y);
                CVTP(af[mt][2], v2.x, v2.y);
                CVTP(af[mt][3], v3.x, v3.y);
            }
            #pragma unroll
            for(int nt=0;nt<4;nt++){
                const float* bp = Bs_ + (ks*16 + 2*tr)*BPADF + wn0 + nt*8 + tq;
                CVTP(bf[nt][0], bp[0], bp[BPADF]);
                CVTP(bf[nt][1], bp[8*BPADF], bp[9*BPADF]);
            }
            #pragma unroll
            for(int mt=0;mt<4;mt++)
                #pragma unroll
                for(int nt=0;nt<4;nt++)
                    MMA16(cacc[mt][nt], af[mt], bf[nt]);
        }
        __syncthreads();
    }

    #pragma unroll
    for(int mt=0;mt<4;mt++){
        #pragma unroll
        for(int hf=0;hf<2;hf++){
            int r = row0 + wm0 + mt*16 + tq + hf*8;
            float rm = rowmask ? rowmask[zb*sMb + r] : 1.0f;
            #pragma unroll
            for(int nt=0;nt<4;nt++){
                int cc = col0 + wn0 + nt*8 + tr*2;
                float v0 = cacc[mt][nt][hf*2+0]*alpha;
                float v1 = cacc[mt][nt][hf*2+1]*alpha;
                if(bias){ v0+=bias[cc]; v1+=bias[cc+1]; }
                if(act==1){ v0=fmaxf(v0,0.f); v1=fmaxf(v1,0.f); }
                else if(act==2){
                    v0=0.5f*v0*(1.0f+erff(v0*0.70710678118654752f));
                    v1=0.5f*v1*(1.0f+erff(v1*0.70710678118654752f));
                }
                v0*=rm; v1*=rm;
                long o=(long)r*ldc+cc;
                if(R1){ float2 t2=*(const float2*)(R1+o); v0+=t2.x; v1+=t2.y; }
                if(res2){ float2 t2=*(const float2*)(res2+o); v0+=t2.x; v1+=t2.y; }
                float2 w; w.x=v0; w.y=v1;
                if(Ax){
                    if(auxinit) *(float2*)(Ax+o)=w;
                    else { float2 t2=*(const float2*)(Ax+o); float2 u; u.x=t2.x+v0; u.y=t2.y+v1; *(float2*)(Ax+o)=u; }
                }
                *(float2*)(Cb+o)=w;
            }
        }
    }
}

// ---------------- fused attention (fp16 MMA) ----------------
// grid (1,2,B*H); 512 thr (16 warps, 2m x 8n). q fp32 smem; k staged [n][36] (CP16, 16B rows);
// P stored fp16 [128][280] in q's smem; v staged [k=32][264].
#define KPAD 36
#define PPAD 280
#define QP_F (8*4608)            // 36864 floats
#define KB_F (256*KPAD)          // 9216 floats per buffer (>= 32*264=8448 for v)
#define RED_OFF (QP_F + 2*KB_F)  // 55296
#define FA_SMEM ((RED_OFF + 1024+128+128+256)*4)  // 227328 bytes

__global__ void __launch_bounds__(512,1) fused_attn(
    const float* __restrict__ q, const float* __restrict__ k, const float* __restrict__ v,
    const float* __restrict__ dist, const float* __restrict__ mask, float* __restrict__ y)
{
    extern __shared__ float sm[];
    float* qp  = sm;
    float* kb0 = sm + QP_F;
    float* kb1 = kb0 + KB_F;
    float* redA    = sm + RED_OFF;
    float* rowmax_ = redA + 1024;
    float* rowsum_ = rowmax_ + 128;
    float* mcol    = rowsum_ + 128;
    __half* Ph = (__half*)qp;

    int tid=threadIdx.x, wid=tid>>5, lane=tid&31;
    int z=blockIdx.z, b=z>>3, h=z&7;
    int row0=blockIdx.y*128;
    const float* qg = q + ((long)b*256)*2048 + (long)h*256;
    const float* kg = k + ((long)b*256)*2048 + (long)h*256;
    const float* vg = v + ((long)b*256)*2048 + (long)h*256;
    const float* dg = dist + (long)b*65536;
    float* yg = y + ((long)b*256)*2048 + (long)h*256;

    uint32_t qpB = smem_u32(qp);
    uint32_t kbB[2] = { smem_u32(kb0), smem_u32(kb1) };

    // q: 8 chunks [128][36] fp32
    #pragma unroll
    for(int i=0;i<16;i++){
        int f4 = tid + i*512;
        int ch = f4>>10, rr=(f4>>3)&127, c4=f4&7;
        CP16(qpB + (uint32_t)(ch*4608 + rr*36 + c4*4)*4,
             qg + (long)(row0+rr)*2048 + ch*32 + c4*4);
    }
    // k chunk 0: [n=256][KPAD] (k-contiguous, CP16, rows 144B = 16B-aligned)
    #pragma unroll
    for(int i=0;i<4;i++){
        int f4=tid+i*512;           // 2048
        int n=f4>>3, c4=f4&7;
        CP16(kbB[0] + (uint32_t)(n*KPAD + c4*4)*4, kg + (long)n*2048 + c4*4);
    }
    CP_COMMIT();

    int wn_idx = wid&7, wm_idx = wid>>3;
    int wm0 = wm_idx*64, wn0 = wn_idx*32;
    int tq = lane>>2, tr = lane&3;

    float cacc[4][4][4];
    #pragma unroll
    for(int a0=0;a0<4;a0++)
        #pragma unroll
        for(int b0=0;b0<4;b0++)
            #pragma unroll
            for(int c0=0;c0<4;c0++) cacc[a0][b0][c0]=0.f;

    // ---- phase 1: S = q @ k^T ----
    for(int kt=0;kt<8;kt++){
        if(kt+1<8){
            int nb=(kt+1)&1;
            #pragma unroll
            for(int i=0;i<4;i++){
                int f4=tid+i*512; int n=f4>>3, c4=f4&7;
                CP16(kbB[nb] + (uint32_t)(n*KPAD + c4*4)*4,
                     kg + (long)n*2048 + (kt+1)*32 + c4*4);
            }
            CP_COMMIT(); CP_WAIT1();
        } else CP_WAIT0();
        __syncthreads();
        const float* As_ = qp + kt*4608;
        const float* Bs_ = (kt&1)? kb1 : kb0;
        #pragma unroll
        for(int ks=0;ks<2;ks++){
            uint32_t af[4][4], bf[4][2];
            #pragma unroll
            for(int mt=0;mt<4;mt++){
                const float* ap = As_ + (wm0+mt*16+tq)*36 + ks*16 + 2*tr;
                float2 v0=*(const float2*)(ap);
                float2 v1=*(const float2*)(ap+8*36);
                float2 v2=*(const float2*)(ap+8);
                float2 v3=*(const float2*)(ap+8*36+8);
                CVTP(af[mt][0], v0.x, v0.y);
                CVTP(af[mt][1], v1.x, v1.y);
                CVTP(af[mt][2], v2.x, v2.y);
                CVTP(af[mt][3], v3.x, v3.y);
            }
            #pragma unroll
            for(int nt=0;nt<4;nt++){
                const float* bp = Bs_ + (wn0+nt*8+tq)*KPAD + ks*16 + 2*tr;
                float2 b0=*(const float2*)(bp);
                float2 b1=*(const float2*)(bp+8);
                CVTP(bf[nt][0], b0.x, b0.y);
                CVTP(bf[nt][1], b1.x, b1.y);
            }
            #pragma unroll
            for(int mt=0;mt<4;mt++)
                #pragma unroll
                for(int nt=0;nt<4;nt++)
                    MMA16(cacc[mt][nt], af[mt], bf[nt]);
        }
        __syncthreads();
    }

    // prefetch v chunk 0 into kb0 ([k=32][264], full 256 cols)
    #pragma unroll
    for(int i=0;i<4;i++){
        int f4=tid+i*512; int kr=f4>>6, c4=f4&63;
        CP16(kbB[0] + (uint32_t)(kr*264+c4*4)*4, vg + (long)kr*2048 + c4*4);
    }
    CP_COMMIT();

    // ---- masked softmax ----
    if(tid<256) mcol[tid]=mask[b*256+tid];
    __syncthreads();

    #pragma unroll
    for(int mt=0;mt<4;mt++){
        #pragma unroll
        for(int hf=0;hf<2;hf++){
            int rl = wm0+mt*16+tq+hf*8;
            float lm=-3.0e38f;
            #pragma unroll
            for(int nt=0;nt<4;nt++){
                int c = wn0+nt*8+tr*2;
                float2 dd = *(const float2*)(dg + (long)(row0+rl)*256 + c);
                float s0 = cacc[mt][nt][hf*2+0]*0.0625f + dd.x;
                float s1 = cacc[mt][nt][hf*2+1]*0.0625f + dd.y;
                cacc[mt][nt][hf*2+0]=s0; cacc[mt][nt][hf*2+1]=s1;
                if(mcol[c]  !=0.0f) lm=fmaxf(lm,s0);
                if(mcol[c+1]!=0.0f) lm=fmaxf(lm,s1);
            }
            lm = fmaxf(lm, __shfl_xor_sync(0xffffffffu,lm,1));
            lm = fmaxf(lm, __shfl_xor_sync(0xffffffffu,lm,2));
            if(tr==0) redA[rl*8+wn_idx]=lm;
        }
    }
    __syncthreads();
    if(tid<128){ float m=-3.0e38f;
        #pragma unroll
        for(int w=0;w<8;w++) m=fmaxf(m,redA[tid*8+w]);
        rowmax_[tid]=m; }
    __syncthreads();

    #pragma unroll
    for(int mt=0;mt<4;mt++){
        #pragma unroll
        for(int hf=0;hf<2;hf++){
            int rl = wm0+mt*16+tq+hf*8;
            float mx = rowmax_[rl];
            float ls=0.f;
            #pragma unroll
            for(int nt=0;nt<4;nt++){
                int c = wn0+nt*8+tr*2;
                float p0 = (mcol[c]  !=0.0f)? expf(cacc[mt][nt][hf*2+0]-mx) : 0.0f;
                float p1 = (mcol[c+1]!=0.0f)? expf(cacc[mt][nt][hf*2+1]-mx) : 0.0f;
                cacc[mt][nt][hf*2+0]=p0; cacc[mt][nt][hf*2+1]=p1;
                ls += p0+p1;
            }
            ls += __shfl_xor_sync(0xffffffffu,ls,1);
            ls += __shfl_xor_sync(0xffffffffu,ls,2);
            if(tr==0) redA[rl*8+wn_idx]=ls;
        }
    }
    __syncthreads();
    if(tid<128){ float s=0.f;
        #pragma unroll
        for(int w=0;w<8;w++) s+=redA[tid*8+w];
        rowsum_[tid]=s; }
    __syncthreads();

    // normalize -> fp16 P into Ph [128][PPAD]; reset acc
    #pragma unroll
    for(int mt=0;mt<4;mt++){
        #pragma unroll
        for(int hf=0;hf<2;hf++){
            int rl = wm0+mt*16+tq+hf*8;
            float sum = rowsum_[rl];
            float inv = (sum>0.0f)? 1.0f/sum : 0.0f;
            #pragma unroll
            for(int nt=0;nt<4;nt++){
                int c = wn0+nt*8+tr*2;
                float p0 = cacc[mt][nt][hf*2+0]*inv;
                float p1 = cacc[mt][nt][hf*2+1]*inv;
                uint32_t u; CVTP(u, p0, p1);
                *(uint32_t*)(Ph + rl*PPAD + c) = u;
                cacc[mt][nt][hf*2+0]=0.f; cacc[mt][nt][hf*2+1]=0.f;
            }
        }
    }
    __syncthreads();

    // ---- phase 2: Y = P @ v ----
    for(int kt=0;kt<8;kt++){
        if(kt+1<8){
            int nb=(kt+1)&1;
            #pragma unroll
            for(int i=0;i<4;i++){
                int f4=tid+i*512; int kr=f4>>6, c4=f4&63;
                CP16(kbB[nb] + (uint32_t)(kr*264+c4*4)*4,
                     vg + (long)((kt+1)*32+kr)*2048 + c4*4);
            }
            CP_COMMIT(); CP_WAIT1();
        } else CP_WAIT0();
        __syncthreads();
        const float* Bs_ = (kt&1)? kb1 : kb0;
        #pragma unroll
        for(int ks=0;ks<2;ks++){
            uint32_t af[4][4], bf[4][2];
            #pragma unroll
            for(int mt=0;mt<4;mt++){
                const __half* ap = Ph + (wm0+mt*16+tq)*PPAD + kt*32 + ks*16 + 2*tr;
                af[mt][0]=*(const uint32_t*)(ap);
                af[mt][1]=*(const uint32_t*)(ap+8*PPAD);
                af[mt][2]=*(const uint32_t*)(ap+8);
                af[mt][3]=*(const uint32_t*)(ap+8*PPAD+8);
            }
            #pragma unroll
            for(int nt=0;nt<4;nt++){
                const float* bp = Bs_ + (ks*16 + 2*tr)*264 + wn0 + nt*8 + tq;
                CVTP(bf[nt][0], bp[0], bp[264]);
                CVTP(bf[nt][1], bp[8*264], bp[9*264]);
            }
            #pragma unroll
            for(int mt=0;mt<4;mt++)
                #pragma unroll
                for(int nt=0;nt<4;nt++)
                    MMA16(cacc[mt][nt], af[mt], bf[nt]);
        }
        __syncthreads();
    }

    #pragma unroll
    for(int mt=0;mt<4;mt++){
        #pragma unroll
        for(int hf=0;hf<2;hf++){
            int rl = wm0+mt*16+tq+hf*8;
            #pragma unroll
            for(int nt=0;nt<4;nt++){
                int c = wn0+nt*8+tr*2;
                float2 w; w.x=cacc[mt][nt][hf*2+0]; w.y=cacc[mt][nt][hf*2+1];
                *(float2*)(yg + (long)(row0+rl)*2048 + c) = w;
            }
        }
    }
}

// ---------------- launch ----------------
extern "C" void kernel_launch(void* const* d_in, const int* in_sizes, int n_in,
                              void* d_out, int out_size){
    const float* x=(const float*)d_in[0];
    const float* adj=(const float*)d_in[1];
    const float* mask=(const float*)d_in[2];
    const float* dist=(const float*)d_in[3];
    const float* W1=(const float*)d_in[4];
    const float* b1=(const float*)d_in[5];
    const float* W2=(const float*)d_in[6];
    const float* b2=(const float*)d_in[7];
    const float* W3=(const float*)d_in[8];
    const float* b3=(const float*)d_in[9];
    const float* ln1g=(const float*)d_in[10];
    const float* ln1b=(const float*)d_in[11];
    const float* Wq=(const float*)d_in[12];
    const float* Wk=(const float*)d_in[13];
    const float* Wv=(const float*)d_in[14];
    const float* Wo=(const float*)d_in[15];
    const float* bo=(const float*)d_in[16];
    const float* ln2g=(const float*)d_in[17];
    const float* ln2b=(const float*)d_in[18];
    const float* Wf1=(const float*)d_in[19];
    const float* bf1=(const float*)d_in[20];
    const float* Wf2=(const float*)d_in[21];
    const float* bf2=(const float*)d_in[22];
    float* out=(float*)d_out;

    float *dis,*an,*t,*g,*res,*h,*q,*k,*v,*y,*att;
    cudaGetSymbolAddress((void**)&dis,d_dis);
    cudaGetSymbolAddress((void**)&an,d_an);
    cudaGetSymbolAddress((void**)&t,d_t);
    cudaGetSymbolAddress((void**)&g,d_g);
    cudaGetSymbolAddress((void**)&res,d_res);
    cudaGetSymbolAddress((void**)&h,d_h);
    cudaGetSymbolAddress((void**)&q,d_q);
    cudaGetSymbolAddress((void**)&k,d_k);
    cudaGetSymbolAddress((void**)&v,d_v);
    cudaGetSymbolAddress((void**)&y,d_y);
    cudaGetSymbolAddress((void**)&att,d_att);

    cudaFuncSetAttribute(tgemm, cudaFuncAttributeMaxDynamicSharedMemorySize, SMEM_BYTES);
    cudaFuncSetAttribute(fused_attn, cudaFuncAttributeMaxDynamicSharedMemorySize, FA_SMEM);
    const long Z=0;

    deg_kernel<<<Mrows,256>>>(adj,dis);
    an_build<<<(Bb*Nn*Nn)/256,256>>>(adj,dis,an);

    // GCN layer 1
    tgemm<<<dim3(2,128,1),256,SMEM_BYTES>>>(x,W1,t, 0,0,0,0, 0,0,
        128,128,256,256, Z,Z,Z,Z,Z,Z,Z,Z,Z, 1,1.0f,0);
    tgemm<<<dim3(2,2,Bb),256,SMEM_BYTES>>>(an,t,g, b1,mask,0,0, res,1,
        256,256,256,256, 65536L,Z, 65536L,Z, 65536L,Z, Z,Z, 256L, 1,1.0f,1);
    // layer 2
    tgemm<<<dim3(2,128,1),256,SMEM_BYTES>>>(g,W2,t, 0,0,0,0, 0,0,
        256,256,256,256, Z,Z,Z,Z,Z,Z,Z,Z,Z, 1,1.0f,0);
    tgemm<<<dim3(2,2,Bb),256,SMEM_BYTES>>>(an,t,g, b2,mask,0,0, res,0,
        256,256,256,256, 65536L,Z, 65536L,Z, 65536L,Z, Z,Z, 256L, 1,1.0f,1);
    // layer 3
    tgemm<<<dim3(2,128,1),256,SMEM_BYTES>>>(g,W3,t, 0,0,0,0, 0,0,
        256,256,256,256, Z,Z,Z,Z,Z,Z,Z,Z,Z, 1,1.0f,0);
    tgemm<<<dim3(2,2,Bb),256,SMEM_BYTES>>>(an,t,g, b3,mask,0,0, res,0,
        256,256,256,256, 65536L,Z, 65536L,Z, 65536L,Z, Z,Z, 256L, 1,1.0f,1);

    // LN1 + QKV
    ln_kernel<<<Mrows,256>>>(res,ln1g,ln1b,h);
    tgemm<<<dim3(16,128,1),256,SMEM_BYTES>>>(h,Wq,q, 0,0,0,0, 0,0,
        256,256,2048,2048, Z,Z,Z,Z,Z,Z,Z,Z,Z, 1,1.0f,0);
    tgemm<<<dim3(16,128,1),256,SMEM_BYTES>>>(h,Wk,k, 0,0,0,0, 0,0,
        256,256,2048,2048, Z,Z,Z,Z,Z,Z,Z,Z,Z, 1,1.0f,0);
    tgemm<<<dim3(16,128,1),256,SMEM_BYTES>>>(h,Wv,v, 0,0,0,0, 0,0,
        256,256,2048,2048, Z,Z,Z,Z,Z,Z,Z,Z,Z, 1,1.0f,0);

    // fused attention -> y
    fused_attn<<<dim3(1,2,Bb*Hh),512,FA_SMEM>>>(q,k,v,dist,mask,y);

    // att = (y@Wo+bo)*mask + res
    tgemm<<<dim3(2,128,1),256,SMEM_BYTES>>>(y,Wo,att, bo,mask,res,0, 0,0,
        2048,2048,256,256, Z,Z,Z,Z,Z,Z,Z,Z,Z, 1,1.0f,0);

    // FFN
    ln_kernel<<<Mrows,256>>>(att,ln2g,ln2b,h);
    tgemm<<<dim3(8,128,1),256,SMEM_BYTES>>>(h,Wf1,t, bf1,0,0,0, 0,0,
        256,256,1024,1024, Z,Z,Z,Z,Z,Z,Z,Z,Z, 1,1.0f,2);
    tgemm<<<dim3(2,128,1),256,SMEM_BYTES>>>(t,Wf2,out, bf2,mask,att,res, 0,0,
        1024,1024,256,256, Z,Z,Z,Z,Z,Z,Z,Z,Z, 1,1.0f,0);
}

// round 11
// speedup vs baseline: 6.0226x; 1.5162x over previous
#include <cuda_runtime.h>
#include <cuda_fp16.h>
#include <math.h>
#include <stdint.h>

#define Bb 64
#define Nn 256
#define INd 128
#define Ee 256
#define Hh 8
#define Ff 1024
#define Mrows (Bb*Nn)
#define HE (Hh*Ee)

// ---------------- fp32 scratch ----------------
__device__ float d_dis[Mrows];
__device__ float d_res[(size_t)Mrows*Ee];
__device__ float d_att[(size_t)Mrows*Ee];

// ---------------- fp16 tensors (all k-contiguous for GEMM use) ----------------
__device__ __half h_x  [(size_t)Mrows*INd];     // [m][128]
__device__ __half h_an [(size_t)Bb*Nn*Nn];      // [b][i][j]
__device__ __half h_tT [(size_t)Ee*Mrows];      // [f][global node]
__device__ __half h_g  [(size_t)Mrows*Ee];      // [m][f]
__device__ __half h_h  [(size_t)Mrows*Ee];      // ln out [m][e]
__device__ __half h_q  [(size_t)Mrows*HE];      // [m][2048]
__device__ __half h_k  [(size_t)Mrows*HE];
__device__ __half h_vT [(size_t)HE*Mrows];      // [e_out(2048)][global node]
__device__ __half h_y  [(size_t)Mrows*HE];
__device__ __half h_f  [(size_t)Mrows*Ff];      // FFN hidden [m][1024]
// transposed fp16 weights [N][K]
__device__ __half h_w1t [256*128];
__device__ __half h_w2t [256*256];
__device__ __half h_w3t [256*256];
__device__ __half h_wqt [(size_t)2048*256];
__device__ __half h_wkt [(size_t)2048*256];
__device__ __half h_wvt [(size_t)2048*256];
__device__ __half h_wot [(size_t)256*2048];
__device__ __half h_wf1t[(size_t)1024*256];
__device__ __half h_wf2t[(size_t)256*1024];

// ---------------- asm helpers ----------------
__device__ __forceinline__ uint32_t smem_u32(const void* p){
    uint32_t a; asm("{ .reg .u64 t; cvta.to.shared.u64 t, %1; cvt.u32.u64 %0, t; }":"=r"(a):"l"(p)); return a; }
#define CP16(dst,src) asm volatile("cp.async.cg.shared.global [%0], [%1], 16;"::"r"(dst),"l"(src))
#define CP_COMMIT()   asm volatile("cp.async.commit_group;")
#define CP_WAIT0()    asm volatile("cp.async.wait_group 0;")
#define CP_WAIT1()    asm volatile("cp.async.wait_group 1;")
#define CP_WAIT2()    asm volatile("cp.async.wait_group 2;")
#define CVTP(u,lo,hi) asm("cvt.rn.f16x2.f32 %0, %1, %2;":"=r"(u):"f"(hi),"f"(lo))
#define LDS32(u,p)    (u = *(const uint32_t*)(p))
#define MMA16(c,a,b) asm volatile( \
  "mma.sync.aligned.m16n8k16.row.col.f32.f16.f16.f32 {%0,%1,%2,%3},{%4,%5,%6,%7},{%8,%9},{%0,%1,%2,%3};" \
  : "+f"((c)[0]),"+f"((c)[1]),"+f"((c)[2]),"+f"((c)[3]) \
  : "r"((a)[0]),"r"((a)[1]),"r"((a)[2]),"r"((a)[3]),"r"((b)[0]),"r"((b)[1]))

// ---------------- small kernels ----------------
__global__ void deg_kernel(const float* __restrict__ adj, float* __restrict__ dis){
    int row=blockIdx.x, b=row>>8, i=row&255, t=threadIdx.x;
    const float* a=adj+(size_t)b*Nn*Nn+(size_t)i*Nn;
    float v=(t==i)?1.0f:a[t];
    __shared__ float sh[8];
    #pragma unroll
    for(int o=16;o>0;o>>=1) v+=__shfl_xor_sync(0xffffffffu,v,o);
    if((t&31)==0) sh[t>>5]=v;
    __syncthreads();
    if(t==0){ float s=0.f; for(int w=0;w<8;w++) s+=sh[w]; dis[row]=rsqrtf(fmaxf(s,1.0f)); }
}
__global__ void an_build(const float* __restrict__ adj, const float* __restrict__ dis,
                         __half* __restrict__ An){
    long idx=(long)blockIdx.x*256+threadIdx.x;
    int j=(int)(idx&255); long t=idx>>8; int i=(int)(t&255); int b=(int)(t>>8);
    float a=(i==j)?1.0f:adj[idx];
    An[idx]=__float2half_rn(a*dis[b*256+i]*dis[b*256+j]);
}
__global__ void conv_h(const float* __restrict__ in, __half* __restrict__ out){
    long i=(long)blockIdx.x*256+threadIdx.x;
    out[i]=__float2half_rn(in[i]);
}
// W fp32 [K][N] -> Wt half [N][K]
__global__ void conv_wt(const float* __restrict__ in, __half* __restrict__ out, int K, int N){
    __shared__ float t[32][33];
    int k0=blockIdx.x*32, n0=blockIdx.y*32;
    int tx=threadIdx.x, ty=threadIdx.y;
    for(int j=ty;j<32;j+=8) t[j][tx]=in[(long)(k0+j)*N + n0+tx];
    __syncthreads();
    for(int j=ty;j<32;j+=8) out[(long)(n0+j)*K + k0+tx]=__float2half_rn(t[tx][j]);
}
__global__ void ln_kernel(const float* __restrict__ x, const float* __restrict__ g,
                          const float* __restrict__ be, __half* __restrict__ out){
    int row=blockIdx.x, t=threadIdx.x;
    float v=x[(size_t)row*Ee+t];
    __shared__ float sh[8]; __shared__ float mv[2];
    float s=v;
    #pragma unroll
    for(int o=16;o>0;o>>=1) s+=__shfl_xor_sync(0xffffffffu,s,o);
    if((t&31)==0) sh[t>>5]=s;
    __syncthreads();
    if(t==0){ float m=0.f; for(int w=0;w<8;w++) m+=sh[w]; mv[0]=m*(1.0f/Ee); }
    __syncthreads();
    float m=mv[0], d=v-m; s=d*d;
    #pragma unroll
    for(int o=16;o>0;o>>=1) s+=__shfl_xor_sync(0xffffffffu,s,o);
    if((t&31)==0) sh[t>>5]=s;
    __syncthreads();
    if(t==0){ float vv=0.f; for(int w=0;w<8;w++) vv+=sh[w]; mv[1]=rsqrtf(vv*(1.0f/Ee)+1e-5f); }
    __syncthreads();
    out[(size_t)row*Ee+t]=__float2half_rn(d*mv[1]*g[t]+be[t]);
}

// ---------------- fp16 GEMM: C[m][n] = epi(sum_k A[m][k]*B[n][k]) -------------
// A,B half k-contiguous. 128x128 tile, BK=32, 8 warps (2m x 4n), 3-stage cp.async.
#define AP 40                       // halfs per smem row (80B, conflict-free)
#define TILE_H (128*AP)             // 5120 halfs = 10240 B
#define SMEM_BYTES (3*2*TILE_H*2)   // 61440

__global__ void __launch_bounds__(256,2) tgemm(
    const __half* __restrict__ A, int lda, const __half* __restrict__ B, int ldb,
    float* __restrict__ Cf, __half* __restrict__ Ch, int ldc,
    const float* __restrict__ bias, const float* __restrict__ rowmask,
    const float* __restrict__ res1, const float* __restrict__ res2,
    float* __restrict__ aux, int auxinit,
    int K, long sAz, long sBz, long sCz, long sMz, int act)
{
    extern __shared__ __half smh[];
    int tid=threadIdx.x, wid=tid>>5, lane=tid&31;
    int z=blockIdx.z;
    int row0=blockIdx.y*128, col0=blockIdx.x*128;

    const __half* Ag = A + z*sAz + (long)row0*lda;
    const __half* Bg = B + z*sBz + (long)col0*ldb;
    long cbase = z*sCz;

    uint32_t sb = smem_u32(smh);
    uint32_t aoff[3], boff[3];
    #pragma unroll
    for(int i=0;i<3;i++){ aoff[i]=sb+i*TILE_H*2; boff[i]=sb+(3+i)*TILE_H*2; }

    auto loadA = [&](int buf, int k0){
        #pragma unroll
        for(int i=0;i<2;i++){
            int f=tid+i*256; int row=f>>2, c=f&3;
            CP16(aoff[buf] + (uint32_t)(row*80 + c*16),
                 Ag + (long)row*lda + k0 + c*8);
        }
    };
    auto loadB = [&](int buf, int k0){
        #pragma unroll
        for(int i=0;i<2;i++){
            int f=tid+i*256; int row=f>>2, c=f&3;
            CP16(boff[buf] + (uint32_t)(row*80 + c*16),
                 Bg + (long)row*ldb + k0 + c*8);
        }
    };

    int wm0 = (wid>>2)*64;
    int wn0 = (wid&3)*32;
    int tq = lane>>2, tr = lane&3;

    float cacc[4][4][4];
    #pragma unroll
    for(int a0=0;a0<4;a0++)
        #pragma unroll
        for(int b0=0;b0<4;b0++)
            #pragma unroll
            for(int c0=0;c0<4;c0++) cacc[a0][b0][c0]=0.f;

    int KT = K >> 5;
    loadA(0,0); loadB(0,0); CP_COMMIT();
    loadA(1,32); loadB(1,32); CP_COMMIT();

    for(int kt=0; kt<KT; kt++){
        int buf = kt%3;
        if(kt+2<KT){ int nb=(kt+2)%3; loadA(nb,(kt+2)*32); loadB(nb,(kt+2)*32); }
        CP_COMMIT();
        CP_WAIT2();
        __syncthreads();

        const __half* As_ = smh + buf*TILE_H;
        const __half* Bs_ = smh + (3+buf)*TILE_H;
        #pragma unroll
        for(int ks=0;ks<2;ks++){
            uint32_t af[4][4], bf[4][2];
            #pragma unroll
            for(int mt=0;mt<4;mt++){
                const __half* ap = As_ + (wm0+mt*16+tq)*AP + ks*16 + 2*tr;
                LDS32(af[mt][0], ap);
                LDS32(af[mt][1], ap+8*AP);
                LDS32(af[mt][2], ap+8);
                LDS32(af[mt][3], ap+8*AP+8);
            }
            #pragma unroll
            for(int nt=0;nt<4;nt++){
                const __half* bp = Bs_ + (wn0+nt*8+tq)*AP + ks*16 + 2*tr;
                LDS32(bf[nt][0], bp);
                LDS32(bf[nt][1], bp+8);
            }
            #pragma unroll
            for(int mt=0;mt<4;mt++)
                #pragma unroll
                for(int nt=0;nt<4;nt++)
                    MMA16(cacc[mt][nt], af[mt], bf[nt]);
        }
        __syncthreads();
    }

    #pragma unroll
    for(int mt=0;mt<4;mt++){
        #pragma unroll
        for(int hf=0;hf<2;hf++){
            int r = row0 + wm0 + mt*16 + tq + hf*8;
            float rm = rowmask ? rowmask[z*sMz + r] : 1.0f;
            #pragma unroll
            for(int nt=0;nt<4;nt++){
                int cc = col0 + wn0 + nt*8 + tr*2;
                float v0 = cacc[mt][nt][hf*2+0];
                float v1 = cacc[mt][nt][hf*2+1];
                if(bias){ v0+=bias[cc]; v1+=bias[cc+1]; }
                if(act==1){ v0=fmaxf(v0,0.f); v1=fmaxf(v1,0.f); }
                else if(act==2){
                    v0=0.5f*v0*(1.0f+erff(v0*0.70710678118654752f));
                    v1=0.5f*v1*(1.0f+erff(v1*0.70710678118654752f));
                }
                v0*=rm; v1*=rm;
                long o = cbase + (long)r*ldc + cc;
                if(res1){ float2 t2=*(const float2*)(res1+o); v0+=t2.x; v1+=t2.y; }
                if(res2){ float2 t2=*(const float2*)(res2+o); v0+=t2.x; v1+=t2.y; }
                if(aux){
                    if(auxinit){ float2 w; w.x=v0; w.y=v1; *(float2*)(aux+o)=w; }
                    else { float2 t2=*(const float2*)(aux+o); float2 u; u.x=t2.x+v0; u.y=t2.y+v1; *(float2*)(aux+o)=u; }
                }
                if(Cf){ float2 w; w.x=v0; w.y=v1; *(float2*)(Cf+o)=w; }
                if(Ch){ uint32_t u; CVTP(u,v0,v1); *(uint32_t*)(Ch+o)=u; }
            }
        }
    }
}

// ---------------- fused attention (fp16 operands) ----------------
// grid(1,2,B*H); 512 thr (16 warps 2m x 8n). q resident [128][264] half;
// k/v tiles [256][40] half double-buffered; P overwrites q region.
#define QROW 264
#define FA_Q_B   (128*QROW*2)          // 67584
#define FA_KB_B  (256*40*2)            // 20480
#define FA_RED_B (FA_Q_B + 2*FA_KB_B)  // 108544
#define FA_SMEM  (FA_RED_B + 6144)     // 114688

__global__ void __launch_bounds__(512,1) fused_attn(
    const __half* __restrict__ q, const __half* __restrict__ k, const __half* __restrict__ vT,
    const float* __restrict__ dist, const float* __restrict__ mask, __half* __restrict__ y)
{
    extern __shared__ char smc[];
    __half* qp = (__half*)smc;
    __half* kb[2] = { (__half*)(smc+FA_Q_B), (__half*)(smc+FA_Q_B+FA_KB_B) };
    float* redA    = (float*)(smc+FA_RED_B);
    float* rowmax_ = redA + 1024;
    float* rowsum_ = rowmax_ + 128;
    float* mcol    = rowsum_ + 128;

    int tid=threadIdx.x, wid=tid>>5, lane=tid&31;
    int z=blockIdx.z, b=z>>3, h=z&7;
    int row0=blockIdx.y*128;
    const __half* qg = q + ((long)b*256+row0)*2048 + (long)h*256;
    const __half* kg = k + ((long)b*256)*2048 + (long)h*256;
    const __half* vg = vT + ((long)h*256)*16384 + (long)b*256;
    const float*  dg = dist + (long)b*65536;
    __half* yg = y + ((long)b*256+row0)*2048 + (long)h*256;

    uint32_t qpB = smem_u32(qp);
    uint32_t kbB[2] = { smem_u32(kb[0]), smem_u32(kb[1]) };

    // q: [128][264] half, 32 CP16-chunks per row
    #pragma unroll
    for(int i=0;i<8;i++){
        int f=tid+i*512; int row=f>>5, c=f&31;
        CP16(qpB + (uint32_t)(row*QROW*2 + c*16), qg + (long)row*2048 + c*8);
    }
    // k chunk 0: [n][40]
    #pragma unroll
    for(int i=0;i<2;i++){
        int f=tid+i*512; int n=f>>2, c=f&3;
        CP16(kbB[0] + (uint32_t)(n*80 + c*16), kg + (long)n*2048 + c*8);
    }
    CP_COMMIT();

    int wn_idx = wid&7, wm_idx = wid>>3;
    int wm0 = wm_idx*64, wn0 = wn_idx*32;
    int tq = lane>>2, tr = lane&3;

    float cacc[4][4][4];
    #pragma unroll
    for(int a0=0;a0<4;a0++)
        #pragma unroll
        for(int b0=0;b0<4;b0++)
            #pragma unroll
            for(int c0=0;c0<4;c0++) cacc[a0][b0][c0]=0.f;

    // ---- phase 1: S = q @ k^T ----
    for(int kt=0;kt<8;kt++){
        if(kt+1<8){
            int nb=(kt+1)&1;
            #pragma unroll
            for(int i=0;i<2;i++){
                int f=tid+i*512; int n=f>>2, c=f&3;
                CP16(kbB[nb] + (uint32_t)(n*80 + c*16),
                     kg + (long)n*2048 + (kt+1)*32 + c*8);
            }
            CP_COMMIT(); CP_WAIT1();
        } else CP_WAIT0();
        __syncthreads();
        const __half* Bs_ = kb[kt&1];
        #pragma unroll
        for(int ks=0;ks<2;ks++){
            uint32_t af[4][4], bf[4][2];
            #pragma unroll
            for(int mt=0;mt<4;mt++){
                const __half* ap = qp + (wm0+mt*16+tq)*QROW + kt*32 + ks*16 + 2*tr;
                LDS32(af[mt][0], ap);
                LDS32(af[mt][1], ap+8*QROW);
                LDS32(af[mt][2], ap+8);
                LDS32(af[mt][3], ap+8*QROW+8);
            }
            #pragma unroll
            for(int nt=0;nt<4;nt++){
                const __half* bp = Bs_ + (wn0+nt*8+tq)*40 + ks*16 + 2*tr;
                LDS32(bf[nt][0], bp);
                LDS32(bf[nt][1], bp+8);
            }
            #pragma unroll
            for(int mt=0;mt<4;mt++)
                #pragma unroll
                for(int nt=0;nt<4;nt++)
                    MMA16(cacc[mt][nt], af[mt], bf[nt]);
        }
        __syncthreads();
    }

    // prefetch v chunk 0 into kb0 ([e=256 rows][32 k])
    #pragma unroll
    for(int i=0;i<2;i++){
        int f=tid+i*512; int n=f>>2, c=f&3;
        CP16(kbB[0] + (uint32_t)(n*80 + c*16), vg + (long)n*16384 + c*8);
    }
    CP_COMMIT();

    // ---- masked softmax ----
    if(tid<256) mcol[tid]=mask[b*256+tid];
    __syncthreads();

    #pragma unroll
    for(int mt=0;mt<4;mt++){
        #pragma unroll
        for(int hf=0;hf<2;hf++){
            int rl = wm0+mt*16+tq+hf*8;
            float lm=-3.0e38f;
            #pragma unroll
            for(int nt=0;nt<4;nt++){
                int c = wn0+nt*8+tr*2;
                float2 dd = *(const float2*)(dg + (long)(row0+rl)*256 + c);
                float s0 = cacc[mt][nt][hf*2+0]*0.0625f + dd.x;
                float s1 = cacc[mt][nt][hf*2+1]*0.0625f + dd.y;
                cacc[mt][nt][hf*2+0]=s0; cacc[mt][nt][hf*2+1]=s1;
                if(mcol[c]  !=0.0f) lm=fmaxf(lm,s0);
                if(mcol[c+1]!=0.0f) lm=fmaxf(lm,s1);
            }
            lm = fmaxf(lm, __shfl_xor_sync(0xffffffffu,lm,1));
            lm = fmaxf(lm, __shfl_xor_sync(0xffffffffu,lm,2));
            if(tr==0) redA[rl*8+wn_idx]=lm;
        }
    }
    __syncthreads();
    if(tid<128){ float m=-3.0e38f;
        #pragma unroll
        for(int w=0;w<8;w++) m=fmaxf(m,redA[tid*8+w]);
        rowmax_[tid]=m; }
    __syncthreads();

    #pragma unroll
    for(int mt=0;mt<4;mt++){
        #pragma unroll
        for(int hf=0;hf<2;hf++){
            int rl = wm0+mt*16+tq+hf*8;
            float mx = rowmax_[rl];
            float ls=0.f;
            #pragma unroll
            for(int nt=0;nt<4;nt++){
                int c = wn0+nt*8+tr*2;
                float p0 = (mcol[c]  !=0.0f)? expf(cacc[mt][nt][hf*2+0]-mx) : 0.0f;
                float p1 = (mcol[c+1]!=0.0f)? expf(cacc[mt][nt][hf*2+1]-mx) : 0.0f;
                cacc[mt][nt][hf*2+0]=p0; cacc[mt][nt][hf*2+1]=p1;
                ls += p0+p1;
            }
            ls += __shfl_xor_sync(0xffffffffu,ls,1);
            ls += __shfl_xor_sync(0xffffffffu,ls,2);
            if(tr==0) redA[rl*8+wn_idx]=ls;
        }
    }
    __syncthreads();
    if(tid<128){ float s=0.f;
        #pragma unroll
        for(int w=0;w<8;w++) s+=redA[tid*8+w];
        rowsum_[tid]=s; }
    __syncthreads();

    // normalize -> fp16 P into qp [128][QROW] (q data dead); reset acc
    #pragma unroll
    for(int mt=0;mt<4;mt++){
        #pragma unroll
        for(int hf=0;hf<2;hf++){
            int rl = wm0+mt*16+tq+hf*8;
            float sum = rowsum_[rl];
            float inv = (sum>0.0f)? 1.0f/sum : 0.0f;
            #pragma unroll
            for(int nt=0;nt<4;nt++){
                int c = wn0+nt*8+tr*2;
                float p0 = cacc[mt][nt][hf*2+0]*inv;
                float p1 = cacc[mt][nt][hf*2+1]*inv;
                uint32_t u; CVTP(u, p0, p1);
                *(uint32_t*)(qp + rl*QROW + c) = u;
                cacc[mt][nt][hf*2+0]=0.f; cacc[mt][nt][hf*2+1]=0.f;
            }
        }
    }
    __syncthreads();

    // ---- phase 2: Y = P @ v  (B = vT slice, rows e, k contiguous) ----
    for(int kt=0;kt<8;kt++){
        if(kt+1<8){
            int nb=(kt+1)&1;
            #pragma unroll
            for(int i=0;i<2;i++){
                int f=tid+i*512; int n=f>>2, c=f&3;
                CP16(kbB[nb] + (uint32_t)(n*80 + c*16),
                     vg + (long)n*16384 + (kt+1)*32 + c*8);
            }
            CP_COMMIT(); CP_WAIT1();
        } else CP_WAIT0();
        __syncthreads();
        const __half* Bs_ = kb[kt&1];
        #pragma unroll
        for(int ks=0;ks<2;ks++){
            uint32_t af[4][4], bf[4][2];
            #pragma unroll
            for(int mt=0;mt<4;mt++){
                const __half* ap = qp + (wm0+mt*16+tq)*QROW + kt*32 + ks*16 + 2*tr;
                LDS32(af[mt][0], ap);
                LDS32(af[mt][1], ap+8*QROW);
                LDS32(af[mt][2], ap+8);
                LDS32(af[mt][3], ap+8*QROW+8);
            }
            #pragma unroll
            for(int nt=0;nt<4;nt++){
                const __half* bp = Bs_ + (wn0+nt*8+tq)*40 + ks*16 + 2*tr;
                LDS32(bf[nt][0], bp);
                LDS32(bf[nt][1], bp+8);
            }
            #pragma unroll
            for(int mt=0;mt<4;mt++)
                #pragma unroll
                for(int nt=0;nt<4;nt++)
                    MMA16(cacc[mt][nt], af[mt], bf[nt]);
        }
        __syncthreads();
    }

    #pragma unroll
    for(int mt=0;mt<4;mt++){
        #pragma unroll
        for(int hf=0;hf<2;hf++){
            int rl = wm0+mt*16+tq+hf*8;
            #pragma unroll
            for(int nt=0;nt<4;nt++){
                int c = wn0+nt*8+tr*2;
                uint32_t u; CVTP(u, cacc[mt][nt][hf*2+0], cacc[mt][nt][hf*2+1]);
                *(uint32_t*)(yg + (long)rl*2048 + c) = u;
            }
        }
    }
}

// ---------------- launch ----------------
extern "C" void kernel_launch(void* const* d_in, const int* in_sizes, int n_in,
                              void* d_out, int out_size){
    const float* x=(const float*)d_in[0];
    const float* adj=(const float*)d_in[1];
    const float* mask=(const float*)d_in[2];
    const float* dist=(const float*)d_in[3];
    const float* W1=(const float*)d_in[4];
    const float* b1=(const float*)d_in[5];
    const float* W2=(const float*)d_in[6];
    const float* b2=(const float*)d_in[7];
    const float* W3=(const float*)d_in[8];
    const float* b3=(const float*)d_in[9];
    const float* ln1g=(const float*)d_in[10];
    const float* ln1b=(const float*)d_in[11];
    const float* Wq=(const float*)d_in[12];
    const float* Wk=(const float*)d_in[13];
    const float* Wv=(const float*)d_in[14];
    const float* Wo=(const float*)d_in[15];
    const float* bo=(const float*)d_in[16];
    const float* ln2g=(const float*)d_in[17];
    const float* ln2b=(const float*)d_in[18];
    const float* Wf1=(const float*)d_in[19];
    const float* bf1=(const float*)d_in[20];
    const float* Wf2=(const float*)d_in[21];
    const float* bf2=(const float*)d_in[22];
    float* out=(float*)d_out;

    float *dis,*res,*att;
    cudaGetSymbolAddress((void**)&dis,d_dis);
    cudaGetSymbolAddress((void**)&res,d_res);
    cudaGetSymbolAddress((void**)&att,d_att);
    __half *hx,*han,*htT,*hg,*hh,*hq,*hk,*hvT,*hy,*hf;
    __half *w1t,*w2t,*w3t,*wqt,*wkt,*wvt,*wot,*wf1t,*wf2t;
    cudaGetSymbolAddress((void**)&hx,h_x);
    cudaGetSymbolAddress((void**)&han,h_an);
    cudaGetSymbolAddress((void**)&htT,h_tT);
    cudaGetSymbolAddress((void**)&hg,h_g);
    cudaGetSymbolAddress((void**)&hh,h_h);
    cudaGetSymbolAddress((void**)&hq,h_q);
    cudaGetSymbolAddress((void**)&hk,h_k);
    cudaGetSymbolAddress((void**)&hvT,h_vT);
    cudaGetSymbolAddress((void**)&hy,h_y);
    cudaGetSymbolAddress((void**)&hf,h_f);
    cudaGetSymbolAddress((void**)&w1t,h_w1t);
    cudaGetSymbolAddress((void**)&w2t,h_w2t);
    cudaGetSymbolAddress((void**)&w3t,h_w3t);
    cudaGetSymbolAddress((void**)&wqt,h_wqt);
    cudaGetSymbolAddress((void**)&wkt,h_wkt);
    cudaGetSymbolAddress((void**)&wvt,h_wvt);
    cudaGetSymbolAddress((void**)&wot,h_wot);
    cudaGetSymbolAddress((void**)&wf1t,h_wf1t);
    cudaGetSymbolAddress((void**)&wf2t,h_wf2t);

    cudaFuncSetAttribute(tgemm, cudaFuncAttributeMaxDynamicSharedMemorySize, SMEM_BYTES);
    cudaFuncSetAttribute(fused_attn, cudaFuncAttributeMaxDynamicSharedMemorySize, FA_SMEM);
    dim3 tb(32,8);
    const long Z=0;

    // prep: conversions + degree + An
    deg_kernel<<<Mrows,256>>>(adj,dis);
    an_build<<<(Bb*Nn*Nn)/256,256>>>(adj,dis,han);
    conv_h<<<(Mrows*INd)/256,256>>>(x,hx);
    conv_wt<<<dim3(4,8),tb>>>(W1,w1t,128,256);
    conv_wt<<<dim3(8,8),tb>>>(W2,w2t,256,256);
    conv_wt<<<dim3(8,8),tb>>>(W3,w3t,256,256);
    conv_wt<<<dim3(8,64),tb>>>(Wq,wqt,256,2048);
    conv_wt<<<dim3(8,64),tb>>>(Wk,wkt,256,2048);
    conv_wt<<<dim3(8,64),tb>>>(Wv,wvt,256,2048);
    conv_wt<<<dim3(64,8),tb>>>(Wo,wot,2048,256);
    conv_wt<<<dim3(8,32),tb>>>(Wf1,wf1t,256,1024);
    conv_wt<<<dim3(32,8),tb>>>(Wf2,wf2t,1024,256);

    // GCN layer 1: tT = W1t @ x  ([256 f][16384 m]); g = relu(An@t + b1)*mask
    tgemm<<<dim3(128,2,1),256,SMEM_BYTES>>>(w1t,128, hx,128, 0,htT,Mrows,
        0,0,0,0, 0,0, 128, Z,Z,Z,Z, 0);
    tgemm<<<dim3(2,2,Bb),256,SMEM_BYTES>>>(han,256, htT,Mrows, 0,hg,256,
        b1,mask,0,0, res,1, 256, 65536L,256L,65536L,256L, 1);
    // layer 2
    tgemm<<<dim3(128,2,1),256,SMEM_BYTES>>>(w2t,256, hg,256, 0,htT,Mrows,
        0,0,0,0, 0,0, 256, Z,Z,Z,Z, 0);
    tgemm<<<dim3(2,2,Bb),256,SMEM_BYTES>>>(han,256, htT,Mrows, 0,hg,256,
        b2,mask,0,0, res,0, 256, 65536L,256L,65536L,256L, 1);
    // layer 3
    tgemm<<<dim3(128,2,1),256,SMEM_BYTES>>>(w3t,256, hg,256, 0,htT,Mrows,
        0,0,0,0, 0,0, 256, Z,Z,Z,Z, 0);
    tgemm<<<dim3(2,2,Bb),256,SMEM_BYTES>>>(han,256, htT,Mrows, 0,hg,256,
        b3,mask,0,0, res,0, 256, 65536L,256L,65536L,256L, 1);

    // LN1 + QKV
    ln_kernel<<<Mrows,256>>>(res,ln1g,ln1b,hh);
    tgemm<<<dim3(16,128,1),256,SMEM_BYTES>>>(hh,256, wqt,256, 0,hq,HE,
        0,0,0,0, 0,0, 256, Z,Z,Z,Z, 0);
    tgemm<<<dim3(16,128,1),256,SMEM_BYTES>>>(hh,256, wkt,256, 0,hk,HE,
        0,0,0,0, 0,0, 256, Z,Z,Z,Z, 0);
    tgemm<<<dim3(128,16,1),256,SMEM_BYTES>>>(wvt,256, hh,256, 0,hvT,Mrows,
        0,0,0,0, 0,0, 256, Z,Z,Z,Z, 0);

    // fused attention -> hy
    fused_attn<<<dim3(1,2,Bb*Hh),512,FA_SMEM>>>(hq,hk,hvT,dist,mask,hy);

    // att = (y@Wo + bo)*mask + res
    tgemm<<<dim3(2,128,1),256,SMEM_BYTES>>>(hy,HE, wot,HE, att,0,256,
        bo,mask,res,0, 0,0, 2048, Z,Z,Z,Z, 0);

    // FFN
    ln_kernel<<<Mrows,256>>>(att,ln2g,ln2b,hh);
    tgemm<<<dim3(8,128,1),256,SMEM_BYTES>>>(hh,256, wf1t,256, 0,hf,Ff,
        bf1,0,0,0, 0,0, 256, Z,Z,Z,Z, 2);
    tgemm<<<dim3(2,128,1),256,SMEM_BYTES>>>(hf,Ff, wf2t,Ff, out,0,256,
        bf2,mask,att,res, 0,0, 1024, Z,Z,Z,Z, 0);
}

// round 13
// speedup vs baseline: 6.1774x; 1.0257x over previous
#include <cuda_runtime.h>
#include <cuda_fp16.h>
#include <math.h>
#include <stdint.h>

#define Bb 64
#define Nn 256
#define INd 128
#define Ee 256
#define Hh 8
#define Ff 1024
#define Mrows (Bb*Nn)
#define HE (Hh*Ee)

// ---------------- fp32 scratch ----------------
__device__ float d_dis[Mrows];
__device__ float d_res[(size_t)Mrows*Ee];
__device__ float d_att[(size_t)Mrows*Ee];

// ---------------- fp16 tensors (k-contiguous) ----------------
__device__ __half h_x  [(size_t)Mrows*INd];
__device__ __half h_an [(size_t)Bb*Nn*Nn];
__device__ __half h_tT [(size_t)Ee*Mrows];
__device__ __half h_g  [(size_t)Mrows*Ee];
__device__ __half h_h  [(size_t)Mrows*Ee];
__device__ __half h_qk [(size_t)2*Mrows*HE];    // [0]=q, [1]=k
__device__ __half h_vT [(size_t)HE*Mrows];
__device__ __half h_y  [(size_t)Mrows*HE];
__device__ __half h_f  [(size_t)Mrows*Ff];
// transposed fp16 weights [N][K]
__device__ __half h_w1t [256*128];
__device__ __half h_w2t [256*256];
__device__ __half h_w3t [256*256];
__device__ __half h_wqkt[(size_t)2*2048*256];   // [0]=Wq^T, [1]=Wk^T
__device__ __half h_wvt [(size_t)2048*256];
__device__ __half h_wot [(size_t)256*2048];
__device__ __half h_wf1t[(size_t)1024*256];
__device__ __half h_wf2t[(size_t)256*1024];

// ---------------- asm helpers ----------------
__device__ __forceinline__ uint32_t smem_u32(const void* p){
    uint32_t a; asm("{ .reg .u64 t; cvta.to.shared.u64 t, %1; cvt.u32.u64 %0, t; }":"=r"(a):"l"(p)); return a; }
#define CP16(dst,src) asm volatile("cp.async.cg.shared.global [%0], [%1], 16;"::"r"(dst),"l"(src))
#define CP_COMMIT()   asm volatile("cp.async.commit_group;")
#define CP_WAIT0()    asm volatile("cp.async.wait_group 0;")
#define CP_WAIT1()    asm volatile("cp.async.wait_group 1;")
#define CP_WAIT3()    asm volatile("cp.async.wait_group 3;")
#define CVTP(u,lo,hi) asm("cvt.rn.f16x2.f32 %0, %1, %2;":"=r"(u):"f"(hi),"f"(lo))
#define LDS32(u,p)    (u = *(const uint32_t*)(p))
#define MMA16(c,a,b) asm volatile( \
  "mma.sync.aligned.m16n8k16.row.col.f32.f16.f16.f32 {%0,%1,%2,%3},{%4,%5,%6,%7},{%8,%9},{%0,%1,%2,%3};" \
  : "+f"((c)[0]),"+f"((c)[1]),"+f"((c)[2]),"+f"((c)[3]) \
  : "r"((a)[0]),"r"((a)[1]),"r"((a)[2]),"r"((a)[3]),"r"((b)[0]),"r"((b)[1]))

// ---------------- small kernels ----------------
__global__ void deg_kernel(const float* __restrict__ adj, float* __restrict__ dis){
    int row=blockIdx.x, b=row>>8, i=row&255, t=threadIdx.x;
    const float* a=adj+(size_t)b*Nn*Nn+(size_t)i*Nn;
    float v=(t==i)?1.0f:a[t];
    __shared__ float sh[8];
    #pragma unroll
    for(int o=16;o>0;o>>=1) v+=__shfl_xor_sync(0xffffffffu,v,o);
    if((t&31)==0) sh[t>>5]=v;
    __syncthreads();
    if(t==0){ float s=0.f; for(int w=0;w<8;w++) s+=sh[w]; dis[row]=rsqrtf(fmaxf(s,1.0f)); }
}
__global__ void an_build(const float* __restrict__ adj, const float* __restrict__ dis,
                         __half* __restrict__ An){
    long idx=(long)blockIdx.x*256+threadIdx.x;
    int j=(int)(idx&255); long t=idx>>8; int i=(int)(t&255); int b=(int)(t>>8);
    float a=(i==j)?1.0f:adj[idx];
    An[idx]=__float2half_rn(a*dis[b*256+i]*dis[b*256+j]);
}
__global__ void conv_h(const float* __restrict__ in, __half* __restrict__ out){
    long i=(long)blockIdx.x*256+threadIdx.x;
    out[i]=__float2half_rn(in[i]);
}
// all weight transpose-conversions in one launch (grid.z selects weight)
struct WT9 {
    const float* src[9];
    __half* dst[9];
    int K[9], N[9];
};
__global__ void conv_wt_all(WT9 wt){
    int z=blockIdx.z;
    int K=wt.K[z], N=wt.N[z];
    int k0=blockIdx.x*32, n0=blockIdx.y*32;
    if(k0>=K || n0>=N) return;
    const float* in=wt.src[z];
    __half* out=wt.dst[z];
    __shared__ float t[32][33];
    int tx=threadIdx.x, ty=threadIdx.y;
    for(int j=ty;j<32;j+=8) t[j][tx]=in[(long)(k0+j)*N + n0+tx];
    __syncthreads();
    for(int j=ty;j<32;j+=8) out[(long)(n0+j)*K + k0+tx]=__float2half_rn(t[tx][j]);
}
__global__ void ln_kernel(const float* __restrict__ x, const float* __restrict__ g,
                          const float* __restrict__ be, __half* __restrict__ out){
    int row=blockIdx.x, t=threadIdx.x;
    float v=x[(size_t)row*Ee+t];
    __shared__ float sh[8]; __shared__ float mv[2];
    float s=v;
    #pragma unroll
    for(int o=16;o>0;o>>=1) s+=__shfl_xor_sync(0xffffffffu,s,o);
    if((t&31)==0) sh[t>>5]=s;
    __syncthreads();
    if(t==0){ float m=0.f; for(int w=0;w<8;w++) m+=sh[w]; mv[0]=m*(1.0f/Ee); }
    __syncthreads();
    float m=mv[0], d=v-m; s=d*d;
    #pragma unroll
    for(int o=16;o>0;o>>=1) s+=__shfl_xor_sync(0xffffffffu,s,o);
    if((t&31)==0) sh[t>>5]=s;
    __syncthreads();
    if(t==0){ float vv=0.f; for(int w=0;w<8;w++) vv+=sh[w]; mv[1]=rsqrtf(vv*(1.0f/Ee)+1e-5f); }
    __syncthreads();
    out[(size_t)row*Ee+t]=__float2half_rn(d*mv[1]*g[t]+be[t]);
}

// ---------------- fp16 GEMM: C[m][n] = epi(sum_k A[m][k]*B[n][k]) -------------
// 128x128 tile, BK=32, 8 warps (2m x 4n), 4-stage cp.async, 2 CTAs/SM.
#define AP 40
#define TILE_H (128*AP)
#define NSTG 4
#define SMEM_BYTES (NSTG*2*TILE_H*2)   // 81920

__global__ void __launch_bounds__(256,2) tgemm(
    const __half* __restrict__ A, int lda, const __half* __restrict__ B, int ldb,
    float* __restrict__ Cf, __half* __restrict__ Ch, int ldc,
    const float* __restrict__ bias, const float* __restrict__ rowmask,
    const float* __restrict__ res1, const float* __restrict__ res2,
    float* __restrict__ aux, int auxinit,
    int K, long sAz, long sBz, long sCz, long sMz, int act)
{
    extern __shared__ __half smh[];
    int tid=threadIdx.x, wid=tid>>5, lane=tid&31;
    int z=blockIdx.z;
    int row0=blockIdx.y*128, col0=blockIdx.x*128;

    const __half* Ag = A + z*sAz + (long)row0*lda;
    const __half* Bg = B + z*sBz + (long)col0*ldb;
    long cbase = z*sCz;

    uint32_t sb = smem_u32(smh);
    uint32_t aoff[NSTG], boff[NSTG];
    #pragma unroll
    for(int i=0;i<NSTG;i++){ aoff[i]=sb+i*TILE_H*2; boff[i]=sb+(NSTG+i)*TILE_H*2; }

    auto loadA = [&](int buf, int k0){
        #pragma unroll
        for(int i=0;i<2;i++){
            int f=tid+i*256; int row=f>>2, c=f&3;
            CP16(aoff[buf] + (uint32_t)(row*80 + c*16),
                 Ag + (long)row*lda + k0 + c*8);
        }
    };
    auto loadB = [&](int buf, int k0){
        #pragma unroll
        for(int i=0;i<2;i++){
            int f=tid+i*256; int row=f>>2, c=f&3;
            CP16(boff[buf] + (uint32_t)(row*80 + c*16),
                 Bg + (long)row*ldb + k0 + c*8);
        }
    };

    int wm0 = (wid>>2)*64;
    int wn0 = (wid&3)*32;
    int tq = lane>>2, tr = lane&3;

    float cacc[4][4][4];
    #pragma unroll
    for(int a0=0;a0<4;a0++)
        #pragma unroll
        for(int b0=0;b0<4;b0++)
            #pragma unroll
            for(int c0=0;c0<4;c0++) cacc[a0][b0][c0]=0.f;

    int KT = K >> 5;
    loadA(0,0); loadB(0,0); CP_COMMIT();
    loadA(1,32); loadB(1,32); CP_COMMIT();
    loadA(2,64); loadB(2,64); CP_COMMIT();

    for(int kt=0; kt<KT; kt++){
        int buf = kt%NSTG;
        if(kt+3<KT){ int nb=(kt+3)%NSTG; loadA(nb,(kt+3)*32); loadB(nb,(kt+3)*32); }
        CP_COMMIT();
        CP_WAIT3();
        __syncthreads();

        const __half* As_ = smh + buf*TILE_H;
        const __half* Bs_ = smh + (NSTG+buf)*TILE_H;
        #pragma unroll
        for(int ks=0;ks<2;ks++){
            uint32_t af[4][4], bf[4][2];
            #pragma unroll
            for(int mt=0;mt<4;mt++){
                const __half* ap = As_ + (wm0+mt*16+tq)*AP + ks*16 + 2*tr;
                LDS32(af[mt][0], ap);
                LDS32(af[mt][1], ap+8*AP);
                LDS32(af[mt][2], ap+8);
                LDS32(af[mt][3], ap+8*AP+8);
            }
            #pragma unroll
            for(int nt=0;nt<4;nt++){
                const __half* bp = Bs_ + (wn0+nt*8+tq)*AP + ks*16 + 2*tr;
                LDS32(bf[nt][0], bp);
                LDS32(bf[nt][1], bp+8);
            }
            #pragma unroll
            for(int mt=0;mt<4;mt++)
                #pragma unroll
                for(int nt=0;nt<4;nt++)
                    MMA16(cacc[mt][nt], af[mt], bf[nt]);
        }
        __syncthreads();
    }

    #pragma unroll
    for(int mt=0;mt<4;mt++){
        #pragma unroll
        for(int hf=0;hf<2;hf++){
            int r = row0 + wm0 + mt*16 + tq + hf*8;
            float rm = rowmask ? rowmask[z*sMz + r] : 1.0f;
            #pragma unroll
            for(int nt=0;nt<4;nt++){
                int cc = col0 + wn0 + nt*8 + tr*2;
                float v0 = cacc[mt][nt][hf*2+0];
                float v1 = cacc[mt][nt][hf*2+1];
                if(bias){ v0+=bias[cc]; v1+=bias[cc+1]; }
                if(act==1){ v0=fmaxf(v0,0.f); v1=fmaxf(v1,0.f); }
                else if(act==2){
                    v0=0.5f*v0*(1.0f+erff(v0*0.70710678118654752f));
                    v1=0.5f*v1*(1.0f+erff(v1*0.70710678118654752f));
                }
                v0*=rm; v1*=rm;
                long o = cbase + (long)r*ldc + cc;
                if(res1){ float2 t2=*(const float2*)(res1+o); v0+=t2.x; v1+=t2.y; }
                if(res2){ float2 t2=*(const float2*)(res2+o); v0+=t2.x; v1+=t2.y; }
                if(aux){
                    if(auxinit){ float2 w; w.x=v0; w.y=v1; *(float2*)(aux+o)=w; }
                    else { float2 t2=*(const float2*)(aux+o); float2 u; u.x=t2.x+v0; u.y=t2.y+v1; *(float2*)(aux+o)=u; }
                }
                if(Cf){ float2 w; w.x=v0; w.y=v1; *(float2*)(Cf+o)=w; }
                if(Ch){ uint32_t u; CVTP(u,v0,v1); *(uint32_t*)(Ch+o)=u; }
            }
        }
    }
}

// ---------------- fused attention (fp16 operands) ----------------
#define QROW 264
#define FA_Q_B   (128*QROW*2)
#define FA_KB_B  (256*40*2)
#define FA_RED_B (FA_Q_B + 2*FA_KB_B)
#define FA_SMEM  (FA_RED_B + 6144)

__global__ void __launch_bounds__(512,1) fused_attn(
    const __half* __restrict__ q, const __half* __restrict__ k, const __half* __restrict__ vT,
    const float* __restrict__ dist, const float* __restrict__ mask, __half* __restrict__ y)
{
    extern __shared__ char smc[];
    __half* qp = (__half*)smc;
    __half* kb[2] = { (__half*)(smc+FA_Q_B), (__half*)(smc+FA_Q_B+FA_KB_B) };
    float* redA    = (float*)(smc+FA_RED_B);
    float* rowmax_ = redA + 1024;
    float* rowsum_ = rowmax_ + 128;
    float* mcol    = rowsum_ + 128;

    int tid=threadIdx.x, wid=tid>>5, lane=tid&31;
    int z=blockIdx.z, b=z>>3, h=z&7;
    int row0=blockIdx.y*128;
    const __half* qg = q + ((long)b*256+row0)*2048 + (long)h*256;
    const __half* kg = k + ((long)b*256)*2048 + (long)h*256;
    const __half* vg = vT + ((long)h*256)*16384 + (long)b*256;
    const float*  dg = dist + (long)b*65536;
    __half* yg = y + ((long)b*256+row0)*2048 + (long)h*256;

    uint32_t qpB = smem_u32(qp);
    uint32_t kbB[2] = { smem_u32(kb[0]), smem_u32(kb[1]) };

    #pragma unroll
    for(int i=0;i<8;i++){
        int f=tid+i*512; int row=f>>5, c=f&31;
        CP16(qpB + (uint32_t)(row*QROW*2 + c*16), qg + (long)row*2048 + c*8);
    }
    #pragma unroll
    for(int i=0;i<2;i++){
        int f=tid+i*512; int n=f>>2, c=f&3;
        CP16(kbB[0] + (uint32_t)(n*80 + c*16), kg + (long)n*2048 + c*8);
    }
    CP_COMMIT();

    int wn_idx = wid&7, wm_idx = wid>>3;
    int wm0 = wm_idx*64, wn0 = wn_idx*32;
    int tq = lane>>2, tr = lane&3;

    float cacc[4][4][4];
    #pragma unroll
    for(int a0=0;a0<4;a0++)
        #pragma unroll
        for(int b0=0;b0<4;b0++)
            #pragma unroll
            for(int c0=0;c0<4;c0++) cacc[a0][b0][c0]=0.f;

    // ---- phase 1: S = q @ k^T ----
    for(int kt=0;kt<8;kt++){
        if(kt+1<8){
            int nb=(kt+1)&1;
            #pragma unroll
            for(int i=0;i<2;i++){
                int f=tid+i*512; int n=f>>2, c=f&3;
                CP16(kbB[nb] + (uint32_t)(n*80 + c*16),
                     kg + (long)n*2048 + (kt+1)*32 + c*8);
            }
            CP_COMMIT(); CP_WAIT1();
        } else CP_WAIT0();
        __syncthreads();
        const __half* Bs_ = kb[kt&1];
        #pragma unroll
        for(int ks=0;ks<2;ks++){
            uint32_t af[4][4], bf[4][2];
            #pragma unroll
            for(int mt=0;mt<4;mt++){
                const __half* ap = qp + (wm0+mt*16+tq)*QROW + kt*32 + ks*16 + 2*tr;
                LDS32(af[mt][0], ap);
                LDS32(af[mt][1], ap+8*QROW);
                LDS32(af[mt][2], ap+8);
                LDS32(af[mt][3], ap+8*QROW+8);
            }
            #pragma unroll
            for(int nt=0;nt<4;nt++){
                const __half* bp = Bs_ + (wn0+nt*8+tq)*40 + ks*16 + 2*tr;
                LDS32(bf[nt][0], bp);
                LDS32(bf[nt][1], bp+8);
            }
            #pragma unroll
            for(int mt=0;mt<4;mt++)
                #pragma unroll
                for(int nt=0;nt<4;nt++)
                    MMA16(cacc[mt][nt], af[mt], bf[nt]);
        }
        __syncthreads();
    }

    #pragma unroll
    for(int i=0;i<2;i++){
        int f=tid+i*512; int n=f>>2, c=f&3;
        CP16(kbB[0] + (uint32_t)(n*80 + c*16), vg + (long)n*16384 + c*8);
    }
    CP_COMMIT();

    if(tid<256) mcol[tid]=mask[b*256+tid];
    __syncthreads();

    #pragma unroll
    for(int mt=0;mt<4;mt++){
        #pragma unroll
        for(int hf=0;hf<2;hf++){
            int rl = wm0+mt*16+tq+hf*8;
            float lm=-3.0e38f;
            #pragma unroll
            for(int nt=0;nt<4;nt++){
                int c = wn0+nt*8+tr*2;
                float2 dd = *(const float2*)(dg + (long)(row0+rl)*256 + c);
                float s0 = cacc[mt][nt][hf*2+0]*0.0625f + dd.x;
                float s1 = cacc[mt][nt][hf*2+1]*0.0625f + dd.y;
                cacc[mt][nt][hf*2+0]=s0; cacc[mt][nt][hf*2+1]=s1;
                if(mcol[c]  !=0.0f) lm=fmaxf(lm,s0);
                if(mcol[c+1]!=0.0f) lm=fmaxf(lm,s1);
            }
            lm = fmaxf(lm, __shfl_xor_sync(0xffffffffu,lm,1));
            lm = fmaxf(lm, __shfl_xor_sync(0xffffffffu,lm,2));
            if(tr==0) redA[rl*8+wn_idx]=lm;
        }
    }
    __syncthreads();
    if(tid<128){ float m=-3.0e38f;
        #pragma unroll
        for(int w=0;w<8;w++) m=fmaxf(m,redA[tid*8+w]);
        rowmax_[tid]=m; }
    __syncthreads();

    #pragma unroll
    for(int mt=0;mt<4;mt++){
        #pragma unroll
        for(int hf=0;hf<2;hf++){
            int rl = wm0+mt*16+tq+hf*8;
            float mx = rowmax_[rl];
            float ls=0.f;
            #pragma unroll
            for(int nt=0;nt<4;nt++){
                int c = wn0+nt*8+tr*2;
                float p0 = (mcol[c]  !=0.0f)? expf(cacc[mt][nt][hf*2+0]-mx) : 0.0f;
                float p1 = (mcol[c+1]!=0.0f)? expf(cacc[mt][nt][hf*2+1]-mx) : 0.0f;
                cacc[mt][nt][hf*2+0]=p0; cacc[mt][nt][hf*2+1]=p1;
                ls += p0+p1;
            }
            ls += __shfl_xor_sync(0xffffffffu,ls,1);
            ls += __shfl_xor_sync(0xffffffffu,ls,2);
            if(tr==0) redA[rl*8+wn_idx]=ls;
        }
    }
    __syncthreads();
    if(tid<128){ float s=0.f;
        #pragma unroll
        for(int w=0;w<8;w++) s+=redA[tid*8+w];
        rowsum_[tid]=s; }
    __syncthreads();

    #pragma unroll
    for(int mt=0;mt<4;mt++){
        #pragma unroll
        for(int hf=0;hf<2;hf++){
            int rl = wm0+mt*16+tq+hf*8;
            float sum = rowsum_[rl];
            float inv = (sum>0.0f)? 1.0f/sum : 0.0f;
            #pragma unroll
            for(int nt=0;nt<4;nt++){
                int c = wn0+nt*8+tr*2;
                float p0 = cacc[mt][nt][hf*2+0]*inv;
                float p1 = cacc[mt][nt][hf*2+1]*inv;
                uint32_t u; CVTP(u, p0, p1);
                *(uint32_t*)(qp + rl*QROW + c) = u;
                cacc[mt][nt][hf*2+0]=0.f; cacc[mt][nt][hf*2+1]=0.f;
            }
        }
    }
    __syncthreads();

    // ---- phase 2: Y = P @ v ----
    for(int kt=0;kt<8;kt++){
        if(kt+1<8){
            int nb=(kt+1)&1;
            #pragma unroll
            for(int i=0;i<2;i++){
                int f=tid+i*512; int n=f>>2, c=f&3;
                CP16(kbB[nb] + (uint32_t)(n*80 + c*16),
                     vg + (long)n*16384 + (kt+1)*32 + c*8);
            }
            CP_COMMIT(); CP_WAIT1();
        } else CP_WAIT0();
        __syncthreads();
        const __half* Bs_ = kb[kt&1];
        #pragma unroll
        for(int ks=0;ks<2;ks++){
            uint32_t af[4][4], bf[4][2];
            #pragma unroll
            for(int mt=0;mt<4;mt++){
                const __half* ap = qp + (wm0+mt*16+tq)*QROW + kt*32 + ks*16 + 2*tr;
                LDS32(af[mt][0], ap);
                LDS32(af[mt][1], ap+8*QROW);
                LDS32(af[mt][2], ap+8);
                LDS32(af[mt][3], ap+8*QROW+8);
            }
            #pragma unroll
            for(int nt=0;nt<4;nt++){
                const __half* bp = Bs_ + (wn0+nt*8+tq)*40 + ks*16 + 2*tr;
                LDS32(bf[nt][0], bp);
                LDS32(bf[nt][1], bp+8);
            }
            #pragma unroll
            for(int mt=0;mt<4;mt++)
                #pragma unroll
                for(int nt=0;nt<4;nt++)
                    MMA16(cacc[mt][nt], af[mt], bf[nt]);
        }
        __syncthreads();
    }

    #pragma unroll
    for(int mt=0;mt<4;mt++){
        #pragma unroll
        for(int hf=0;hf<2;hf++){
            int rl = wm0+mt*16+tq+hf*8;
            #pragma unroll
            for(int nt=0;nt<4;nt++){
                int c = wn0+nt*8+tr*2;
                uint32_t u; CVTP(u, cacc[mt][nt][hf*2+0], cacc[mt][nt][hf*2+1]);
                *(uint32_t*)(yg + (long)rl*2048 + c) = u;
            }
        }
    }
}

// ---------------- launch ----------------
extern "C" void kernel_launch(void* const* d_in, const int* in_sizes, int n_in,
                              void* d_out, int out_size){
    const float* x=(const float*)d_in[0];
    const float* adj=(const float*)d_in[1];
    const float* mask=(const float*)d_in[2];
    const float* dist=(const float*)d_in[3];
    const float* W1=(const float*)d_in[4];
    const float* b1=(const float*)d_in[5];
    const float* W2=(const float*)d_in[6];
    const float* b2=(const float*)d_in[7];
    const float* W3=(const float*)d_in[8];
    const float* b3=(const float*)d_in[9];
    const float* ln1g=(const float*)d_in[10];
    const float* ln1b=(const float*)d_in[11];
    const float* Wq=(const float*)d_in[12];
    const float* Wk=(const float*)d_in[13];
    const float* Wv=(const float*)d_in[14];
    const float* Wo=(const float*)d_in[15];
    const float* bo=(const float*)d_in[16];
    const float* ln2g=(const float*)d_in[17];
    const float* ln2b=(const float*)d_in[18];
    const float* Wf1=(const float*)d_in[19];
    const float* bf1=(const float*)d_in[20];
    const float* Wf2=(const float*)d_in[21];
    const float* bf2=(const float*)d_in[22];
    float* out=(float*)d_out;

    float *dis,*res,*att;
    cudaGetSymbolAddress((void**)&dis,d_dis);
    cudaGetSymbolAddress((void**)&res,d_res);
    cudaGetSymbolAddress((void**)&att,d_att);
    __half *hx,*han,*htT,*hg,*hh,*hqk,*hvT,*hy,*hf;
    __half *w1t,*w2t,*w3t,*wqkt,*wvt,*wot,*wf1t,*wf2t;
    cudaGetSymbolAddress((void**)&hx,h_x);
    cudaGetSymbolAddress((void**)&han,h_an);
    cudaGetSymbolAddress((void**)&htT,h_tT);
    cudaGetSymbolAddress((void**)&hg,h_g);
    cudaGetSymbolAddress((void**)&hh,h_h);
    cudaGetSymbolAddress((void**)&hqk,h_qk);
    cudaGetSymbolAddress((void**)&hvT,h_vT);
    cudaGetSymbolAddress((void**)&hy,h_y);
    cudaGetSymbolAddress((void**)&hf,h_f);
    cudaGetSymbolAddress((void**)&w1t,h_w1t);
    cudaGetSymbolAddress((void**)&w2t,h_w2t);
    cudaGetSymbolAddress((void**)&w3t,h_w3t);
    cudaGetSymbolAddress((void**)&wqkt,h_wqkt);
    cudaGetSymbolAddress((void**)&wvt,h_wvt);
    cudaGetSymbolAddress((void**)&wot,h_wot);
    cudaGetSymbolAddress((void**)&wf1t,h_wf1t);
    cudaGetSymbolAddress((void**)&wf2t,h_wf2t);
    __half* hq = hqk;
    __half* hk = hqk + (size_t)Mrows*HE;

    cudaFuncSetAttribute(tgemm, cudaFuncAttributeMaxDynamicSharedMemorySize, SMEM_BYTES);
    cudaFuncSetAttribute(fused_attn, cudaFuncAttributeMaxDynamicSharedMemorySize, FA_SMEM);
    dim3 tb(32,8);
    const long Z=0;

    // prep
    deg_kernel<<<Mrows,256>>>(adj,dis);
    an_build<<<(Bb*Nn*Nn)/256,256>>>(adj,dis,han);
    conv_h<<<(Mrows*INd)/256,256>>>(x,hx);
    WT9 wt;
    wt.src[0]=W1;  wt.dst[0]=w1t;              wt.K[0]=128;  wt.N[0]=256;
    wt.src[1]=W2;  wt.dst[1]=w2t;              wt.K[1]=256;  wt.N[1]=256;
    wt.src[2]=W3;  wt.dst[2]=w3t;              wt.K[2]=256;  wt.N[2]=256;
    wt.src[3]=Wq;  wt.dst[3]=wqkt;             wt.K[3]=256;  wt.N[3]=2048;
    wt.src[4]=Wk;  wt.dst[4]=wqkt+(size_t)2048*256; wt.K[4]=256; wt.N[4]=2048;
    wt.src[5]=Wv;  wt.dst[5]=wvt;              wt.K[5]=256;  wt.N[5]=2048;
    wt.src[6]=Wo;  wt.dst[6]=wot;              wt.K[6]=2048; wt.N[6]=256;
    wt.src[7]=Wf1; wt.dst[7]=wf1t;             wt.K[7]=256;  wt.N[7]=1024;
    wt.src[8]=Wf2; wt.dst[8]=wf2t;             wt.K[8]=1024; wt.N[8]=256;
    conv_wt_all<<<dim3(64,64,9),tb>>>(wt);

    // GCN layer 1
    tgemm<<<dim3(128,2,1),256,SMEM_BYTES>>>(w1t,128, hx,128, 0,htT,Mrows,
        0,0,0,0, 0,0, 128, Z,Z,Z,Z, 0);
    tgemm<<<dim3(2,2,Bb),256,SMEM_BYTES>>>(han,256, htT,Mrows, 0,hg,256,
        b1,mask,0,0, res,1, 256, 65536L,256L,65536L,256L, 1);
    // layer 2
    tgemm<<<dim3(128,2,1),256,SMEM_BYTES>>>(w2t,256, hg,256, 0,htT,Mrows,
        0,0,0,0, 0,0, 256, Z,Z,Z,Z, 0);
    tgemm<<<dim3(2,2,Bb),256,SMEM_BYTES>>>(han,256, htT,Mrows, 0,hg,256,
        b2,mask,0,0, res,0, 256, 65536L,256L,65536L,256L, 1);
    // layer 3
    tgemm<<<dim3(128,2,1),256,SMEM_BYTES>>>(w3t,256, hg,256, 0,htT,Mrows,
        0,0,0,0, 0,0, 256, Z,Z,Z,Z, 0);
    tgemm<<<dim3(2,2,Bb),256,SMEM_BYTES>>>(han,256, htT,Mrows, 0,hg,256,
        b3,mask,0,0, res,0, 256, 65536L,256L,65536L,256L, 1);

    // LN1 + QKV (q and k in one batched launch)
    ln_kernel<<<Mrows,256>>>(res,ln1g,ln1b,hh);
    tgemm<<<dim3(16,128,2),256,SMEM_BYTES>>>(hh,256, wqkt,256, 0,hqk,HE,
        0,0,0,0, 0,0, 256, 0L,(long)2048*256,(long)Mrows*HE,Z, 0);
    tgemm<<<dim3(128,16,1),256,SMEM_BYTES>>>(wvt,256, hh,256, 0,hvT,Mrows,
        0,0,0,0, 0,0, 256, Z,Z,Z,Z, 0);

    // fused attention -> hy
    fused_attn<<<dim3(1,2,Bb*Hh),512,FA_SMEM>>>(hq,hk,hvT,dist,mask,hy);

    // att = (y@Wo + bo)*mask + res
    tgemm<<<dim3(2,128,1),256,SMEM_BYTES>>>(hy,HE, wot,HE, att,0,256,
        bo,mask,res,0, 0,0, 2048, Z,Z,Z,Z, 0);

    // FFN
    ln_kernel<<<Mrows,256>>>(att,ln2g,ln2b,hh);
    tgemm<<<dim3(8,128,1),256,SMEM_BYTES>>>(hh,256, wf1t,256, 0,hf,Ff,
        bf1,0,0,0, 0,0, 256, Z,Z,Z,Z, 2);
    tgemm<<<dim3(2,128,1),256,SMEM_BYTES>>>(hf,Ff, wf2t,Ff, out,0,256,
        bf2,mask,att,res, 0,0, 1024, Z,Z,Z,Z, 0);
}

// round 14
// speedup vs baseline: 6.6075x; 1.0696x over previous
#include <cuda_runtime.h>
#include <cuda_fp16.h>
#include <math.h>
#include <stdint.h>

#define Bb 64
#define Nn 256
#define INd 128
#define Ee 256
#define Hh 8
#define Ff 1024
#define Mrows (Bb*Nn)
#define HE (Hh*Ee)

// ---------------- fp32 scratch ----------------
__device__ float d_dis[Mrows];
__device__ float d_res[(size_t)Mrows*Ee];
__device__ float d_att[(size_t)Mrows*Ee];

// ---------------- fp16 tensors (k-contiguous) ----------------
__device__ __half h_x  [(size_t)Mrows*INd];
__device__ __half h_an [(size_t)Bb*Nn*Nn];
__device__ __half h_tT [(size_t)Ee*Mrows];
__device__ __half h_g  [(size_t)Mrows*Ee];
__device__ __half h_h  [(size_t)Mrows*Ee];
__device__ __half h_qk [(size_t)2*Mrows*HE];
__device__ __half h_vT [(size_t)HE*Mrows];
__device__ __half h_y  [(size_t)Mrows*HE];
__device__ __half h_f  [(size_t)Mrows*Ff];
__device__ __half h_w1t [256*128];
__device__ __half h_w2t [256*256];
__device__ __half h_w3t [256*256];
__device__ __half h_wqkt[(size_t)2*2048*256];
__device__ __half h_wvt [(size_t)2048*256];
__device__ __half h_wot [(size_t)256*2048];
__device__ __half h_wf1t[(size_t)1024*256];
__device__ __half h_wf2t[(size_t)256*1024];

// ---------------- asm helpers ----------------
__device__ __forceinline__ uint32_t smem_u32(const void* p){
    uint32_t a; asm("{ .reg .u64 t; cvta.to.shared.u64 t, %1; cvt.u32.u64 %0, t; }":"=r"(a):"l"(p)); return a; }
#define CP16(dst,src) asm volatile("cp.async.cg.shared.global [%0], [%1], 16;"::"r"(dst),"l"(src))
#define CP_COMMIT()   asm volatile("cp.async.commit_group;")
#define CP_WAIT0()    asm volatile("cp.async.wait_group 0;")
#define CP_WAIT1()    asm volatile("cp.async.wait_group 1;")
#define CP_WAIT3()    asm volatile("cp.async.wait_group 3;")
#define CVTP(u,lo,hi) asm("cvt.rn.f16x2.f32 %0, %1, %2;":"=r"(u):"f"(hi),"f"(lo))
#define LDS32(u,p)    (u = *(const uint32_t*)(p))
#define LDSM4(r,addr) asm volatile("ldmatrix.sync.aligned.m8n8.x4.shared.b16 {%0,%1,%2,%3}, [%4];" \
    : "=r"((r)[0]),"=r"((r)[1]),"=r"((r)[2]),"=r"((r)[3]) : "r"(addr))
#define MMA16(c,a,b) asm volatile( \
  "mma.sync.aligned.m16n8k16.row.col.f32.f16.f16.f32 {%0,%1,%2,%3},{%4,%5,%6,%7},{%8,%9},{%0,%1,%2,%3};" \
  : "+f"((c)[0]),"+f"((c)[1]),"+f"((c)[2]),"+f"((c)[3]) \
  : "r"((a)[0]),"r"((a)[1]),"r"((a)[2]),"r"((a)[3]),"r"((b)[0]),"r"((b)[1]))

// ---------------- small kernels ----------------
__global__ void deg_kernel(const float* __restrict__ adj, float* __restrict__ dis){
    int row=blockIdx.x, b=row>>8, i=row&255, t=threadIdx.x;
    const float* a=adj+(size_t)b*Nn*Nn+(size_t)i*Nn;
    float v=(t==i)?1.0f:a[t];
    __shared__ float sh[8];
    #pragma unroll
    for(int o=16;o>0;o>>=1) v+=__shfl_xor_sync(0xffffffffu,v,o);
    if((t&31)==0) sh[t>>5]=v;
    __syncthreads();
    if(t==0){ float s=0.f; for(int w=0;w<8;w++) s+=sh[w]; dis[row]=rsqrtf(fmaxf(s,1.0f)); }
}
__global__ void an_build(const float* __restrict__ adj, const float* __restrict__ dis,
                         __half* __restrict__ An){
    long idx=(long)blockIdx.x*256+threadIdx.x;
    int j=(int)(idx&255); long t=idx>>8; int i=(int)(t&255); int b=(int)(t>>8);
    float a=(i==j)?1.0f:adj[idx];
    An[idx]=__float2half_rn(a*dis[b*256+i]*dis[b*256+j]);
}
__global__ void conv_h(const float* __restrict__ in, __half* __restrict__ out){
    long i=(long)blockIdx.x*256+threadIdx.x;
    out[i]=__float2half_rn(in[i]);
}
// all weight transpose-conversions, flat tile grid
struct WT9 {
    const float* src[9];
    __half* dst[9];
    int K[9], N[9], base[9];   // base = first tile index of weight z
};
__global__ void conv_wt_all(WT9 wt, int ntot){
    int bid=blockIdx.x;
    if(bid>=ntot) return;
    int z=0;
    #pragma unroll
    for(int i=1;i<9;i++) if(bid>=wt.base[i]) z=i;
    int rel=bid-wt.base[z];
    int K=wt.K[z], N=wt.N[z];
    int ntx=K>>5;
    int k0=(rel%ntx)*32, n0=(rel/ntx)*32;
    const float* in=wt.src[z];
    __half* out=wt.dst[z];
    __shared__ float t[32][33];
    int tx=threadIdx.x, ty=threadIdx.y;
    for(int j=ty;j<32;j+=8) t[j][tx]=in[(long)(k0+j)*N + n0+tx];
    __syncthreads();
    for(int j=ty;j<32;j+=8) out[(long)(n0+j)*K + k0+tx]=__float2half_rn(t[tx][j]);
}
__global__ void ln_kernel(const float* __restrict__ x, const float* __restrict__ g,
                          const float* __restrict__ be, __half* __restrict__ out){
    int row=blockIdx.x, t=threadIdx.x;
    float v=x[(size_t)row*Ee+t];
    __shared__ float sh[8]; __shared__ float mv[2];
    float s=v;
    #pragma unroll
    for(int o=16;o>0;o>>=1) s+=__shfl_xor_sync(0xffffffffu,s,o);
    if((t&31)==0) sh[t>>5]=s;
    __syncthreads();
    if(t==0){ float m=0.f; for(int w=0;w<8;w++) m+=sh[w]; mv[0]=m*(1.0f/Ee); }
    __syncthreads();
    float m=mv[0], d=v-m; s=d*d;
    #pragma unroll
    for(int o=16;o>0;o>>=1) s+=__shfl_xor_sync(0xffffffffu,s,o);
    if((t&31)==0) sh[t>>5]=s;
    __syncthreads();
    if(t==0){ float vv=0.f; for(int w=0;w<8;w++) vv+=sh[w]; mv[1]=rsqrtf(vv*(1.0f/Ee)+1e-5f); }
    __syncthreads();
    out[(size_t)row*Ee+t]=__float2half_rn(d*mv[1]*g[t]+be[t]);
}

// ---------------- fp16 GEMM (ldmatrix fragments) ----------------
#define AP 40
#define TILE_H (128*AP)
#define NSTG 4
#define SMEM_BYTES (NSTG*2*TILE_H*2)   // 81920

__global__ void __launch_bounds__(256,2) tgemm(
    const __half* __restrict__ A, int lda, const __half* __restrict__ B, int ldb,
    float* __restrict__ Cf, __half* __restrict__ Ch, int ldc,
    const float* __restrict__ bias, const float* __restrict__ rowmask,
    const float* __restrict__ res1, const float* __restrict__ res2,
    float* __restrict__ aux, int auxinit,
    int K, long sAz, long sBz, long sCz, long sMz, int act)
{
    extern __shared__ __half smh[];
    int tid=threadIdx.x, wid=tid>>5, lane=tid&31;
    int z=blockIdx.z;
    int row0=blockIdx.y*128, col0=blockIdx.x*128;

    const __half* Ag = A + z*sAz + (long)row0*lda;
    const __half* Bg = B + z*sBz + (long)col0*ldb;
    long cbase = z*sCz;

    uint32_t sb = smem_u32(smh);
    uint32_t aoff[NSTG], boff[NSTG];
    #pragma unroll
    for(int i=0;i<NSTG;i++){ aoff[i]=sb+i*TILE_H*2; boff[i]=sb+(NSTG+i)*TILE_H*2; }

    auto loadA = [&](int buf, int k0){
        #pragma unroll
        for(int i=0;i<2;i++){
            int f=tid+i*256; int row=f>>2, c=f&3;
            CP16(aoff[buf] + (uint32_t)(row*80 + c*16),
                 Ag + (long)row*lda + k0 + c*8);
        }
    };
    auto loadB = [&](int buf, int k0){
        #pragma unroll
        for(int i=0;i<2;i++){
            int f=tid+i*256; int row=f>>2, c=f&3;
            CP16(boff[buf] + (uint32_t)(row*80 + c*16),
                 Bg + (long)row*ldb + k0 + c*8);
        }
    };

    int wm0 = (wid>>2)*64;
    int wn0 = (wid&3)*32;
    int tq = lane>>2, tr = lane&3;

    // ldmatrix lane-dependent offsets (in halfs)
    uint32_t aRow = lane&15,  aK = (lane&16)?8:0;
    uint32_t bRow = (lane&7) + ((lane>>4)<<3), bK = (lane&8)?8:0;
    uint32_t aBase = ((wm0+aRow)*AP + aK)*2;          // bytes
    uint32_t bBase = ((wn0+bRow)*AP + bK)*2;

    float cacc[4][4][4];
    #pragma unroll
    for(int a0=0;a0<4;a0++)
        #pragma unroll
        for(int b0=0;b0<4;b0++)
            #pragma unroll
            for(int c0=0;c0<4;c0++) cacc[a0][b0][c0]=0.f;

    int KT = K >> 5;
    loadA(0,0); loadB(0,0); CP_COMMIT();
    loadA(1,32); loadB(1,32); CP_COMMIT();
    loadA(2,64); loadB(2,64); CP_COMMIT();

    for(int kt=0; kt<KT; kt++){
        int buf = kt%NSTG;
        if(kt+3<KT){ int nb=(kt+3)%NSTG; loadA(nb,(kt+3)*32); loadB(nb,(kt+3)*32); }
        CP_COMMIT();
        CP_WAIT3();
        __syncthreads();

        uint32_t asm_ = aoff[buf] + aBase;
        uint32_t bsm_ = boff[buf] + bBase;
        #pragma unroll
        for(int ks=0;ks<2;ks++){
            uint32_t af[4][4], bf[4][2];
            #pragma unroll
            for(int mt=0;mt<4;mt++)
                LDSM4(af[mt], asm_ + (uint32_t)(mt*16*AP + ks*16)*2);
            #pragma unroll
            for(int p=0;p<2;p++){
                uint32_t r[4];
                LDSM4(r, bsm_ + (uint32_t)(p*16*AP + ks*16)*2);
                bf[p*2  ][0]=r[0]; bf[p*2  ][1]=r[1];
                bf[p*2+1][0]=r[2]; bf[p*2+1][1]=r[3];
            }
            #pragma unroll
            for(int mt=0;mt<4;mt++)
                #pragma unroll
                for(int nt=0;nt<4;nt++)
                    MMA16(cacc[mt][nt], af[mt], bf[nt]);
        }
        __syncthreads();
    }

    #pragma unroll
    for(int mt=0;mt<4;mt++){
        #pragma unroll
        for(int hf=0;hf<2;hf++){
            int r = row0 + wm0 + mt*16 + tq + hf*8;
            float rm = rowmask ? rowmask[z*sMz + r] : 1.0f;
            #pragma unroll
            for(int nt=0;nt<4;nt++){
                int cc = col0 + wn0 + nt*8 + tr*2;
                float v0 = cacc[mt][nt][hf*2+0];
                float v1 = cacc[mt][nt][hf*2+1];
                if(bias){ v0+=bias[cc]; v1+=bias[cc+1]; }
                if(act==1){ v0=fmaxf(v0,0.f); v1=fmaxf(v1,0.f); }
                else if(act==2){
                    v0=0.5f*v0*(1.0f+erff(v0*0.70710678118654752f));
                    v1=0.5f*v1*(1.0f+erff(v1*0.70710678118654752f));
                }
                v0*=rm; v1*=rm;
                long o = cbase + (long)r*ldc + cc;
                if(res1){ float2 t2=*(const float2*)(res1+o); v0+=t2.x; v1+=t2.y; }
                if(res2){ float2 t2=*(const float2*)(res2+o); v0+=t2.x; v1+=t2.y; }
                if(aux){
                    if(auxinit){ float2 w; w.x=v0; w.y=v1; *(float2*)(aux+o)=w; }
                    else { float2 t2=*(const float2*)(aux+o); float2 u; u.x=t2.x+v0; u.y=t2.y+v1; *(float2*)(aux+o)=u; }
                }
                if(Cf){ float2 w; w.x=v0; w.y=v1; *(float2*)(Cf+o)=w; }
                if(Ch){ uint32_t u; CVTP(u,v0,v1); *(uint32_t*)(Ch+o)=u; }
            }
        }
    }
}

// ---------------- fused attention (unchanged from R13) ----------------
#define QROW 264
#define FA_Q_B   (128*QROW*2)
#define FA_KB_B  (256*40*2)
#define FA_RED_B (FA_Q_B + 2*FA_KB_B)
#define FA_SMEM  (FA_RED_B + 6144)

__global__ void __launch_bounds__(512,1) fused_attn(
    const __half* __restrict__ q, const __half* __restrict__ k, const __half* __restrict__ vT,
    const float* __restrict__ dist, const float* __restrict__ mask, __half* __restrict__ y)
{
    extern __shared__ char smc[];
    __half* qp = (__half*)smc;
    __half* kb[2] = { (__half*)(smc+FA_Q_B), (__half*)(smc+FA_Q_B+FA_KB_B) };
    float* redA    = (float*)(smc+FA_RED_B);
    float* rowmax_ = redA + 1024;
    float* rowsum_ = rowmax_ + 128;
    float* mcol    = rowsum_ + 128;

    int tid=threadIdx.x, wid=tid>>5, lane=tid&31;
    int z=blockIdx.z, b=z>>3, h=z&7;
    int row0=blockIdx.y*128;
    const __half* qg = q + ((long)b*256+row0)*2048 + (long)h*256;
    const __half* kg = k + ((long)b*256)*2048 + (long)h*256;
    const __half* vg = vT + ((long)h*256)*16384 + (long)b*256;
    const float*  dg = dist + (long)b*65536;
    __half* yg = y + ((long)b*256+row0)*2048 + (long)h*256;

    uint32_t qpB = smem_u32(qp);
    uint32_t kbB[2] = { smem_u32(kb[0]), smem_u32(kb[1]) };

    #pragma unroll
    for(int i=0;i<8;i++){
        int f=tid+i*512; int row=f>>5, c=f&31;
        CP16(qpB + (uint32_t)(row*QROW*2 + c*16), qg + (long)row*2048 + c*8);
    }
    #pragma unroll
    for(int i=0;i<2;i++){
        int f=tid+i*512; int n=f>>2, c=f&3;
        CP16(kbB[0] + (uint32_t)(n*80 + c*16), kg + (long)n*2048 + c*8);
    }
    CP_COMMIT();

    int wn_idx = wid&7, wm_idx = wid>>3;
    int wm0 = wm_idx*64, wn0 = wn_idx*32;
    int tq = lane>>2, tr = lane&3;

    float cacc[4][4][4];
    #pragma unroll
    for(int a0=0;a0<4;a0++)
        #pragma unroll
        for(int b0=0;b0<4;b0++)
            #pragma unroll
            for(int c0=0;c0<4;c0++) cacc[a0][b0][c0]=0.f;

    for(int kt=0;kt<8;kt++){
        if(kt+1<8){
            int nb=(kt+1)&1;
            #pragma unroll
            for(int i=0;i<2;i++){
                int f=tid+i*512; int n=f>>2, c=f&3;
                CP16(kbB[nb] + (uint32_t)(n*80 + c*16),
                     kg + (long)n*2048 + (kt+1)*32 + c*8);
            }
            CP_COMMIT(); CP_WAIT1();
        } else CP_WAIT0();
        __syncthreads();
        const __half* Bs_ = kb[kt&1];
        #pragma unroll
        for(int ks=0;ks<2;ks++){
            uint32_t af[4][4], bf[4][2];
            #pragma unroll
            for(int mt=0;mt<4;mt++){
                const __half* ap = qp + (wm0+mt*16+tq)*QROW + kt*32 + ks*16 + 2*tr;
                LDS32(af[mt][0], ap);
                LDS32(af[mt][1], ap+8*QROW);
                LDS32(af[mt][2], ap+8);
                LDS32(af[mt][3], ap+8*QROW+8);
            }
            #pragma unroll
            for(int nt=0;nt<4;nt++){
                const __half* bp = Bs_ + (wn0+nt*8+tq)*40 + ks*16 + 2*tr;
                LDS32(bf[nt][0], bp);
                LDS32(bf[nt][1], bp+8);
            }
            #pragma unroll
            for(int mt=0;mt<4;mt++)
                #pragma unroll
                for(int nt=0;nt<4;nt++)
                    MMA16(cacc[mt][nt], af[mt], bf[nt]);
        }
        __syncthreads();
    }

    #pragma unroll
    for(int i=0;i<2;i++){
        int f=tid+i*512; int n=f>>2, c=f&3;
        CP16(kbB[0] + (uint32_t)(n*80 + c*16), vg + (long)n*16384 + c*8);
    }
    CP_COMMIT();

    if(tid<256) mcol[tid]=mask[b*256+tid];
    __syncthreads();

    #pragma unroll
    for(int mt=0;mt<4;mt++){
        #pragma unroll
        for(int hf=0;hf<2;hf++){
            int rl = wm0+mt*16+tq+hf*8;
            float lm=-3.0e38f;
            #pragma unroll
            for(int nt=0;nt<4;nt++){
                int c = wn0+nt*8+tr*2;
                float2 dd = *(const float2*)(dg + (long)(row0+rl)*256 + c);
                float s0 = cacc[mt][nt][hf*2+0]*0.0625f + dd.x;
                float s1 = cacc[mt][nt][hf*2+1]*0.0625f + dd.y;
                cacc[mt][nt][hf*2+0]=s0; cacc[mt][nt][hf*2+1]=s1;
                if(mcol[c]  !=0.0f) lm=fmaxf(lm,s0);
                if(mcol[c+1]!=0.0f) lm=fmaxf(lm,s1);
            }
            lm = fmaxf(lm, __shfl_xor_sync(0xffffffffu,lm,1));
            lm = fmaxf(lm, __shfl_xor_sync(0xffffffffu,lm,2));
            if(tr==0) redA[rl*8+wn_idx]=lm;
        }
    }
    __syncthreads();
    if(tid<128){ float m=-3.0e38f;
        #pragma unroll
        for(int w=0;w<8;w++) m=fmaxf(m,redA[tid*8+w]);
        rowmax_[tid]=m; }
    __syncthreads();

    #pragma unroll
    for(int mt=0;mt<4;mt++){
        #pragma unroll
        for(int hf=0;hf<2;hf++){
            int rl = wm0+mt*16+tq+hf*8;
            float mx = rowmax_[rl];
            float ls=0.f;
            #pragma unroll
            for(int nt=0;nt<4;nt++){
                int c = wn0+nt*8+tr*2;
                float p0 = (mcol[c]  !=0.0f)? expf(cacc[mt][nt][hf*2+0]-mx) : 0.0f;
                float p1 = (mcol[c+1]!=0.0f)? expf(cacc[mt][nt][hf*2+1]-mx) : 0.0f;
                cacc[mt][nt][hf*2+0]=p0; cacc[mt][nt][hf*2+1]=p1;
                ls += p0+p1;
            }
            ls += __shfl_xor_sync(0xffffffffu,ls,1);
            ls += __shfl_xor_sync(0xffffffffu,ls,2);
            if(tr==0) redA[rl*8+wn_idx]=ls;
        }
    }
    __syncthreads();
    if(tid<128){ float s=0.f;
        #pragma unroll
        for(int w=0;w<8;w++) s+=redA[tid*8+w];
        rowsum_[tid]=s; }
    __syncthreads();

    #pragma unroll
    for(int mt=0;mt<4;mt++){
        #pragma unroll
        for(int hf=0;hf<2;hf++){
            int rl = wm0+mt*16+tq+hf*8;
            float sum = rowsum_[rl];
            float inv = (sum>0.0f)? 1.0f/sum : 0.0f;
            #pragma unroll
            for(int nt=0;nt<4;nt++){
                int c = wn0+nt*8+tr*2;
                float p0 = cacc[mt][nt][hf*2+0]*inv;
                float p1 = cacc[mt][nt][hf*2+1]*inv;
                uint32_t u; CVTP(u, p0, p1);
                *(uint32_t*)(qp + rl*QROW + c) = u;
                cacc[mt][nt][hf*2+0]=0.f; cacc[mt][nt][hf*2+1]=0.f;
            }
        }
    }
    __syncthreads();

    for(int kt=0;kt<8;kt++){
        if(kt+1<8){
            int nb=(kt+1)&1;
            #pragma unroll
            for(int i=0;i<2;i++){
                int f=tid+i*512; int n=f>>2, c=f&3;
                CP16(kbB[nb] + (uint32_t)(n*80 + c*16),
                     vg + (long)n*16384 + (kt+1)*32 + c*8);
            }
            CP_COMMIT(); CP_WAIT1();
        } else CP_WAIT0();
        __syncthreads();
        const __half* Bs_ = kb[kt&1];
        #pragma unroll
        for(int ks=0;ks<2;ks++){
            uint32_t af[4][4], bf[4][2];
            #pragma unroll
            for(int mt=0;mt<4;mt++){
                const __half* ap = qp + (wm0+mt*16+tq)*QROW + kt*32 + ks*16 + 2*tr;
                LDS32(af[mt][0], ap);
                LDS32(af[mt][1], ap+8*QROW);
                LDS32(af[mt][2], ap+8);
                LDS32(af[mt][3], ap+8*QROW+8);
            }
            #pragma unroll
            for(int nt=0;nt<4;nt++){
                const __half* bp = Bs_ + (wn0+nt*8+tq)*40 + ks*16 + 2*tr;
                LDS32(bf[nt][0], bp);
                LDS32(bf[nt][1], bp+8);
            }
            #pragma unroll
            for(int mt=0;mt<4;mt++)
                #pragma unroll
                for(int nt=0;nt<4;nt++)
                    MMA16(cacc[mt][nt], af[mt], bf[nt]);
        }
        __syncthreads();
    }

    #pragma unroll
    for(int mt=0;mt<4;mt++){
        #pragma unroll
        for(int hf=0;hf<2;hf++){
            int rl = wm0+mt*16+tq+hf*8;
            #pragma unroll
            for(int nt=0;nt<4;nt++){
                int c = wn0+nt*8+tr*2;
                uint32_t u; CVTP(u, cacc[mt][nt][hf*2+0], cacc[mt][nt][hf*2+1]);
                *(uint32_t*)(yg + (long)rl*2048 + c) = u;
            }
        }
    }
}

// ---------------- launch ----------------
extern "C" void kernel_launch(void* const* d_in, const int* in_sizes, int n_in,
                              void* d_out, int out_size){
    const float* x=(const float*)d_in[0];
    const float* adj=(const float*)d_in[1];
    const float* mask=(const float*)d_in[2];
    const float* dist=(const float*)d_in[3];
    const float* W1=(const float*)d_in[4];
    const float* b1=(const float*)d_in[5];
    const float* W2=(const float*)d_in[6];
    const float* b2=(const float*)d_in[7];
    const float* W3=(const float*)d_in[8];
    const float* b3=(const float*)d_in[9];
    const float* ln1g=(const float*)d_in[10];
    const float* ln1b=(const float*)d_in[11];
    const float* Wq=(const float*)d_in[12];
    const float* Wk=(const float*)d_in[13];
    const float* Wv=(const float*)d_in[14];
    const float* Wo=(const float*)d_in[15];
    const float* bo=(const float*)d_in[16];
    const float* ln2g=(const float*)d_in[17];
    const float* ln2b=(const float*)d_in[18];
    const float* Wf1=(const float*)d_in[19];
    const float* bf1=(const float*)d_in[20];
    const float* Wf2=(const float*)d_in[21];
    const float* bf2=(const float*)d_in[22];
    float* out=(float*)d_out;

    float *dis,*res,*att;
    cudaGetSymbolAddress((void**)&dis,d_dis);
    cudaGetSymbolAddress((void**)&res,d_res);
    cudaGetSymbolAddress((void**)&att,d_att);
    __half *hx,*han,*htT,*hg,*hh,*hqk,*hvT,*hy,*hf;
    __half *w1t,*w2t,*w3t,*wqkt,*wvt,*wot,*wf1t,*wf2t;
    cudaGetSymbolAddress((void**)&hx,h_x);
    cudaGetSymbolAddress((void**)&han,h_an);
    cudaGetSymbolAddress((void**)&htT,h_tT);
    cudaGetSymbolAddress((void**)&hg,h_g);
    cudaGetSymbolAddress((void**)&hh,h_h);
    cudaGetSymbolAddress((void**)&hqk,h_qk);
    cudaGetSymbolAddress((void**)&hvT,h_vT);
    cudaGetSymbolAddress((void**)&hy,h_y);
    cudaGetSymbolAddress((void**)&hf,h_f);
    cudaGetSymbolAddress((void**)&w1t,h_w1t);
    cudaGetSymbolAddress((void**)&w2t,h_w2t);
    cudaGetSymbolAddress((void**)&w3t,h_w3t);
    cudaGetSymbolAddress((void**)&wqkt,h_wqkt);
    cudaGetSymbolAddress((void**)&wvt,h_wvt);
    cudaGetSymbolAddress((void**)&wot,h_wot);
    cudaGetSymbolAddress((void**)&wf1t,h_wf1t);
    cudaGetSymbolAddress((void**)&wf2t,h_wf2t);
    __half* hq = hqk;
    __half* hk = hqk + (size_t)Mrows*HE;

    cudaFuncSetAttribute(tgemm, cudaFuncAttributeMaxDynamicSharedMemorySize, SMEM_BYTES);
    cudaFuncSetAttribute(fused_attn, cudaFuncAttributeMaxDynamicSharedMemorySize, FA_SMEM);
    dim3 tb(32,8);
    const long Z=0;

    deg_kernel<<<Mrows,256>>>(adj,dis);
    an_build<<<(Bb*Nn*Nn)/256,256>>>(adj,dis,han);
    conv_h<<<(Mrows*INd)/256,256>>>(x,hx);
    WT9 wt;
    wt.src[0]=W1;  wt.dst[0]=w1t;                   wt.K[0]=128;  wt.N[0]=256;
    wt.src[1]=W2;  wt.dst[1]=w2t;                   wt.K[1]=256;  wt.N[1]=256;
    wt.src[2]=W3;  wt.dst[2]=w3t;                   wt.K[2]=256;  wt.N[2]=256;
    wt.src[3]=Wq;  wt.dst[3]=wqkt;                  wt.K[3]=256;  wt.N[3]=2048;
    wt.src[4]=Wk;  wt.dst[4]=wqkt+(size_t)2048*256; wt.K[4]=256;  wt.N[4]=2048;
    wt.src[5]=Wv;  wt.dst[5]=wvt;                   wt.K[5]=256;  wt.N[5]=2048;
    wt.src[6]=Wo;  wt.dst[6]=wot;                   wt.K[6]=2048; wt.N[6]=256;
    wt.src[7]=Wf1; wt.dst[7]=wf1t;                  wt.K[7]=256;  wt.N[7]=1024;
    wt.src[8]=Wf2; wt.dst[8]=wf2t;                  wt.K[8]=1024; wt.N[8]=256;
    int ntot=0;
    for(int i=0;i<9;i++){ wt.base[i]=ntot; ntot += (wt.K[i]>>5)*(wt.N[i]>>5); }
    conv_wt_all<<<ntot,tb>>>(wt,ntot);

    // GCN layer 1
    tgemm<<<dim3(128,2,1),256,SMEM_BYTES>>>(w1t,128, hx,128, 0,htT,Mrows,
        0,0,0,0, 0,0, 128, Z,Z,Z,Z, 0);
    tgemm<<<dim3(2,2,Bb),256,SMEM_BYTES>>>(han,256, htT,Mrows, 0,hg,256,
        b1,mask,0,0, res,1, 256, 65536L,256L,65536L,256L, 1);
    // layer 2
    tgemm<<<dim3(128,2,1),256,SMEM_BYTES>>>(w2t,256, hg,256, 0,htT,Mrows,
        0,0,0,0, 0,0, 256, Z,Z,Z,Z, 0);
    tgemm<<<dim3(2,2,Bb),256,SMEM_BYTES>>>(han,256, htT,Mrows, 0,hg,256,
        b2,mask,0,0, res,0, 256, 65536L,256L,65536L,256L, 1);
    // layer 3
    tgemm<<<dim3(128,2,1),256,SMEM_BYTES>>>(w3t,256, hg,256, 0,htT,Mrows,
        0,0,0,0, 0,0, 256, Z,Z,Z,Z, 0);
    tgemm<<<dim3(2,2,Bb),256,SMEM_BYTES>>>(han,256, htT,Mrows, 0,hg,256,
        b3,mask,0,0, res,0, 256, 65536L,256L,65536L,256L, 1);

    // LN1 + QKV
    ln_kernel<<<Mrows,256>>>(res,ln1g,ln1b,hh);
    tgemm<<<dim3(16,128,2),256,SMEM_BYTES>>>(hh,256, wqkt,256, 0,hqk,HE,
        0,0,0,0, 0,0, 256, 0L,(long)2048*256,(long)Mrows*HE,Z, 0);
    tgemm<<<dim3(128,16,1),256,SMEM_BYTES>>>(wvt,256, hh,256, 0,hvT,Mrows,
        0,0,0,0, 0,0, 256, Z,Z,Z,Z, 0);

    // fused attention
    fused_attn<<<dim3(1,2,Bb*Hh),512,FA_SMEM>>>(hq,hk,hvT,dist,mask,hy);

    // att = (y@Wo + bo)*mask + res
    tgemm<<<dim3(2,128,1),256,SMEM_BYTES>>>(hy,HE, wot,HE, att,0,256,
        bo,mask,res,0, 0,0, 2048, Z,Z,Z,Z, 0);

    // FFN
    ln_kernel<<<Mrows,256>>>(att,ln2g,ln2b,hh);
    tgemm<<<dim3(8,128,1),256,SMEM_BYTES>>>(hh,256, wf1t,256, 0,hf,Ff,
        bf1,0,0,0, 0,0, 256, Z,Z,Z,Z, 2);
    tgemm<<<dim3(2,128,1),256,SMEM_BYTES>>>(hf,Ff, wf2t,Ff, out,0,256,
        bf2,mask,att,res, 0,0, 1024, Z,Z,Z,Z, 0);
}

// round 17
// speedup vs baseline: 6.6959x; 1.0134x over previous
#include <cuda_runtime.h>
#include <cuda_fp16.h>
#include <math.h>
#include <stdint.h>

#define Bb 64
#define Nn 256
#define INd 128
#define Ee 256
#define Hh 8
#define Ff 1024
#define Mrows (Bb*Nn)
#define HE (Hh*Ee)

// ---------------- fp32 scratch ----------------
__device__ float d_dis[Mrows];
__device__ float d_res[(size_t)Mrows*Ee];
__device__ float d_att[(size_t)Mrows*Ee];

// ---------------- fp16 tensors (k-contiguous) ----------------
__device__ __half h_x  [(size_t)Mrows*INd];
__device__ __half h_an [(size_t)Bb*Nn*Nn];
__device__ __half h_tT [(size_t)Ee*Mrows];
__device__ __half h_g  [(size_t)Mrows*Ee];
__device__ __half h_h  [(size_t)Mrows*Ee];
__device__ __half h_qk [(size_t)2*Mrows*HE];
__device__ __half h_vT [(size_t)HE*Mrows];
__device__ __half h_y  [(size_t)Mrows*HE];
__device__ __half h_f  [(size_t)Mrows*Ff];
__device__ __half h_w1t [256*128];
__device__ __half h_w2t [256*256];
__device__ __half h_w3t [256*256];
__device__ __half h_wqkt[(size_t)2*2048*256];
__device__ __half h_wvt [(size_t)2048*256];
__device__ __half h_wot [(size_t)256*2048];
__device__ __half h_wf1t[(size_t)1024*256];
__device__ __half h_wf2t[(size_t)256*1024];

// ---------------- asm helpers ----------------
__device__ __forceinline__ uint32_t smem_u32(const void* p){
    uint32_t a; asm("{ .reg .u64 t; cvta.to.shared.u64 t, %1; cvt.u32.u64 %0, t; }":"=r"(a):"l"(p)); return a; }
#define CP16(dst,src) asm volatile("cp.async.cg.shared.global [%0], [%1], 16;"::"r"(dst),"l"(src))
#define CP_COMMIT()   asm volatile("cp.async.commit_group;")
#define CP_WAIT0()    asm volatile("cp.async.wait_group 0;")
#define CP_WAIT1()    asm volatile("cp.async.wait_group 1;")
#define CP_WAIT3()    asm volatile("cp.async.wait_group 3;")
#define CVTP(u,lo,hi) asm("cvt.rn.f16x2.f32 %0, %1, %2;":"=r"(u):"f"(hi),"f"(lo))
#define LDSM4(r,addr) asm volatile("ldmatrix.sync.aligned.m8n8.x4.shared.b16 {%0,%1,%2,%3}, [%4];" \
    : "=r"((r)[0]),"=r"((r)[1]),"=r"((r)[2]),"=r"((r)[3]) : "r"(addr))
#define MMA16(c,a,b) asm volatile( \
  "mma.sync.aligned.m16n8k16.row.col.f32.f16.f16.f32 {%0,%1,%2,%3},{%4,%5,%6,%7},{%8,%9},{%0,%1,%2,%3};" \
  : "+f"((c)[0]),"+f"((c)[1]),"+f"((c)[2]),"+f"((c)[3]) \
  : "r"((a)[0]),"r"((a)[1]),"r"((a)[2]),"r"((a)[3]),"r"((b)[0]),"r"((b)[1]))

// ---------------- small kernels ----------------
__global__ void deg_kernel(const float* __restrict__ adj, float* __restrict__ dis){
    int row=blockIdx.x, b=row>>8, i=row&255, t=threadIdx.x;
    const float* a=adj+(size_t)b*Nn*Nn+(size_t)i*Nn;
    float v=(t==i)?1.0f:a[t];
    __shared__ float sh[8];
    #pragma unroll
    for(int o=16;o>0;o>>=1) v+=__shfl_xor_sync(0xffffffffu,v,o);
    if((t&31)==0) sh[t>>5]=v;
    __syncthreads();
    if(t==0){ float s=0.f; for(int w=0;w<8;w++) s+=sh[w]; dis[row]=rsqrtf(fmaxf(s,1.0f)); }
}
__global__ void an_build(const float* __restrict__ adj, const float* __restrict__ dis,
                         __half* __restrict__ An){
    long idx=(long)blockIdx.x*256+threadIdx.x;
    int j=(int)(idx&255); long t=idx>>8; int i=(int)(t&255); int b=(int)(t>>8);
    float a=(i==j)?1.0f:adj[idx];
    An[idx]=__float2half_rn(a*dis[b*256+i]*dis[b*256+j]);
}
__global__ void conv_h(const float* __restrict__ in, __half* __restrict__ out){
    long i=(long)blockIdx.x*256+threadIdx.x;
    out[i]=__float2half_rn(in[i]);
}
// all weight transpose-conversions, flat tile grid, float4 loads, 32k x 128n tiles
struct WT9 {
    const float* src[9];
    __half* dst[9];
    int K[9], N[9], base[9];
};
__global__ void conv_wt_all(WT9 wt, int ntot){
    int bid=blockIdx.x;
    if(bid>=ntot) return;
    int z=0;
    #pragma unroll
    for(int i=1;i<9;i++) if(bid>=wt.base[i]) z=i;
    int rel=bid-wt.base[z];
    int K=wt.K[z], N=wt.N[z];
    int ntx=K>>5;
    int k0=(rel%ntx)*32, n0=(rel/ntx)*128;
    const float* in=wt.src[z];
    __half* out=wt.dst[z];
    __shared__ float t[32][132];
    int tx=threadIdx.x, ty=threadIdx.y;
    for(int j=ty;j<32;j+=8){
        float4 v=*(const float4*)(in + (long)(k0+j)*N + n0 + tx*4);
        t[j][tx*4+0]=v.x; t[j][tx*4+1]=v.y; t[j][tx*4+2]=v.z; t[j][tx*4+3]=v.w;
    }
    __syncthreads();
    for(int c=ty;c<128;c+=8)
        out[(long)(n0+c)*K + k0+tx]=__float2half_rn(t[tx][c]);
}
__global__ void ln_kernel(const float* __restrict__ x, const float* __restrict__ g,
                          const float* __restrict__ be, __half* __restrict__ out){
    int row=blockIdx.x, t=threadIdx.x;
    float v=x[(size_t)row*Ee+t];
    __shared__ float sh[8]; __shared__ float mv[2];
    float s=v;
    #pragma unroll
    for(int o=16;o>0;o>>=1) s+=__shfl_xor_sync(0xffffffffu,s,o);
    if((t&31)==0) sh[t>>5]=s;
    __syncthreads();
    if(t==0){ float m=0.f; for(int w=0;w<8;w++) m+=sh[w]; mv[0]=m*(1.0f/Ee); }
    __syncthreads();
    float m=mv[0], d=v-m; s=d*d;
    #pragma unroll
    for(int o=16;o>0;o>>=1) s+=__shfl_xor_sync(0xffffffffu,s,o);
    if((t&31)==0) sh[t>>5]=s;
    __syncthreads();
    if(t==0){ float vv=0.f; for(int w=0;w<8;w++) vv+=sh[w]; mv[1]=rsqrtf(vv*(1.0f/Ee)+1e-5f); }
    __syncthreads();
    out[(size_t)row*Ee+t]=__float2half_rn(d*mv[1]*g[t]+be[t]);
}

// ---------------- fp16 GEMM (ldmatrix fragments) ----------------
#define AP 40
#define TILE_H (128*AP)
#define NSTG 4
#define SMEM_BYTES (NSTG*2*TILE_H*2)   // 81920

__global__ void __launch_bounds__(256,2) tgemm(
    const __half* __restrict__ A, int lda, const __half* __restrict__ B, int ldb,
    float* __restrict__ Cf, __half* __restrict__ Ch, int ldc,
    const float* __restrict__ bias, const float* __restrict__ rowmask,
    const float* __restrict__ res1, const float* __restrict__ res2,
    float* __restrict__ aux, int auxinit,
    int K, long sAz, long sBz, long sCz, long sMz, int act)
{
    extern __shared__ __half smh[];
    int tid=threadIdx.x, wid=tid>>5, lane=tid&31;
    int z=blockIdx.z;
    int row0=blockIdx.y*128, col0=blockIdx.x*128;

    const __half* Ag = A + z*sAz + (long)row0*lda;
    const __half* Bg = B + z*sBz + (long)col0*ldb;
    long cbase = z*sCz;

    uint32_t sb = smem_u32(smh);
    uint32_t aoff[NSTG], boff[NSTG];
    #pragma unroll
    for(int i=0;i<NSTG;i++){ aoff[i]=sb+i*TILE_H*2; boff[i]=sb+(NSTG+i)*TILE_H*2; }

    auto loadA = [&](int buf, int k0){
        #pragma unroll
        for(int i=0;i<2;i++){
            int f=tid+i*256; int row=f>>2, c=f&3;
            CP16(aoff[buf] + (uint32_t)(row*80 + c*16),
                 Ag + (long)row*lda + k0 + c*8);
        }
    };
    auto loadB = [&](int buf, int k0){
        #pragma unroll
        for(int i=0;i<2;i++){
            int f=tid+i*256; int row=f>>2, c=f&3;
            CP16(boff[buf] + (uint32_t)(row*80 + c*16),
                 Bg + (long)row*ldb + k0 + c*8);
        }
    };

    int wm0 = (wid>>2)*64;
    int wn0 = (wid&3)*32;
    int tq = lane>>2, tr = lane&3;

    uint32_t aRow = lane&15,  aK = (lane&16)?8:0;
    uint32_t bRow = (lane&7) + ((lane>>4)<<3), bK = (lane&8)?8:0;
    uint32_t aBase = ((wm0+aRow)*AP + aK)*2;
    uint32_t bBase = ((wn0+bRow)*AP + bK)*2;

    float cacc[4][4][4];
    #pragma unroll
    for(int a0=0;a0<4;a0++)
        #pragma unroll
        for(int b0=0;b0<4;b0++)
            #pragma unroll
            for(int c0=0;c0<4;c0++) cacc[a0][b0][c0]=0.f;

    int KT = K >> 5;
    loadA(0,0); loadB(0,0); CP_COMMIT();
    loadA(1,32); loadB(1,32); CP_COMMIT();
    loadA(2,64); loadB(2,64); CP_COMMIT();

    for(int kt=0; kt<KT; kt++){
        int buf = kt%NSTG;
        if(kt+3<KT){ int nb=(kt+3)%NSTG; loadA(nb,(kt+3)*32); loadB(nb,(kt+3)*32); }
        CP_COMMIT();
        CP_WAIT3();
        __syncthreads();

        uint32_t asm_ = aoff[buf] + aBase;
        uint32_t bsm_ = boff[buf] + bBase;
        #pragma unroll
        for(int ks=0;ks<2;ks++){
            uint32_t af[4][4], bf[4][2];
            #pragma unroll
            for(int mt=0;mt<4;mt++)
                LDSM4(af[mt], asm_ + (uint32_t)(mt*16*AP + ks*16)*2);
            #pragma unroll
            for(int p=0;p<2;p++){
                uint32_t r[4];
                LDSM4(r, bsm_ + (uint32_t)(p*16*AP + ks*16)*2);
                bf[p*2  ][0]=r[0]; bf[p*2  ][1]=r[1];
                bf[p*2+1][0]=r[2]; bf[p*2+1][1]=r[3];
            }
            #pragma unroll
            for(int mt=0;mt<4;mt++)
                #pragma unroll
                for(int nt=0;nt<4;nt++)
                    MMA16(cacc[mt][nt], af[mt], bf[nt]);
        }
        __syncthreads();
    }

    #pragma unroll
    for(int mt=0;mt<4;mt++){
        #pragma unroll
        for(int hf=0;hf<2;hf++){
            int r = row0 + wm0 + mt*16 + tq + hf*8;
            float rm = rowmask ? rowmask[z*sMz + r] : 1.0f;
            #pragma unroll
            for(int nt=0;nt<4;nt++){
                int cc = col0 + wn0 + nt*8 + tr*2;
                float v0 = cacc[mt][nt][hf*2+0];
                float v1 = cacc[mt][nt][hf*2+1];
                if(bias){ v0+=bias[cc]; v1+=bias[cc+1]; }
                if(act==1){ v0=fmaxf(v0,0.f); v1=fmaxf(v1,0.f); }
                else if(act==2){
                    v0=0.5f*v0*(1.0f+erff(v0*0.70710678118654752f));
                    v1=0.5f*v1*(1.0f+erff(v1*0.70710678118654752f));
                }
                v0*=rm; v1*=rm;
                long o = cbase + (long)r*ldc + cc;
                if(res1){ float2 t2=*(const float2*)(res1+o); v0+=t2.x; v1+=t2.y; }
                if(res2){ float2 t2=*(const float2*)(res2+o); v0+=t2.x; v1+=t2.y; }
                if(aux){
                    if(auxinit){ float2 w; w.x=v0; w.y=v1; *(float2*)(aux+o)=w; }
                    else { float2 t2=*(const float2*)(aux+o); float2 u; u.x=t2.x+v0; u.y=t2.y+v1; *(float2*)(aux+o)=u; }
                }
                if(Cf){ float2 w; w.x=v0; w.y=v1; *(float2*)(Cf+o)=w; }
                if(Ch){ uint32_t u; CVTP(u,v0,v1); *(uint32_t*)(Ch+o)=u; }
            }
        }
    }
}

// ---------------- fused attention (ldmatrix fragments) ----------------
#define QROW 264
#define FA_Q_B   (128*QROW*2)
#define FA_KB_B  (256*40*2)
#define FA_RED_B (FA_Q_B + 2*FA_KB_B)
#define FA_SMEM  (FA_RED_B + 6144)

__global__ void __launch_bounds__(512,1) fused_attn(
    const __half* __restrict__ q, const __half* __restrict__ k, const __half* __restrict__ vT,
    const float* __restrict__ dist, const float* __restrict__ mask, __half* __restrict__ y)
{
    extern __shared__ char smc[];
    __half* qp = (__half*)smc;
    float* redA    = (float*)(smc+FA_RED_B);
    float* rowmax_ = redA + 1024;
    float* rowsum_ = rowmax_ + 128;
    float* mcol    = rowsum_ + 128;

    int tid=threadIdx.x, wid=tid>>5, lane=tid&31;
    int z=blockIdx.z, b=z>>3, h=z&7;
    int row0=blockIdx.y*128;
    const __half* qg = q + ((long)b*256+row0)*2048 + (long)h*256;
    const __half* kg = k + ((long)b*256)*2048 + (long)h*256;
    const __half* vg = vT + ((long)h*256)*16384 + (long)b*256;
    const float*  dg = dist + (long)b*65536;
    __half* yg = y + ((long)b*256+row0)*2048 + (long)h*256;

    uint32_t qpB = smem_u32(qp);
    uint32_t kbB[2] = { qpB + FA_Q_B, qpB + FA_Q_B + FA_KB_B };

    #pragma unroll
    for(int i=0;i<8;i++){
        int f=tid+i*512; int row=f>>5, c=f&31;
        CP16(qpB + (uint32_t)(row*QROW*2 + c*16), qg + (long)row*2048 + c*8);
    }
    #pragma unroll
    for(int i=0;i<2;i++){
        int f=tid+i*512; int n=f>>2, c=f&3;
        CP16(kbB[0] + (uint32_t)(n*80 + c*16), kg + (long)n*2048 + c*8);
    }
    CP_COMMIT();

    int wn_idx = wid&7, wm_idx = wid>>3;
    int wm0 = wm_idx*64, wn0 = wn_idx*32;
    int tq = lane>>2, tr = lane&3;

    uint32_t aRow = lane&15,  aK = (lane&16)?8:0;
    uint32_t bRow = (lane&7) + ((lane>>4)<<3), bK = (lane&8)?8:0;
    uint32_t aBase = qpB + ((wm0+aRow)*QROW + aK)*2;
    uint32_t bBase = ((wn0+bRow)*40 + bK)*2;

    float cacc[4][4][4];
    #pragma unroll
    for(int a0=0;a0<4;a0++)
        #pragma unroll
        for(int b0=0;b0<4;b0++)
            #pragma unroll
            for(int c0=0;c0<4;c0++) cacc[a0][b0][c0]=0.f;

    // ---- phase 1: S = q @ k^T ----
    for(int kt=0;kt<8;kt++){
        if(kt+1<8){
            int nb=(kt+1)&1;
            #pragma unroll
            for(int i=0;i<2;i++){
                int f=tid+i*512; int n=f>>2, c=f&3;
                CP16(kbB[nb] + (uint32_t)(n*80 + c*16),
                     kg + (long)n*2048 + (kt+1)*32 + c*8);
            }
            CP_COMMIT(); CP_WAIT1();
        } else CP_WAIT0();
        __syncthreads();
        uint32_t bsm_ = kbB[kt&1] + bBase;
        uint32_t asm_ = aBase + (uint32_t)(kt*32)*2;
        #pragma unroll
        for(int ks=0;ks<2;ks++){
            uint32_t af[4][4], bf[4][2];
            #pragma unroll
            for(int mt=0;mt<4;mt++)
                LDSM4(af[mt], asm_ + (uint32_t)(mt*16*QROW + ks*16)*2);
            #pragma unroll
            for(int p=0;p<2;p++){
                uint32_t r[4];
                LDSM4(r, bsm_ + (uint32_t)(p*16*40 + ks*16)*2);
                bf[p*2  ][0]=r[0]; bf[p*2  ][1]=r[1];
                bf[p*2+1][0]=r[2]; bf[p*2+1][1]=r[3];
            }
            #pragma unroll
            for(int mt=0;mt<4;mt++)
                #pragma unroll
                for(int nt=0;nt<4;nt++)
                    MMA16(cacc[mt][nt], af[mt], bf[nt]);
        }
        __syncthreads();
    }

    #pragma unroll
    for(int i=0;i<2;i++){
        int f=tid+i*512; int n=f>>2, c=f&3;
        CP16(kbB[0] + (uint32_t)(n*80 + c*16), vg + (long)n*16384 + c*8);
    }
    CP_COMMIT();

    if(tid<256) mcol[tid]=mask[b*256+tid];
    __syncthreads();

    #pragma unroll
    for(int mt=0;mt<4;mt++){
        #pragma unroll
        for(int hf=0;hf<2;hf++){
            int rl = wm0+mt*16+tq+hf*8;
            float lm=-3.0e38f;
            #pragma unroll
            for(int nt=0;nt<4;nt++){
                int c = wn0+nt*8+tr*2;
                float2 dd = *(const float2*)(dg + (long)(row0+rl)*256 + c);
                float s0 = cacc[mt][nt][hf*2+0]*0.0625f + dd.x;
                float s1 = cacc[mt][nt][hf*2+1]*0.0625f + dd.y;
                cacc[mt][nt][hf*2+0]=s0; cacc[mt][nt][hf*2+1]=s1;
                if(mcol[c]  !=0.0f) lm=fmaxf(lm,s0);
                if(mcol[c+1]!=0.0f) lm=fmaxf(lm,s1);
            }
            lm = fmaxf(lm, __shfl_xor_sync(0xffffffffu,lm,1));
            lm = fmaxf(lm, __shfl_xor_sync(0xffffffffu,lm,2));
            if(tr==0) redA[rl*8+wn_idx]=lm;
        }
    }
    __syncthreads();
    if(tid<128){ float m=-3.0e38f;
        #pragma unroll
        for(int w=0;w<8;w++) m=fmaxf(m,redA[tid*8+w]);
        rowmax_[tid]=m; }
    __syncthreads();

    #pragma unroll
    for(int mt=0;mt<4;mt++){
        #pragma unroll
        for(int hf=0;hf<2;hf++){
            int rl = wm0+mt*16+tq+hf*8;
            float mx = rowmax_[rl];
            float ls=0.f;
            #pragma unroll
            for(int nt=0;nt<4;nt++){
                int c = wn0+nt*8+tr*2;
                float p0 = (mcol[c]  !=0.0f)? expf(cacc[mt][nt][hf*2+0]-mx) : 0.0f;
                float p1 = (mcol[c+1]!=0.0f)? expf(cacc[mt][nt][hf*2+1]-mx) : 0.0f;
                cacc[mt][nt][hf*2+0]=p0; cacc[mt][nt][hf*2+1]=p1;
                ls += p0+p1;
            }
            ls += __shfl_xor_sync(0xffffffffu,ls,1);
            ls += __shfl_xor_sync(0xffffffffu,ls,2);
            if(tr==0) redA[rl*8+wn_idx]=ls;
        }
    }
    __syncthreads();
    if(tid<128){ float s=0.f;
        #pragma unroll
        for(int w=0;w<8;w++) s+=redA[tid*8+w];
        rowsum_[tid]=s; }
    __syncthreads();

    #pragma unroll
    for(int mt=0;mt<4;mt++){
        #pragma unroll
        for(int hf=0;hf<2;hf++){
            int rl = wm0+mt*16+tq+hf*8;
            float sum = rowsum_[rl];
            float inv = (sum>0.0f)? 1.0f/sum : 0.0f;
            #pragma unroll
            for(int nt=0;nt<4;nt++){
                int c = wn0+nt*8+tr*2;
                float p0 = cacc[mt][nt][hf*2+0]*inv;
                float p1 = cacc[mt][nt][hf*2+1]*inv;
                uint32_t u; CVTP(u, p0, p1);
                *(uint32_t*)(qp + rl*QROW + c) = u;
                cacc[mt][nt][hf*2+0]=0.f; cacc[mt][nt][hf*2+1]=0.f;
            }
        }
    }
    __syncthreads();

    // ---- phase 2: Y = P @ v ----
    for(int kt=0;kt<8;kt++){
        if(kt+1<8){
            int nb=(kt+1)&1;
            #pragma unroll
            for(int i=0;i<2;i++){
                int f=tid+i*512; int n=f>>2, c=f&3;
                CP16(kbB[nb] + (uint32_t)(n*80 + c*16),
                     vg + (long)n*16384 + (kt+1)*32 + c*8);
            }
            CP_COMMIT(); CP_WAIT1();
        } else CP_WAIT0();
        __syncthreads();
        uint32_t bsm_ = kbB[kt&1] + bBase;
        uint32_t asm_ = aBase + (uint32_t)(kt*32)*2;
        #pragma unroll
        for(int ks=0;ks<2;ks++){
            uint32_t af[4][4], bf[4][2];
            #pragma unroll
            for(int mt=0;mt<4;mt++)
                LDSM4(af[mt], asm_ + (uint32_t)(mt*16*QROW + ks*16)*2);
            #pragma unroll
            for(int p=0;p<2;p++){
                uint32_t r[4];
                LDSM4(r, bsm_ + (uint32_t)(p*16*40 + ks*16)*2);
                bf[p*2  ][0]=r[0]; bf[p*2  ][1]=r[1];
                bf[p*2+1][0]=r[2]; bf[p*2+1][1]=r[3];
            }
            #pragma unroll
            for(int mt=0;mt<4;mt++)
                #pragma unroll
                for(int nt=0;nt<4;nt++)
                    MMA16(cacc[mt][nt], af[mt], bf[nt]);
        }
        __syncthreads();
    }

    #pragma unroll
    for(int mt=0;mt<4;mt++){
        #pragma unroll
        for(int hf=0;hf<2;hf++){
            int rl = wm0+mt*16+tq+hf*8;
            #pragma unroll
            for(int nt=0;nt<4;nt++){
                int c = wn0+nt*8+tr*2;
                uint32_t u; CVTP(u, cacc[mt][nt][hf*2+0], cacc[mt][nt][hf*2+1]);
                *(uint32_t*)(yg + (long)rl*2048 + c) = u;
            }
        }
    }
}

// ---------------- launch ----------------
extern "C" void kernel_launch(void* const* d_in, const int* in_sizes, int n_in,
                              void* d_out, int out_size){
    const float* x=(const float*)d_in[0];
    const float* adj=(const float*)d_in[1];
    const float* mask=(const float*)d_in[2];
    const float* dist=(const float*)d_in[3];
    const float* W1=(const float*)d_in[4];
    const float* b1=(const float*)d_in[5];
    const float* W2=(const float*)d_in[6];
    const float* b2=(const float*)d_in[7];
    const float* W3=(const float*)d_in[8];
    const float* b3=(const float*)d_in[9];
    const float* ln1g=(const float*)d_in[10];
    const float* ln1b=(const float*)d_in[11];
    const float* Wq=(const float*)d_in[12];
    const float* Wk=(const float*)d_in[13];
    const float* Wv=(const float*)d_in[14];
    const float* Wo=(const float*)d_in[15];
    const float* bo=(const float*)d_in[16];
    const float* ln2g=(const float*)d_in[17];
    const float* ln2b=(const float*)d_in[18];
    const float* Wf1=(const float*)d_in[19];
    const float* bf1=(const float*)d_in[20];
    const float* Wf2=(const float*)d_in[21];
    const float* bf2=(const float*)d_in[22];
    float* out=(float*)d_out;

    float *dis,*res,*att;
    cudaGetSymbolAddress((void**)&dis,d_dis);
    cudaGetSymbolAddress((void**)&res,d_res);
    cudaGetSymbolAddress((void**)&att,d_att);
    __half *hx,*han,*htT,*hg,*hh,*hqk,*hvT,*hy,*hf;
    __half *w1t,*w2t,*w3t,*wqkt,*wvt,*wot,*wf1t,*wf2t;
    cudaGetSymbolAddress((void**)&hx,h_x);
    cudaGetSymbolAddress((void**)&han,h_an);
    cudaGetSymbolAddress((void**)&htT,h_tT);
    cudaGetSymbolAddress((void**)&hg,h_g);
    cudaGetSymbolAddress((void**)&hh,h_h);
    cudaGetSymbolAddress((void**)&hqk,h_qk);
    cudaGetSymbolAddress((void**)&hvT,h_vT);
    cudaGetSymbolAddress((void**)&hy,h_y);
    cudaGetSymbolAddress((void**)&hf,h_f);
    cudaGetSymbolAddress((void**)&w1t,h_w1t);
    cudaGetSymbolAddress((void**)&w2t,h_w2t);
    cudaGetSymbolAddress((void**)&w3t,h_w3t);
    cudaGetSymbolAddress((void**)&wqkt,h_wqkt);
    cudaGetSymbolAddress((void**)&wvt,h_wvt);
    cudaGetSymbolAddress((void**)&wot,h_wot);
    cudaGetSymbolAddress((void**)&wf1t,h_wf1t);
    cudaGetSymbolAddress((void**)&wf2t,h_wf2t);
    __half* hq = hqk;
    __half* hk = hqk + (size_t)Mrows*HE;

    cudaFuncSetAttribute(tgemm, cudaFuncAttributeMaxDynamicSharedMemorySize, SMEM_BYTES);
    cudaFuncSetAttribute(fused_attn, cudaFuncAttributeMaxDynamicSharedMemorySize, FA_SMEM);
    dim3 tb(32,8);
    const long Z=0;

    deg_kernel<<<Mrows,256>>>(adj,dis);
    an_build<<<(Bb*Nn*Nn)/256,256>>>(adj,dis,han);
    conv_h<<<(Mrows*INd)/256,256>>>(x,hx);
    WT9 wt;
    wt.src[0]=W1;  wt.dst[0]=w1t;                   wt.K[0]=128;  wt.N[0]=256;
    wt.src[1]=W2;  wt.dst[1]=w2t;                   wt.K[1]=256;  wt.N[1]=256;
    wt.src[2]=W3;  wt.dst[2]=w3t;                   wt.K[2]=256;  wt.N[2]=256;
    wt.src[3]=Wq;  wt.dst[3]=wqkt;                  wt.K[3]=256;  wt.N[3]=2048;
    wt.src[4]=Wk;  wt.dst[4]=wqkt+(size_t)2048*256; wt.K[4]=256;  wt.N[4]=2048;
    wt.src[5]=Wv;  wt.dst[5]=wvt;                   wt.K[5]=256;  wt.N[5]=2048;
    wt.src[6]=Wo;  wt.dst[6]=wot;                   wt.K[6]=2048; wt.N[6]=256;
    wt.src[7]=Wf1; wt.dst[7]=wf1t;                  wt.K[7]=256;  wt.N[7]=1024;
    wt.src[8]=Wf2; wt.dst[8]=wf2t;                  wt.K[8]=1024; wt.N[8]=256;
    int ntot=0;
    for(int i=0;i<9;i++){ wt.base[i]=ntot; ntot += (wt.K[i]>>5)*(wt.N[i]>>7); }
    conv_wt_all<<<ntot,tb>>>(wt,ntot);

    // GCN layer 1
    tgemm<<<dim3(128,2,1),256,SMEM_BYTES>>>(w1t,128, hx,128, 0,htT,Mrows,
        0,0,0,0, 0,0, 128, Z,Z,Z,Z, 0);
    tgemm<<<dim3(2,2,Bb),256,SMEM_BYTES>>>(han,256, htT,Mrows, 0,hg,256,
        b1,mask,0,0, res,1, 256, 65536L,256L,65536L,256L, 1);
    // layer 2
    tgemm<<<dim3(128,2,1),256,SMEM_BYTES>>>(w2t,256, hg,256, 0,htT,Mrows,
        0,0,0,0, 0,0, 256, Z,Z,Z,Z, 0);
    tgemm<<<dim3(2,2,Bb),256,SMEM_BYTES>>>(han,256, htT,Mrows, 0,hg,256,
        b2,mask,0,0, res,0, 256, 65536L,256L,65536L,256L, 1);
    // layer 3
    tgemm<<<dim3(128,2,1),256,SMEM_BYTES>>>(w3t,256, hg,256, 0,htT,Mrows,
        0,0,0,0, 0,0, 256, Z,Z,Z,Z, 0);
    tgemm<<<dim3(2,2,Bb),256,SMEM_BYTES>>>(han,256, htT,Mrows, 0,hg,256,
        b3,mask,0,0, res,0, 256, 65536L,256L,65536L,256L, 1);

    // LN1 + QKV
    ln_kernel<<<Mrows,256>>>(res,ln1g,ln1b,hh);
    tgemm<<<dim3(16,128,2),256,SMEM_BYTES>>>(hh,256, wqkt,256, 0,hqk,HE,
        0,0,0,0, 0,0, 256, 0L,(long)2048*256,(long)Mrows*HE,Z, 0);
    tgemm<<<dim3(128,16,1),256,SMEM_BYTES>>>(wvt,256, hh,256, 0,hvT,Mrows,
        0,0,0,0, 0,0, 256, Z,Z,Z,Z, 0);

    // fused attention
    fused_attn<<<dim3(1,2,Bb*Hh),512,FA_SMEM>>>(hq,hk,hvT,dist,mask,hy);

    // att = (y@Wo + bo)*mask + res
    tgemm<<<dim3(2,128,1),256,SMEM_BYTES>>>(hy,HE, wot,HE, att,0,256,
        bo,mask,res,0, 0,0, 2048, Z,Z,Z,Z, 0);

    // FFN
    ln_kernel<<<Mrows,256>>>(att,ln2g,ln2b,hh);
    tgemm<<<dim3(8,128,1),256,SMEM_BYTES>>>(hh,256, wf1t,256, 0,hf,Ff,
        bf1,0,0,0, 0,0, 256, Z,Z,Z,Z, 2);
    tgemm<<<dim3(2,128,1),256,SMEM_BYTES>>>(hf,Ff, wf2t,Ff, out,0,256,
        bf2,mask,att,res, 0,0, 1024, Z,Z,Z,Z, 0);
}